// round 7
// baseline (speedup 1.0000x reference)
#include <cuda_runtime.h>
#include <cuda_bf16.h>
#include <math.h>
#include <stdint.h>

// Problem constants
#define B_  4
#define S_  1024
#define BH  64     // B*H

// ---------------------------------------------------------------------------
// Scratch. "h/l" arrays hold packed bf16 pairs: word w = bf16(x[2w]) |
// bf16(x[2w+1])<<16 ; hi = rn(x), lo = rn(x - hi).
// ---------------------------------------------------------------------------
static __device__ uint32_t g_INh[(size_t)5 * 4096 * 512];   // [qa,qg,ka,kg,va]
static __device__ uint32_t g_INl[(size_t)5 * 4096 * 512];
static __device__ uint32_t g_Wh[(size_t)4194304];           // Wqa..Wva,Wgate,Winfo
static __device__ uint32_t g_Wl[(size_t)4194304];
static __device__ uint32_t g_Qh[(size_t)BH * S_ * 64];      // [bh,s,64w] (qa|qg)
static __device__ uint32_t g_Ql[(size_t)BH * S_ * 64];
static __device__ uint32_t g_Kh[(size_t)BH * S_ * 64];
static __device__ uint32_t g_Kl[(size_t)BH * S_ * 64];
static __device__ float    g_V [(size_t)BH * 64 * S_];      // transposed [bh,j,s]
static __device__ uint32_t g_Xh[(size_t)4096 * 512];        // attn out packed
static __device__ uint32_t g_Xl[(size_t)4096 * 512];
static __device__ float    g_G [(size_t)4096 * 1024];       // gate fp32

#define OW_QA 0u
#define OW_QG 524288u
#define OW_KA 1048576u
#define OW_KG 1572864u
#define OW_VA 2097152u
#define OW_GATE 2621440u
#define OW_INFO 3670016u

// ---------------------------------------------------------------------------
__device__ __forceinline__ void cvt_split2(float x, float y, uint32_t &hi, uint32_t &lo) {
    __nv_bfloat16 hx = __float2bfloat16_rn(x);
    __nv_bfloat16 hy = __float2bfloat16_rn(y);
    float rx = x - __bfloat162float(hx);
    float ry = y - __bfloat162float(hy);
    __nv_bfloat16 lx = __float2bfloat16_rn(rx);
    __nv_bfloat16 ly = __float2bfloat16_rn(ry);
    hi = (uint32_t)__bfloat16_as_ushort(hx) | ((uint32_t)__bfloat16_as_ushort(hy) << 16);
    lo = (uint32_t)__bfloat16_as_ushort(lx) | ((uint32_t)__bfloat16_as_ushort(ly) << 16);
}

__device__ __forceinline__ void mma_bf16(float* c,
    uint32_t a0, uint32_t a1, uint32_t a2, uint32_t a3,
    uint32_t b0, uint32_t b1)
{
    asm volatile(
        "mma.sync.aligned.m16n8k16.row.col.f32.bf16.bf16.f32 "
        "{%0,%1,%2,%3},{%4,%5,%6,%7},{%8,%9},{%0,%1,%2,%3};"
        : "+f"(c[0]), "+f"(c[1]), "+f"(c[2]), "+f"(c[3])
        : "r"(a0), "r"(a1), "r"(a2), "r"(a3), "r"(b0), "r"(b1));
}

#define LDMX4(r0, r1, r2, r3, addr) \
    asm volatile("ldmatrix.sync.aligned.m8n8.x4.shared.b16 {%0,%1,%2,%3}, [%4];" \
        : "=r"(r0), "=r"(r1), "=r"(r2), "=r"(r3) : "r"(addr))

__device__ __forceinline__ uint32_t smem_u32(const void* p) {
    uint32_t a;
    asm("{ .reg .u64 t; cvta.to.shared.u64 t, %1; cvt.u32.u64 %0, t; }" : "=r"(a) : "l"(p));
    return a;
}

// ---------------------------------------------------------------------------
// Conversion kernels
// ---------------------------------------------------------------------------
__global__ __launch_bounds__(256) void conv_in_kernel(
    const float* __restrict__ q_g, const float* __restrict__ k_g,
    const float* __restrict__ q_a, const float* __restrict__ k_a,
    const float* __restrict__ v_a)
{
    const int z = blockIdx.y;
    const float* src = (z == 0) ? q_a : (z == 1) ? q_g : (z == 2) ? k_a
                     : (z == 3) ? k_g : v_a;
    const size_t i = (size_t)blockIdx.x * 256 + threadIdx.x;
    float4 v = ((const float4*)src)[i];
    uint32_t h0, l0, h1, l1;
    cvt_split2(v.x, v.y, h0, l0);
    cvt_split2(v.z, v.w, h1, l1);
    const size_t w = (size_t)z * 2097152 + i * 2;
    g_INh[w] = h0; g_INh[w + 1] = h1;
    g_INl[w] = l0; g_INl[w + 1] = l1;
}

__global__ __launch_bounds__(256) void conv_w_kernel(
    const float* __restrict__ Wqa, const float* __restrict__ Wqg,
    const float* __restrict__ Wka, const float* __restrict__ Wkg,
    const float* __restrict__ Wva, const float* __restrict__ Wgate,
    const float* __restrict__ Winfo)
{
    const int z = blockIdx.y;
    const float* src; size_t offw; size_t nf4;
    switch (z) {
        case 0: src = Wqa;   offw = OW_QA;   nf4 = 262144; break;
        case 1: src = Wqg;   offw = OW_QG;   nf4 = 262144; break;
        case 2: src = Wka;   offw = OW_KA;   nf4 = 262144; break;
        case 3: src = Wkg;   offw = OW_KG;   nf4 = 262144; break;
        case 4: src = Wva;   offw = OW_VA;   nf4 = 262144; break;
        case 5: src = Wgate; offw = OW_GATE; nf4 = 524288; break;
        default: src = Winfo; offw = OW_INFO; nf4 = 262144; break;
    }
    for (size_t i = (size_t)blockIdx.x * 256 + threadIdx.x; i < nf4; i += 262144) {
        float4 v = ((const float4*)src)[i];
        uint32_t h0, l0, h1, l1;
        cvt_split2(v.x, v.y, h0, l0);
        cvt_split2(v.z, v.w, h1, l1);
        const size_t w = offw + i * 2;
        g_Wh[w] = h0; g_Wh[w + 1] = h1;
        g_Wl[w] = l0; g_Wl[w + 1] = l1;
    }
}

// ---------------------------------------------------------------------------
// GEMM: C[128,128] = A * B^T on pre-split word arrays. K-tile = 16 words.
// Double-buffered smem, register prefetch, one sync per tile, ldmatrix frags.
// Stage = 4 arrays x [128][20] words. 2 stages = 81920 B dynamic smem.
// ---------------------------------------------------------------------------
#define GSMEM 81920
typedef uint32_t (*SmT)[20];

struct GT { uint4 ah[2], al[2], bh[2], bl[2]; };

__device__ __forceinline__ void ld_tile(
    const uint32_t* __restrict__ Ahp, const uint32_t* __restrict__ Alp, int ldaw,
    const uint32_t* __restrict__ A2h, const uint32_t* __restrict__ A2l, int ld2w, int kspw,
    const uint32_t* __restrict__ Bhp, const uint32_t* __restrict__ Blp, int ldbw,
    int m0, int n0, int kw0, GT& t)
{
    const int tid = threadIdx.x;
    #pragma unroll
    for (int c = 0; c < 2; c++) {
        const int cid = tid + c * 256;
        const int row = cid >> 2, colw = (cid & 3) << 2;
        const int gw = kw0 + colw;
        const uint32_t *pah, *pal;
        if (gw >= kspw) {
            pah = A2h + (size_t)(m0 + row) * ld2w + (gw - kspw);
            pal = A2l + (size_t)(m0 + row) * ld2w + (gw - kspw);
        } else {
            pah = Ahp + (size_t)(m0 + row) * ldaw + gw;
            pal = Alp + (size_t)(m0 + row) * ldaw + gw;
        }
        t.ah[c] = *(const uint4*)pah;
        t.al[c] = *(const uint4*)pal;
        t.bh[c] = *(const uint4*)(Bhp + (size_t)(n0 + row) * ldbw + gw);
        t.bl[c] = *(const uint4*)(Blp + (size_t)(n0 + row) * ldbw + gw);
    }
}

__device__ __forceinline__ void st_tile(const GT& t, uint32_t* sm, int stage)
{
    SmT Ah = (SmT)(sm + stage * 10240);
    SmT Al = (SmT)(sm + stage * 10240 + 2560);
    SmT Bh = (SmT)(sm + stage * 10240 + 5120);
    SmT Bl = (SmT)(sm + stage * 10240 + 7680);
    const int tid = threadIdx.x;
    #pragma unroll
    for (int c = 0; c < 2; c++) {
        const int cid = tid + c * 256;
        const int row = cid >> 2, colw = (cid & 3) << 2;
        *(uint4*)&Ah[row][colw] = t.ah[c];
        *(uint4*)&Al[row][colw] = t.al[c];
        *(uint4*)&Bh[row][colw] = t.bh[c];
        *(uint4*)&Bl[row][colw] = t.bl[c];
    }
}

// Fragment loads via ldmatrix.x4. aro/aco: lane's row/col offset in the
// 16x16 (8-word) tile; r0..r3 map to mma a0..a3 / (b0,b0',b1,b1').
__device__ __forceinline__ void mma_stage(
    uint32_t smu, int stage, int wm, int wn, int lane, float acc[2][8][4])
{
    const int lr  = lane & 7;
    const int g8  = lane >> 3;
    const int aro = (g8 & 1) * 8 + lr;
    const int aco = (g8 >> 1) * 4;
    const uint32_t base = smu + stage * 40960u;

    #pragma unroll
    for (int kk = 0; kk < 2; kk++) {
        const int pc = kk * 8;
        uint32_t ah[2][4], al[2][4];
        #pragma unroll
        for (int mt = 0; mt < 2; mt++) {
            const uint32_t ra = base + (uint32_t)(((wm + mt * 16 + aro) * 20 + pc + aco) * 4);
            LDMX4(ah[mt][0], ah[mt][1], ah[mt][2], ah[mt][3], ra);
            LDMX4(al[mt][0], al[mt][1], al[mt][2], al[mt][3], ra + 10240u);
        }
        #pragma unroll
        for (int np = 0; np < 4; np++) {
            const uint32_t rb = base + 20480u +
                (uint32_t)(((wn + np * 16 + aro) * 20 + pc + aco) * 4);
            uint32_t bh[4], bl[4];
            LDMX4(bh[0], bh[1], bh[2], bh[3], rb);
            LDMX4(bl[0], bl[1], bl[2], bl[3], rb + 10240u);
            #pragma unroll
            for (int sub = 0; sub < 2; sub++) {
                const int nf = np * 2 + sub;
                #pragma unroll
                for (int mt = 0; mt < 2; mt++) {
                    mma_bf16(acc[mt][nf], ah[mt][0], ah[mt][1], ah[mt][2], ah[mt][3], bh[sub], bh[2 + sub]);
                    mma_bf16(acc[mt][nf], ah[mt][0], ah[mt][1], ah[mt][2], ah[mt][3], bl[sub], bl[2 + sub]);
                    mma_bf16(acc[mt][nf], al[mt][0], al[mt][1], al[mt][2], al[mt][3], bh[sub], bh[2 + sub]);
                }
            }
        }
    }
}

__device__ __forceinline__ void gemm_body(
    const uint32_t* Ahp, const uint32_t* Alp, int ldaw,
    const uint32_t* A2h, const uint32_t* A2l, int ld2w, int kspw,
    const uint32_t* Bhp, const uint32_t* Blp, int ldbw,
    int Kw, int m0, int n0, float acc[2][8][4], uint32_t* sm)
{
    const int warp = threadIdx.x >> 5, lane = threadIdx.x & 31;
    const int wm = (warp & 3) * 32;
    const int wn = (warp >> 2) * 64;
    const int nK = Kw >> 4;
    const uint32_t smu = smem_u32(sm);

    GT tr;
    ld_tile(Ahp, Alp, ldaw, A2h, A2l, ld2w, kspw, Bhp, Blp, ldbw, m0, n0, 0, tr);
    st_tile(tr, sm, 0);

    for (int kt = 0; kt < nK; kt++) {
        __syncthreads();
        if (kt + 1 < nK)
            ld_tile(Ahp, Alp, ldaw, A2h, A2l, ld2w, kspw, Bhp, Blp, ldbw,
                    m0, n0, (kt + 1) * 16, tr);
        mma_stage(smu, kt & 1, wm, wn, lane, acc);
        if (kt + 1 < nK)
            st_tile(tr, sm, (kt + 1) & 1);
    }
}

// ---------------------------------------------------------------------------
// Kernel: 5 head projections. Writes Q/K packed hi/lo, V fp32 transposed.
// ---------------------------------------------------------------------------
__global__ __launch_bounds__(256, 2) void proj_kernel(
    const float* __restrict__ bqa, const float* __restrict__ bqg,
    const float* __restrict__ bka, const float* __restrict__ bkg,
    const float* __restrict__ bva)
{
    extern __shared__ uint32_t sm[];
    const int p = blockIdx.z;
    const uint32_t* Ahp = g_INh + (size_t)p * 2097152;
    const uint32_t* Alp = g_INl + (size_t)p * 2097152;
    const uint32_t woff = (p == 0) ? OW_QA : (p == 1) ? OW_QG : (p == 2) ? OW_KA
                        : (p == 3) ? OW_KG : OW_VA;
    const float* bias = (p == 0) ? bqa : (p == 1) ? bqg : (p == 2) ? bka
                      : (p == 3) ? bkg : bva;

    const int m0 = blockIdx.y * 128;
    const int n0 = blockIdx.x * 128;
    float acc[2][8][4] = {};
    gemm_body(Ahp, Alp, 512, nullptr, nullptr, 512, 1 << 30,
              g_Wh + woff, g_Wl + woff, 512, 512, m0, n0, acc, sm);

    const int lane = threadIdx.x & 31, warp = threadIdx.x >> 5;
    const int wm = (warp & 3) * 32, wn = (warp >> 2) * 64;
    const int g = lane >> 2, t = lane & 3;

    #pragma unroll
    for (int nf = 0; nf < 8; nf++) {
        const int n  = n0 + wn + nf * 8 + 2 * t;
        const int h  = n >> 6, jj = n & 63;
        const float bx = bias[n], by = bias[n + 1];
        #pragma unroll
        for (int mt = 0; mt < 2; mt++) {
            #pragma unroll
            for (int h2 = 0; h2 < 2; h2++) {
                const int m = m0 + wm + mt * 16 + g + h2 * 8;
                const int b = m >> 10, s = m & 1023;
                const size_t bhh = (size_t)(b * 16 + h);
                const float vx = acc[mt][nf][h2 * 2 + 0] + bx;
                const float vy = acc[mt][nf][h2 * 2 + 1] + by;
                if (p == 4) {
                    g_V[(bhh * 64 + jj)     * 1024 + s] = vx;
                    g_V[(bhh * 64 + jj + 1) * 1024 + s] = vy;
                } else {
                    uint32_t hw, lw;
                    cvt_split2(vx, vy, hw, lw);
                    const size_t widx = (bhh * 1024 + s) * 64 + ((p & 1) ? 32 : 0) + (jj >> 1);
                    if (p < 2) { g_Qh[widx] = hw; g_Ql[widx] = lw; }
                    else       { g_Kh[widx] = hw; g_Kl[widx] = lw; }
                }
            }
        }
    }
}

// ---------------------------------------------------------------------------
// Kernel: gate = sigmoid(concat(qa,qg) @ Wgate^T + bgate), Kw=1024 words
// ---------------------------------------------------------------------------
__global__ __launch_bounds__(256, 2) void gate_kernel(const float* __restrict__ bgate)
{
    extern __shared__ uint32_t sm[];
    const int m0 = blockIdx.y * 128;
    const int n0 = blockIdx.x * 128;
    float acc[2][8][4] = {};
    gemm_body(g_INh, g_INl, 512,
              g_INh + 2097152, g_INl + 2097152, 512, 512,
              g_Wh + OW_GATE, g_Wl + OW_GATE, 1024,
              1024, m0, n0, acc, sm);

    const int lane = threadIdx.x & 31, warp = threadIdx.x >> 5;
    const int wm = (warp & 3) * 32, wn = (warp >> 2) * 64;
    const int g = lane >> 2, t = lane & 3;

    #pragma unroll
    for (int nf = 0; nf < 8; nf++) {
        const int n = n0 + wn + nf * 8 + 2 * t;
        const float bx = bgate[n], by = bgate[n + 1];
        #pragma unroll
        for (int mt = 0; mt < 2; mt++) {
            #pragma unroll
            for (int h2 = 0; h2 < 2; h2++) {
                const int m = m0 + wm + mt * 16 + g + h2 * 8;
                float2 v;
                v.x = 1.0f / (1.0f + __expf(-(acc[mt][nf][h2 * 2 + 0] + bx)));
                v.y = 1.0f / (1.0f + __expf(-(acc[mt][nf][h2 * 2 + 1] + by)));
                *(float2*)&g_G[(size_t)m * 1024 + n] = v;
            }
        }
    }
}

// ---------------------------------------------------------------------------
// Kernel: fused flash attention (pre-split Q/K; V fp32 + in-kernel split).
// ldmatrix fragment loads for QK^T (A and B) and PV (B).
// ---------------------------------------------------------------------------
#define ATTN_SMEM 176128

__global__ __launch_bounds__(256) void attn_kernel(const int* __restrict__ mask)
{
    extern __shared__ char smem[];
    uint32_t (*Qh)[68] = (uint32_t(*)[68])(smem);
    uint32_t (*Ql)[68] = (uint32_t(*)[68])(smem + 34816);
    uint32_t (*Kh)[68] = (uint32_t(*)[68])(smem + 69632);
    uint32_t (*Kl)[68] = (uint32_t(*)[68])(smem + 104448);
    uint32_t (*Vh)[68] = (uint32_t(*)[68])(smem + 139264);
    uint32_t (*Vl)[68] = (uint32_t(*)[68])(smem + 156672);
    float* redmax = (float*)(smem + 174080);
    float* redsum = (float*)(smem + 175104);
    float* Osum   = (float*)(smem + 69632);
    const uint32_t smu = smem_u32(smem);

    const int tid  = threadIdx.x;
    const int warp = tid >> 5, lane = tid & 31;
    const int wm = (warp & 3) * 32;
    const int wn = (warp >> 2);
    const int g  = lane >> 2;
    const int t  = lane & 3;
    const int lr  = lane & 7;
    const int g8  = lane >> 3;
    const int aro = (g8 & 1) * 8 + lr;
    const int aco = (g8 >> 1) * 4;

    const int bh = blockIdx.y;
    const int b  = bh >> 4, h = bh & 15;
    const int m0 = blockIdx.x * 128;

    const uint32_t* Qhg = g_Qh + ((size_t)bh << 16);
    const uint32_t* Qlg = g_Ql + ((size_t)bh << 16);
    const uint32_t* Khg = g_Kh + ((size_t)bh << 16);
    const uint32_t* Klg = g_Kl + ((size_t)bh << 16);
    const float*    Vg  = g_V  + ((size_t)bh << 16);

    const int lrow = tid >> 5;
    const int col4 = (tid & 31) * 4;
    const int pcw  = (tid & 31) * 2;

    #pragma unroll
    for (int i = 0; i < 16; i++) {
        const int r = lrow + i * 8;
        const size_t base = (size_t)(m0 + r) * 64 + pcw;
        *(uint2*)&Qh[r][pcw] = *(const uint2*)(Qhg + base);
        *(uint2*)&Ql[r][pcw] = *(const uint2*)(Qlg + base);
    }

    float o[2][8][4] = {};
    float mrun[2][2] = {{-INFINITY, -INFINITY}, {-INFINITY, -INFINITY}};
    float lrun[2][2] = {};
    const float scale = 0.08838834764831845f;

    for (int nt = 0; nt < 8; nt++) {
        const int n0 = nt * 128;
        __syncthreads();

        #pragma unroll
        for (int i = 0; i < 16; i++) {
            const int r = lrow + i * 8;
            const size_t base = (size_t)(n0 + r) * 64 + pcw;
            *(uint2*)&Kh[r][pcw] = *(const uint2*)(Khg + base);
            *(uint2*)&Kl[r][pcw] = *(const uint2*)(Klg + base);
        }
        #pragma unroll
        for (int i = 0; i < 8; i++) {
            const int r = lrow + i * 8;
            float4 v = *(const float4*)(Vg + (size_t)r * 1024 + n0 + col4);
            uint32_t h0, l0, h1, l1;
            cvt_split2(v.x, v.y, h0, l0);
            cvt_split2(v.z, v.w, h1, l1);
            Vh[r][pcw] = h0; Vh[r][pcw + 1] = h1;
            Vl[r][pcw] = l0; Vl[r][pcw + 1] = l1;
        }
        __syncthreads();

        // ---- S = Q K^T (ldmatrix frags) ----
        float s[2][8][4] = {};
        #pragma unroll
        for (int ks = 0; ks < 8; ks++) {
            const int pc = ks * 8;
            uint32_t ah[2][4], al[2][4];
            #pragma unroll
            for (int mt = 0; mt < 2; mt++) {
                const uint32_t ra = smu + (uint32_t)(((wm + mt * 16 + aro) * 68 + pc + aco) * 4);
                LDMX4(ah[mt][0], ah[mt][1], ah[mt][2], ah[mt][3], ra);
                LDMX4(al[mt][0], al[mt][1], al[mt][2], al[mt][3], ra + 34816u);
            }
            #pragma unroll
            for (int np = 0; np < 4; np++) {
                const uint32_t rb = smu + 69632u +
                    (uint32_t)(((wn * 64 + np * 16 + aro) * 68 + pc + aco) * 4);
                uint32_t bhf[4], blf[4];
                LDMX4(bhf[0], bhf[1], bhf[2], bhf[3], rb);
                LDMX4(blf[0], blf[1], blf[2], blf[3], rb + 34816u);
                #pragma unroll
                for (int sub = 0; sub < 2; sub++) {
                    const int nf = np * 2 + sub;
                    #pragma unroll
                    for (int mt = 0; mt < 2; mt++) {
                        mma_bf16(s[mt][nf], ah[mt][0], ah[mt][1], ah[mt][2], ah[mt][3], bhf[sub], bhf[2 + sub]);
                        mma_bf16(s[mt][nf], ah[mt][0], ah[mt][1], ah[mt][2], ah[mt][3], blf[sub], blf[2 + sub]);
                        mma_bf16(s[mt][nf], al[mt][0], al[mt][1], al[mt][2], al[mt][3], bhf[sub], bhf[2 + sub]);
                    }
                }
            }
        }

        // ---- scale + mask + row max ----
        float pm[2][2];
        #pragma unroll
        for (int mt = 0; mt < 2; mt++) {
            #pragma unroll
            for (int h2 = 0; h2 < 2; h2++) {
                const int rglob = m0 + wm + mt * 16 + g + h2 * 8;
                float mx = -INFINITY;
                #pragma unroll
                for (int nf = 0; nf < 8; nf++) {
                    const int ncol = n0 + wn * 64 + nf * 8 + 2 * t;
                    const int2 mk = *(const int2*)(mask + (((size_t)b << 20) + ((size_t)rglob << 10) + ncol));
                    float v0 = s[mt][nf][h2 * 2 + 0] * scale;
                    float v1 = s[mt][nf][h2 * 2 + 1] * scale;
                    if (mk.x == 0) v0 = -1e9f;
                    if (mk.y == 0) v1 = -1e9f;
                    s[mt][nf][h2 * 2 + 0] = v0;
                    s[mt][nf][h2 * 2 + 1] = v1;
                    mx = fmaxf(mx, fmaxf(v0, v1));
                }
                pm[mt][h2] = mx;
            }
        }
        #pragma unroll
        for (int mt = 0; mt < 2; mt++)
            #pragma unroll
            for (int h2 = 0; h2 < 2; h2++) {
                pm[mt][h2] = fmaxf(pm[mt][h2], __shfl_xor_sync(0xffffffffu, pm[mt][h2], 1));
                pm[mt][h2] = fmaxf(pm[mt][h2], __shfl_xor_sync(0xffffffffu, pm[mt][h2], 2));
            }
        if (t == 0) {
            #pragma unroll
            for (int mt = 0; mt < 2; mt++)
                #pragma unroll
                for (int h2 = 0; h2 < 2; h2++)
                    redmax[wn * 128 + wm + mt * 16 + g + h2 * 8] = pm[mt][h2];
        }
        __syncthreads();

        // ---- running stats, exponentiate, rescale O ----
        float alpha[2][2], psum[2][2];
        #pragma unroll
        for (int mt = 0; mt < 2; mt++) {
            #pragma unroll
            for (int h2 = 0; h2 < 2; h2++) {
                const int rl = wm + mt * 16 + g + h2 * 8;
                const float mtile = fmaxf(redmax[rl], redmax[128 + rl]);
                const float mnew  = fmaxf(mrun[mt][h2], mtile);
                alpha[mt][h2] = __expf(mrun[mt][h2] - mnew);
                mrun[mt][h2]  = mnew;
                float ps = 0.0f;
                #pragma unroll
                for (int nf = 0; nf < 8; nf++) {
                    float p0 = __expf(s[mt][nf][h2 * 2 + 0] - mnew);
                    float p1 = __expf(s[mt][nf][h2 * 2 + 1] - mnew);
                    s[mt][nf][h2 * 2 + 0] = p0;
                    s[mt][nf][h2 * 2 + 1] = p1;
                    ps += p0 + p1;
                }
                psum[mt][h2] = ps;
            }
        }
        #pragma unroll
        for (int mt = 0; mt < 2; mt++)
            #pragma unroll
            for (int nf = 0; nf < 8; nf++)
                #pragma unroll
                for (int e = 0; e < 4; e++)
                    o[mt][nf][e] *= alpha[mt][e >> 1];
        #pragma unroll
        for (int mt = 0; mt < 2; mt++)
            #pragma unroll
            for (int h2 = 0; h2 < 2; h2++) {
                psum[mt][h2] += __shfl_xor_sync(0xffffffffu, psum[mt][h2], 1);
                psum[mt][h2] += __shfl_xor_sync(0xffffffffu, psum[mt][h2], 2);
            }
        if (t == 0) {
            #pragma unroll
            for (int mt = 0; mt < 2; mt++)
                #pragma unroll
                for (int h2 = 0; h2 < 2; h2++)
                    redsum[wn * 128 + wm + mt * 16 + g + h2 * 8] = psum[mt][h2];
        }
        __syncthreads();
        #pragma unroll
        for (int mt = 0; mt < 2; mt++)
            #pragma unroll
            for (int h2 = 0; h2 < 2; h2++) {
                const int rl = wm + mt * 16 + g + h2 * 8;
                lrun[mt][h2] = lrun[mt][h2] * alpha[mt][h2] + redsum[rl] + redsum[128 + rl];
            }

        // ---- O += P V (P from regs; V frags via ldmatrix) ----
        #pragma unroll
        for (int ks2 = 0; ks2 < 4; ks2++) {
            uint32_t ah[2][4], al[2][4];
            #pragma unroll
            for (int mt = 0; mt < 2; mt++) {
                cvt_split2(s[mt][2 * ks2][0],     s[mt][2 * ks2][1],     ah[mt][0], al[mt][0]);
                cvt_split2(s[mt][2 * ks2][2],     s[mt][2 * ks2][3],     ah[mt][1], al[mt][1]);
                cvt_split2(s[mt][2 * ks2 + 1][0], s[mt][2 * ks2 + 1][1], ah[mt][2], al[mt][2]);
                cvt_split2(s[mt][2 * ks2 + 1][2], s[mt][2 * ks2 + 1][3], ah[mt][3], al[mt][3]);
            }
            const int colw = wn * 32 + ks2 * 8 + aco;
            #pragma unroll
            for (int np = 0; np < 4; np++) {
                const uint32_t rv = smu + 139264u +
                    (uint32_t)(((np * 16 + aro) * 68 + colw) * 4);
                uint32_t bhf[4], blf[4];
                LDMX4(bhf[0], bhf[1], bhf[2], bhf[3], rv);
                LDMX4(blf[0], blf[1], blf[2], blf[3], rv + 17408u);
                #pragma unroll
                for (int sub = 0; sub < 2; sub++) {
                    const int nf = np * 2 + sub;
                    #pragma unroll
                    for (int mt = 0; mt < 2; mt++) {
                        mma_bf16(o[mt][nf], ah[mt][0], ah[mt][1], ah[mt][2], ah[mt][3], bhf[sub], bhf[2 + sub]);
                        mma_bf16(o[mt][nf], ah[mt][0], ah[mt][1], ah[mt][2], ah[mt][3], blf[sub], blf[2 + sub]);
                        mma_bf16(o[mt][nf], al[mt][0], al[mt][1], al[mt][2], al[mt][3], bhf[sub], bhf[2 + sub]);
                    }
                }
            }
        }
    }

    // ---- epilogue: combine partials, normalize, write packed X ----
    __syncthreads();
    if (wn == 1) {
        #pragma unroll
        for (int mt = 0; mt < 2; mt++)
            #pragma unroll
            for (int h2 = 0; h2 < 2; h2++) {
                const int rl = wm + mt * 16 + g + h2 * 8;
                #pragma unroll
                for (int nf = 0; nf < 8; nf++) {
                    float2 v;
                    v.x = o[mt][nf][h2 * 2 + 0];
                    v.y = o[mt][nf][h2 * 2 + 1];
                    *(float2*)&Osum[rl * 66 + nf * 8 + 2 * t] = v;
                }
            }
    }
    __syncthreads();
    if (wn == 0) {
        #pragma unroll
        for (int mt = 0; mt < 2; mt++)
            #pragma unroll
            for (int h2 = 0; h2 < 2; h2++) {
                const int rl = wm + mt * 16 + g + h2 * 8;
                const float inv = 1.0f / lrun[mt][h2];
                #pragma unroll
                for (int nf = 0; nf < 8; nf++) {
                    const int c = nf * 8 + 2 * t;
                    float2 p = *(float2*)&Osum[rl * 66 + c];
                    const float vx = (o[mt][nf][h2 * 2 + 0] + p.x) * inv;
                    const float vy = (o[mt][nf][h2 * 2 + 1] + p.y) * inv;
                    uint32_t hw, lw;
                    cvt_split2(vx, vy, hw, lw);
                    const size_t widx = (size_t)(b * 1024 + m0 + rl) * 512 + ((h * 64 + c) >> 1);
                    g_Xh[widx] = hw;
                    g_Xl[widx] = lw;
                }
            }
    }
}

// ---------------------------------------------------------------------------
// Kernel: out = gate * (X @ Winfo^T + binfo)
// ---------------------------------------------------------------------------
__global__ __launch_bounds__(256, 2) void info_kernel(
    const float* __restrict__ binfo, float* __restrict__ out)
{
    extern __shared__ uint32_t sm[];
    const int m0 = blockIdx.y * 128;
    const int n0 = blockIdx.x * 128;
    float acc[2][8][4] = {};
    gemm_body(g_Xh, g_Xl, 512, nullptr, nullptr, 512, 1 << 30,
              g_Wh + OW_INFO, g_Wl + OW_INFO, 512, 512, m0, n0, acc, sm);

    const int lane = threadIdx.x & 31, warp = threadIdx.x >> 5;
    const int wm = (warp & 3) * 32, wn = (warp >> 2) * 64;
    const int g = lane >> 2, t = lane & 3;

    #pragma unroll
    for (int nf = 0; nf < 8; nf++) {
        const int n = n0 + wn + nf * 8 + 2 * t;
        const float bx = binfo[n], by = binfo[n + 1];
        #pragma unroll
        for (int mt = 0; mt < 2; mt++) {
            #pragma unroll
            for (int h2 = 0; h2 < 2; h2++) {
                const int m = m0 + wm + mt * 16 + g + h2 * 8;
                const float2 gg = *(const float2*)&g_G[(size_t)m * 1024 + n];
                float2 v;
                v.x = gg.x * (acc[mt][nf][h2 * 2 + 0] + bx);
                v.y = gg.y * (acc[mt][nf][h2 * 2 + 1] + by);
                *(float2*)&out[(size_t)m * 1024 + n] = v;
            }
        }
    }
}

// ---------------------------------------------------------------------------
extern "C" void kernel_launch(void* const* d_in, const int* in_sizes, int n_in,
                              void* d_out, int out_size)
{
    (void)in_sizes; (void)n_in; (void)out_size;
    const float* query_g = (const float*)d_in[0];
    const float* key_g   = (const float*)d_in[1];
    const float* query_a = (const float*)d_in[2];
    const float* key_a   = (const float*)d_in[3];
    const float* value_a = (const float*)d_in[4];
    const int*   mask    = (const int*)  d_in[5];
    const float* Wqg = (const float*)d_in[6];  const float* bqg = (const float*)d_in[7];
    const float* Wkg = (const float*)d_in[8];  const float* bkg = (const float*)d_in[9];
    const float* Wqa = (const float*)d_in[10]; const float* bqa = (const float*)d_in[11];
    const float* Wka = (const float*)d_in[12]; const float* bka = (const float*)d_in[13];
    const float* Wva = (const float*)d_in[14]; const float* bva = (const float*)d_in[15];
    const float* Wgate = (const float*)d_in[16]; const float* bgate = (const float*)d_in[17];
    const float* Winfo = (const float*)d_in[18]; const float* binfo = (const float*)d_in[19];

    static int attr_set = 0;
    if (!attr_set) {
        cudaFuncSetAttribute(attn_kernel, cudaFuncAttributeMaxDynamicSharedMemorySize, ATTN_SMEM);
        cudaFuncSetAttribute(proj_kernel, cudaFuncAttributeMaxDynamicSharedMemorySize, GSMEM);
        cudaFuncSetAttribute(gate_kernel, cudaFuncAttributeMaxDynamicSharedMemorySize, GSMEM);
        cudaFuncSetAttribute(info_kernel, cudaFuncAttributeMaxDynamicSharedMemorySize, GSMEM);
        attr_set = 1;
    }

    dim3 blk(256);
    conv_in_kernel<<<dim3(4096, 5), blk>>>(query_g, key_g, query_a, key_a, value_a);
    conv_w_kernel<<<dim3(1024, 7), blk>>>(Wqa, Wqg, Wka, Wkg, Wva, Wgate, Winfo);
    proj_kernel<<<dim3(8, 32, 5), blk, GSMEM>>>(bqa, bqg, bka, bkg, bva);
    gate_kernel<<<dim3(8, 32, 1), blk, GSMEM>>>(bgate);
    attn_kernel<<<dim3(8, 64), blk, ATTN_SMEM>>>(mask);
    info_kernel<<<dim3(8, 32, 1), blk, GSMEM>>>(binfo, (float*)d_out);
}

// round 8
// speedup vs baseline: 1.0997x; 1.0997x over previous
#include <cuda_runtime.h>
#include <cuda_bf16.h>
#include <math.h>
#include <stdint.h>

// Problem constants
#define B_  4
#define S_  1024
#define D_  1024
#define H_  16
#define BH  64     // B*H

// Scratch
static __device__ float g_Q[(size_t)BH * S_ * 128];   // [bh, s, 128] (qa|qg)
static __device__ float g_K[(size_t)BH * S_ * 128];   // [bh, s, 128] (ka|kg)
static __device__ float g_V[(size_t)BH * 64 * S_];    // TRANSPOSED [bh, j(64), s(1024)]
static __device__ float g_X[(size_t)B_ * S_ * D_];    // attn out [token][1024]
static __device__ float g_G[(size_t)B_ * S_ * D_];    // gate

// ---------------------------------------------------------------------------
// bf16 split helpers: x = hi + lo. 3-term mma (hh+hl+lh) leaves ~eps^2 error.
// ---------------------------------------------------------------------------
__device__ __forceinline__ void cvt_split2(float x, float y, uint32_t &hi, uint32_t &lo) {
    __nv_bfloat16 hx = __float2bfloat16_rn(x);
    __nv_bfloat16 hy = __float2bfloat16_rn(y);
    float rx = x - __bfloat162float(hx);
    float ry = y - __bfloat162float(hy);
    __nv_bfloat16 lx = __float2bfloat16_rn(rx);
    __nv_bfloat16 ly = __float2bfloat16_rn(ry);
    hi = (uint32_t)__bfloat16_as_ushort(hx) | ((uint32_t)__bfloat16_as_ushort(hy) << 16);
    lo = (uint32_t)__bfloat16_as_ushort(lx) | ((uint32_t)__bfloat16_as_ushort(ly) << 16);
}

__device__ __forceinline__ void mma_bf16(float* c,
    uint32_t a0, uint32_t a1, uint32_t a2, uint32_t a3,
    uint32_t b0, uint32_t b1)
{
    asm volatile(
        "mma.sync.aligned.m16n8k16.row.col.f32.bf16.bf16.f32 "
        "{%0,%1,%2,%3},{%4,%5,%6,%7},{%8,%9},{%0,%1,%2,%3};"
        : "+f"(c[0]), "+f"(c[1]), "+f"(c[2]), "+f"(c[3])
        : "r"(a0), "r"(a1), "r"(a2), "r"(a3), "r"(b0), "r"(b1));
}

// ---------------------------------------------------------------------------
// Pipelined 128x128 C-tile GEMM body: C = A[m0:, :K] * B[n0:, :K]^T.
// Register-prefetch pipeline + TERM-MAJOR mma issue (dependent mmas on the
// same accumulator are 8 instructions apart -> RAW latency covered).
// ---------------------------------------------------------------------------
typedef uint32_t (*SmT)[20];

__device__ __forceinline__ void load_ab_regs(
    const float* __restrict__ A, int lda,
    const float* __restrict__ A2, int ksplit,
    const float* __restrict__ Bm, int ldb,
    int m0, int n0, int k0, int k4, int ar,
    float4 va[4], float4 vb[4])
{
    const int colA = k0 + k4;
    const float* abase; int ldaa;
    if (colA >= ksplit) { abase = A2 + (colA - ksplit); ldaa = 1024; }
    else                { abase = A  + colA;            ldaa = lda;  }
    #pragma unroll
    for (int i = 0; i < 4; i++) {
        const int m = ar + i * 32;
        va[i] = *(const float4*)(abase + (size_t)(m0 + m) * ldaa);
        vb[i] = *(const float4*)(Bm + (size_t)(n0 + m) * ldb + k0 + k4);
    }
}

__device__ __forceinline__ void store_tile(
    const float4 va[4], const float4 vb[4], int k4, int ar,
    SmT Ah, SmT Al, SmT Bh, SmT Bl)
{
    const int pc = k4 >> 1;
    #pragma unroll
    for (int i = 0; i < 4; i++) {
        const int m = ar + i * 32;
        uint32_t h0, l0, h1, l1;
        cvt_split2(va[i].x, va[i].y, h0, l0);
        cvt_split2(va[i].z, va[i].w, h1, l1);
        Ah[m][pc] = h0; Ah[m][pc + 1] = h1;
        Al[m][pc] = l0; Al[m][pc + 1] = l1;
        cvt_split2(vb[i].x, vb[i].y, h0, l0);
        cvt_split2(vb[i].z, vb[i].w, h1, l1);
        Bh[m][pc] = h0; Bh[m][pc + 1] = h1;
        Bl[m][pc] = l0; Bl[m][pc + 1] = l1;
    }
}

__device__ __forceinline__ void gemm_bf16_body(
    const float* __restrict__ A, int lda,
    const float* __restrict__ A2, int ksplit,
    const float* __restrict__ Bm, int ldb,
    int K, int m0, int n0,
    float acc[2][8][4],
    SmT Ah, SmT Al, SmT Bh, SmT Bl)
{
    const int tid  = threadIdx.x;
    const int warp = tid >> 5, lane = tid & 31;
    const int wm = (warp & 3) * 32;
    const int wn = (warp >> 2) * 64;
    const int g  = lane >> 2;
    const int t  = lane & 3;
    const int k4 = (tid & 7) * 4;
    const int ar = tid >> 3;

    float4 va[4], vb[4];
    load_ab_regs(A, lda, A2, ksplit, Bm, ldb, m0, n0, 0, k4, ar, va, vb);

    for (int k0 = 0; k0 < K; k0 += 32) {
        __syncthreads();
        store_tile(va, vb, k4, ar, Ah, Al, Bh, Bl);
        __syncthreads();

        if (k0 + 32 < K)
            load_ab_regs(A, lda, A2, ksplit, Bm, ldb, m0, n0, k0 + 32, k4, ar, va, vb);

        #pragma unroll
        for (int kk = 0; kk < 2; kk++) {
            const int pc = kk * 8;
            uint32_t ah[2][4], al[2][4];
            #pragma unroll
            for (int mt = 0; mt < 2; mt++) {
                #pragma unroll
                for (int q = 0; q < 4; q++) {
                    const int row = wm + mt * 16 + g + (q & 1) * 8;
                    const int col = pc + t + (q >> 1) * 4;
                    ah[mt][q] = Ah[row][col];
                    al[mt][q] = Al[row][col];
                }
            }
            #pragma unroll
            for (int half = 0; half < 2; half++) {
                uint32_t b0h[4], b1h[4], b0l[4], b1l[4];
                #pragma unroll
                for (int j = 0; j < 4; j++) {
                    const int rb = wn + (half * 4 + j) * 8 + g;
                    b0h[j] = Bh[rb][pc + t]; b1h[j] = Bh[rb][pc + t + 4];
                    b0l[j] = Bl[rb][pc + t]; b1l[j] = Bl[rb][pc + t + 4];
                }
                // term hh (8 independent mmas)
                #pragma unroll
                for (int j = 0; j < 4; j++)
                    #pragma unroll
                    for (int mt = 0; mt < 2; mt++)
                        mma_bf16(acc[mt][half * 4 + j],
                                 ah[mt][0], ah[mt][1], ah[mt][2], ah[mt][3], b0h[j], b1h[j]);
                // term hl
                #pragma unroll
                for (int j = 0; j < 4; j++)
                    #pragma unroll
                    for (int mt = 0; mt < 2; mt++)
                        mma_bf16(acc[mt][half * 4 + j],
                                 ah[mt][0], ah[mt][1], ah[mt][2], ah[mt][3], b0l[j], b1l[j]);
                // term lh
                #pragma unroll
                for (int j = 0; j < 4; j++)
                    #pragma unroll
                    for (int mt = 0; mt < 2; mt++)
                        mma_bf16(acc[mt][half * 4 + j],
                                 al[mt][0], al[mt][1], al[mt][2], al[mt][3], b0h[j], b1h[j]);
            }
        }
    }
}

// ---------------------------------------------------------------------------
// Kernel 1: 5 head projections, grid.z selects which. V written transposed.
// ---------------------------------------------------------------------------
__global__ __launch_bounds__(256, 2) void proj_kernel(
    const float* __restrict__ qa_in, const float* __restrict__ qg_in,
    const float* __restrict__ ka_in, const float* __restrict__ kg_in,
    const float* __restrict__ va_in,
    const float* __restrict__ Wqa, const float* __restrict__ Wqg,
    const float* __restrict__ Wka, const float* __restrict__ Wkg,
    const float* __restrict__ Wva,
    const float* __restrict__ bqa, const float* __restrict__ bqg,
    const float* __restrict__ bka, const float* __restrict__ bkg,
    const float* __restrict__ bva)
{
    __shared__ uint32_t Ah[128][20], Al[128][20], Bh[128][20], Bl[128][20];
    const int p = blockIdx.z;
    const float* A; const float* W; const float* bias;
    if      (p == 0) { A = qa_in; W = Wqa; bias = bqa; }
    else if (p == 1) { A = qg_in; W = Wqg; bias = bqg; }
    else if (p == 2) { A = ka_in; W = Wka; bias = bka; }
    else if (p == 3) { A = kg_in; W = Wkg; bias = bkg; }
    else             { A = va_in; W = Wva; bias = bva; }

    const int m0 = blockIdx.y * 128;
    const int n0 = blockIdx.x * 128;
    float acc[2][8][4] = {};
    gemm_bf16_body(A, 1024, nullptr, 1 << 30, W, 1024, 1024, m0, n0, acc,
                   (SmT)Ah, (SmT)Al, (SmT)Bh, (SmT)Bl);

    const int lane = threadIdx.x & 31, warp = threadIdx.x >> 5;
    const int wm = (warp & 3) * 32, wn = (warp >> 2) * 64;
    const int g = lane >> 2, t = lane & 3;

    #pragma unroll
    for (int nf = 0; nf < 8; nf++) {
        const int n  = n0 + wn + nf * 8 + 2 * t;
        const int h  = n >> 6, jj = n & 63;
        const float bx = bias[n], by = bias[n + 1];
        #pragma unroll
        for (int mt = 0; mt < 2; mt++) {
            #pragma unroll
            for (int h2 = 0; h2 < 2; h2++) {
                const int m = m0 + wm + mt * 16 + g + h2 * 8;
                const int b = m >> 10, s = m & 1023;
                const size_t bhh = (size_t)(b * 16 + h);
                float2 v;
                v.x = acc[mt][nf][h2 * 2 + 0] + bx;
                v.y = acc[mt][nf][h2 * 2 + 1] + by;
                if      (p == 0) *(float2*)&g_Q[(bhh * 1024 + s) * 128 + jj]      = v;
                else if (p == 1) *(float2*)&g_Q[(bhh * 1024 + s) * 128 + 64 + jj] = v;
                else if (p == 2) *(float2*)&g_K[(bhh * 1024 + s) * 128 + jj]      = v;
                else if (p == 3) *(float2*)&g_K[(bhh * 1024 + s) * 128 + 64 + jj] = v;
                else {
                    g_V[(bhh * 64 + jj)     * 1024 + s] = v.x;
                    g_V[(bhh * 64 + jj + 1) * 1024 + s] = v.y;
                }
            }
        }
    }
}

// ---------------------------------------------------------------------------
// Kernel 2: gate = sigmoid(concat(query_a, query_g) @ Wgate^T + bgate), K=2048
// ---------------------------------------------------------------------------
__global__ __launch_bounds__(256, 2) void gate_kernel(
    const float* __restrict__ qa_in, const float* __restrict__ qg_in,
    const float* __restrict__ Wgate, const float* __restrict__ bgate)
{
    __shared__ uint32_t Ah[128][20], Al[128][20], Bh[128][20], Bl[128][20];
    const int m0 = blockIdx.y * 128;
    const int n0 = blockIdx.x * 128;
    float acc[2][8][4] = {};
    gemm_bf16_body(qa_in, 1024, qg_in, 1024, Wgate, 2048, 2048, m0, n0, acc,
                   (SmT)Ah, (SmT)Al, (SmT)Bh, (SmT)Bl);

    const int lane = threadIdx.x & 31, warp = threadIdx.x >> 5;
    const int wm = (warp & 3) * 32, wn = (warp >> 2) * 64;
    const int g = lane >> 2, t = lane & 3;

    #pragma unroll
    for (int nf = 0; nf < 8; nf++) {
        const int n = n0 + wn + nf * 8 + 2 * t;
        const float bx = bgate[n], by = bgate[n + 1];
        #pragma unroll
        for (int mt = 0; mt < 2; mt++) {
            #pragma unroll
            for (int h2 = 0; h2 < 2; h2++) {
                const int m = m0 + wm + mt * 16 + g + h2 * 8;
                float2 v;
                v.x = 1.0f / (1.0f + __expf(-(acc[mt][nf][h2 * 2 + 0] + bx)));
                v.y = 1.0f / (1.0f + __expf(-(acc[mt][nf][h2 * 2 + 1] + by)));
                *(float2*)&g_G[(size_t)m * 1024 + n] = v;
            }
        }
    }
}

// ---------------------------------------------------------------------------
// Kernel 3: fused flash attention (term-major mma issue).
// ---------------------------------------------------------------------------
#define ATTN_SMEM 176128

__global__ __launch_bounds__(256) void attn_kernel(const int* __restrict__ mask)
{
    extern __shared__ char smem[];
    uint32_t (*Qh)[68] = (uint32_t(*)[68])(smem);
    uint32_t (*Ql)[68] = (uint32_t(*)[68])(smem + 34816);
    uint32_t (*Kh)[68] = (uint32_t(*)[68])(smem + 69632);
    uint32_t (*Kl)[68] = (uint32_t(*)[68])(smem + 104448);
    uint32_t (*Vh)[68] = (uint32_t(*)[68])(smem + 139264);
    uint32_t (*Vl)[68] = (uint32_t(*)[68])(smem + 156672);
    float* redmax = (float*)(smem + 174080);
    float* redsum = (float*)(smem + 175104);
    float* Osum   = (float*)(smem + 69632);

    const int tid  = threadIdx.x;
    const int warp = tid >> 5, lane = tid & 31;
    const int wm = (warp & 3) * 32;
    const int wn = (warp >> 2);
    const int g  = lane >> 2;
    const int t  = lane & 3;

    const int bh = blockIdx.y;
    const int b  = bh >> 4, h = bh & 15;
    const int m0 = blockIdx.x * 128;

    const float* Qg = g_Q + ((size_t)bh << 17);
    const float* Kg = g_K + ((size_t)bh << 17);
    const float* Vg = g_V + ((size_t)bh << 16);

    const int lrow = tid >> 5;
    const int col4 = (tid & 31) * 4;
    const int pcw  = (tid & 31) * 2;

    #pragma unroll
    for (int i = 0; i < 16; i++) {
        const int r = lrow + i * 8;
        float4 v = *(const float4*)(Qg + (size_t)(m0 + r) * 128 + col4);
        uint32_t h0, l0, h1, l1;
        cvt_split2(v.x, v.y, h0, l0);
        cvt_split2(v.z, v.w, h1, l1);
        Qh[r][pcw] = h0; Qh[r][pcw + 1] = h1;
        Ql[r][pcw] = l0; Ql[r][pcw + 1] = l1;
    }

    float o[2][8][4] = {};
    float mrun[2][2] = {{-INFINITY, -INFINITY}, {-INFINITY, -INFINITY}};
    float lrun[2][2] = {};
    const float scale = 0.08838834764831845f;

    for (int nt = 0; nt < 8; nt++) {
        const int n0 = nt * 128;
        __syncthreads();

        #pragma unroll
        for (int i = 0; i < 16; i++) {
            const int r = lrow + i * 8;
            float4 v = *(const float4*)(Kg + (size_t)(n0 + r) * 128 + col4);
            uint32_t h0, l0, h1, l1;
            cvt_split2(v.x, v.y, h0, l0);
            cvt_split2(v.z, v.w, h1, l1);
            Kh[r][pcw] = h0; Kh[r][pcw + 1] = h1;
            Kl[r][pcw] = l0; Kl[r][pcw + 1] = l1;
        }
        #pragma unroll
        for (int i = 0; i < 8; i++) {
            const int r = lrow + i * 8;
            float4 v = *(const float4*)(Vg + (size_t)r * 1024 + n0 + col4);
            uint32_t h0, l0, h1, l1;
            cvt_split2(v.x, v.y, h0, l0);
            cvt_split2(v.z, v.w, h1, l1);
            Vh[r][pcw] = h0; Vh[r][pcw + 1] = h1;
            Vl[r][pcw] = l0; Vl[r][pcw + 1] = l1;
        }
        __syncthreads();

        // ---- S = Q K^T (term-major) ----
        float s[2][8][4] = {};
        #pragma unroll
        for (int ks = 0; ks < 8; ks++) {
            const int pc = ks * 8;
            uint32_t ah[2][4], al[2][4];
            #pragma unroll
            for (int mt = 0; mt < 2; mt++) {
                #pragma unroll
                for (int q = 0; q < 4; q++) {
                    const int row = wm + mt * 16 + g + (q & 1) * 8;
                    const int col = pc + t + (q >> 1) * 4;
                    ah[mt][q] = Qh[row][col];
                    al[mt][q] = Ql[row][col];
                }
            }
            #pragma unroll
            for (int half = 0; half < 2; half++) {
                uint32_t b0h[4], b1h[4], b0l[4], b1l[4];
                #pragma unroll
                for (int j = 0; j < 4; j++) {
                    const int rb = wn * 64 + (half * 4 + j) * 8 + g;
                    b0h[j] = Kh[rb][pc + t]; b1h[j] = Kh[rb][pc + t + 4];
                    b0l[j] = Kl[rb][pc + t]; b1l[j] = Kl[rb][pc + t + 4];
                }
                #pragma unroll
                for (int j = 0; j < 4; j++)
                    #pragma unroll
                    for (int mt = 0; mt < 2; mt++)
                        mma_bf16(s[mt][half * 4 + j],
                                 ah[mt][0], ah[mt][1], ah[mt][2], ah[mt][3], b0h[j], b1h[j]);
                #pragma unroll
                for (int j = 0; j < 4; j++)
                    #pragma unroll
                    for (int mt = 0; mt < 2; mt++)
                        mma_bf16(s[mt][half * 4 + j],
                                 ah[mt][0], ah[mt][1], ah[mt][2], ah[mt][3], b0l[j], b1l[j]);
                #pragma unroll
                for (int j = 0; j < 4; j++)
                    #pragma unroll
                    for (int mt = 0; mt < 2; mt++)
                        mma_bf16(s[mt][half * 4 + j],
                                 al[mt][0], al[mt][1], al[mt][2], al[mt][3], b0h[j], b1h[j]);
            }
        }

        // ---- scale + mask + row max ----
        float pm[2][2];
        #pragma unroll
        for (int mt = 0; mt < 2; mt++) {
            #pragma unroll
            for (int h2 = 0; h2 < 2; h2++) {
                const int rglob = m0 + wm + mt * 16 + g + h2 * 8;
                float mx = -INFINITY;
                #pragma unroll
                for (int nf = 0; nf < 8; nf++) {
                    const int ncol = n0 + wn * 64 + nf * 8 + 2 * t;
                    const int2 mk = *(const int2*)(mask + (((size_t)b << 20) + ((size_t)rglob << 10) + ncol));
                    float v0 = s[mt][nf][h2 * 2 + 0] * scale;
                    float v1 = s[mt][nf][h2 * 2 + 1] * scale;
                    if (mk.x == 0) v0 = -1e9f;
                    if (mk.y == 0) v1 = -1e9f;
                    s[mt][nf][h2 * 2 + 0] = v0;
                    s[mt][nf][h2 * 2 + 1] = v1;
                    mx = fmaxf(mx, fmaxf(v0, v1));
                }
                pm[mt][h2] = mx;
            }
        }
        #pragma unroll
        for (int mt = 0; mt < 2; mt++)
            #pragma unroll
            for (int h2 = 0; h2 < 2; h2++) {
                pm[mt][h2] = fmaxf(pm[mt][h2], __shfl_xor_sync(0xffffffffu, pm[mt][h2], 1));
                pm[mt][h2] = fmaxf(pm[mt][h2], __shfl_xor_sync(0xffffffffu, pm[mt][h2], 2));
            }
        if (t == 0) {
            #pragma unroll
            for (int mt = 0; mt < 2; mt++)
                #pragma unroll
                for (int h2 = 0; h2 < 2; h2++)
                    redmax[wn * 128 + wm + mt * 16 + g + h2 * 8] = pm[mt][h2];
        }
        __syncthreads();

        // ---- running stats, exponentiate, rescale O ----
        float alpha[2][2], psum[2][2];
        #pragma unroll
        for (int mt = 0; mt < 2; mt++) {
            #pragma unroll
            for (int h2 = 0; h2 < 2; h2++) {
                const int rl = wm + mt * 16 + g + h2 * 8;
                const float mtile = fmaxf(redmax[rl], redmax[128 + rl]);
                const float mnew  = fmaxf(mrun[mt][h2], mtile);
                alpha[mt][h2] = __expf(mrun[mt][h2] - mnew);
                mrun[mt][h2]  = mnew;
                float ps = 0.0f;
                #pragma unroll
                for (int nf = 0; nf < 8; nf++) {
                    float p0 = __expf(s[mt][nf][h2 * 2 + 0] - mnew);
                    float p1 = __expf(s[mt][nf][h2 * 2 + 1] - mnew);
                    s[mt][nf][h2 * 2 + 0] = p0;
                    s[mt][nf][h2 * 2 + 1] = p1;
                    ps += p0 + p1;
                }
                psum[mt][h2] = ps;
            }
        }
        #pragma unroll
        for (int mt = 0; mt < 2; mt++)
            #pragma unroll
            for (int nf = 0; nf < 8; nf++)
                #pragma unroll
                for (int e = 0; e < 4; e++)
                    o[mt][nf][e] *= alpha[mt][e >> 1];
        #pragma unroll
        for (int mt = 0; mt < 2; mt++)
            #pragma unroll
            for (int h2 = 0; h2 < 2; h2++) {
                psum[mt][h2] += __shfl_xor_sync(0xffffffffu, psum[mt][h2], 1);
                psum[mt][h2] += __shfl_xor_sync(0xffffffffu, psum[mt][h2], 2);
            }
        if (t == 0) {
            #pragma unroll
            for (int mt = 0; mt < 2; mt++)
                #pragma unroll
                for (int h2 = 0; h2 < 2; h2++)
                    redsum[wn * 128 + wm + mt * 16 + g + h2 * 8] = psum[mt][h2];
        }
        __syncthreads();
        #pragma unroll
        for (int mt = 0; mt < 2; mt++)
            #pragma unroll
            for (int h2 = 0; h2 < 2; h2++) {
                const int rl = wm + mt * 16 + g + h2 * 8;
                lrun[mt][h2] = lrun[mt][h2] * alpha[mt][h2] + redsum[rl] + redsum[128 + rl];
            }

        // ---- O += P V (term-major) ----
        #pragma unroll
        for (int ks2 = 0; ks2 < 4; ks2++) {
            uint32_t ah[2][4], al[2][4];
            #pragma unroll
            for (int mt = 0; mt < 2; mt++) {
                cvt_split2(s[mt][2 * ks2][0],     s[mt][2 * ks2][1],     ah[mt][0], al[mt][0]);
                cvt_split2(s[mt][2 * ks2][2],     s[mt][2 * ks2][3],     ah[mt][1], al[mt][1]);
                cvt_split2(s[mt][2 * ks2 + 1][0], s[mt][2 * ks2 + 1][1], ah[mt][2], al[mt][2]);
                cvt_split2(s[mt][2 * ks2 + 1][2], s[mt][2 * ks2 + 1][3], ah[mt][3], al[mt][3]);
            }
            const int vcol = wn * 32 + ks2 * 8 + t;
            #pragma unroll
            for (int half = 0; half < 2; half++) {
                uint32_t b0h[4], b1h[4], b0l[4], b1l[4];
                #pragma unroll
                for (int j = 0; j < 4; j++) {
                    const int rv = (half * 4 + j) * 8 + g;
                    b0h[j] = Vh[rv][vcol]; b1h[j] = Vh[rv][vcol + 4];
                    b0l[j] = Vl[rv][vcol]; b1l[j] = Vl[rv][vcol + 4];
                }
                #pragma unroll
                for (int j = 0; j < 4; j++)
                    #pragma unroll
                    for (int mt = 0; mt < 2; mt++)
                        mma_bf16(o[mt][half * 4 + j],
                                 ah[mt][0], ah[mt][1], ah[mt][2], ah[mt][3], b0h[j], b1h[j]);
                #pragma unroll
                for (int j = 0; j < 4; j++)
                    #pragma unroll
                    for (int mt = 0; mt < 2; mt++)
                        mma_bf16(o[mt][half * 4 + j],
                                 ah[mt][0], ah[mt][1], ah[mt][2], ah[mt][3], b0l[j], b1l[j]);
                #pragma unroll
                for (int j = 0; j < 4; j++)
                    #pragma unroll
                    for (int mt = 0; mt < 2; mt++)
                        mma_bf16(o[mt][half * 4 + j],
                                 al[mt][0], al[mt][1], al[mt][2], al[mt][3], b0h[j], b1h[j]);
            }
        }
    }

    // ---- epilogue ----
    __syncthreads();
    if (wn == 1) {
        #pragma unroll
        for (int mt = 0; mt < 2; mt++)
            #pragma unroll
            for (int h2 = 0; h2 < 2; h2++) {
                const int rl = wm + mt * 16 + g + h2 * 8;
                #pragma unroll
                for (int nf = 0; nf < 8; nf++) {
                    float2 v;
                    v.x = o[mt][nf][h2 * 2 + 0];
                    v.y = o[mt][nf][h2 * 2 + 1];
                    *(float2*)&Osum[rl * 66 + nf * 8 + 2 * t] = v;
                }
            }
    }
    __syncthreads();
    if (wn == 0) {
        #pragma unroll
        for (int mt = 0; mt < 2; mt++)
            #pragma unroll
            for (int h2 = 0; h2 < 2; h2++) {
                const int rl = wm + mt * 16 + g + h2 * 8;
                const float inv = 1.0f / lrun[mt][h2];
                #pragma unroll
                for (int nf = 0; nf < 8; nf++) {
                    const int c = nf * 8 + 2 * t;
                    float2 p = *(float2*)&Osum[rl * 66 + c];
                    float2 v;
                    v.x = (o[mt][nf][h2 * 2 + 0] + p.x) * inv;
                    v.y = (o[mt][nf][h2 * 2 + 1] + p.y) * inv;
                    *(float2*)&g_X[(size_t)(b * 1024 + m0 + rl) * 1024 + h * 64 + c] = v;
                }
            }
    }
}

// ---------------------------------------------------------------------------
// Kernel 4: out = gate * (X @ Winfo^T + binfo)
// ---------------------------------------------------------------------------
__global__ __launch_bounds__(256, 2) void info_kernel(
    const float* __restrict__ Winfo, const float* __restrict__ binfo,
    float* __restrict__ out)
{
    __shared__ uint32_t Ah[128][20], Al[128][20], Bh[128][20], Bl[128][20];
    const int m0 = blockIdx.y * 128;
    const int n0 = blockIdx.x * 128;
    float acc[2][8][4] = {};
    gemm_bf16_body(g_X, 1024, nullptr, 1 << 30, Winfo, 1024, 1024, m0, n0, acc,
                   (SmT)Ah, (SmT)Al, (SmT)Bh, (SmT)Bl);

    const int lane = threadIdx.x & 31, warp = threadIdx.x >> 5;
    const int wm = (warp & 3) * 32, wn = (warp >> 2) * 64;
    const int g = lane >> 2, t = lane & 3;

    #pragma unroll
    for (int nf = 0; nf < 8; nf++) {
        const int n = n0 + wn + nf * 8 + 2 * t;
        const float bx = binfo[n], by = binfo[n + 1];
        #pragma unroll
        for (int mt = 0; mt < 2; mt++) {
            #pragma unroll
            for (int h2 = 0; h2 < 2; h2++) {
                const int m = m0 + wm + mt * 16 + g + h2 * 8;
                const float2 gg = *(const float2*)&g_G[(size_t)m * 1024 + n];
                float2 v;
                v.x = gg.x * (acc[mt][nf][h2 * 2 + 0] + bx);
                v.y = gg.y * (acc[mt][nf][h2 * 2 + 1] + by);
                *(float2*)&out[(size_t)m * 1024 + n] = v;
            }
        }
    }
}

// ---------------------------------------------------------------------------
extern "C" void kernel_launch(void* const* d_in, const int* in_sizes, int n_in,
                              void* d_out, int out_size)
{
    (void)in_sizes; (void)n_in; (void)out_size;
    const float* query_g = (const float*)d_in[0];
    const float* key_g   = (const float*)d_in[1];
    const float* query_a = (const float*)d_in[2];
    const float* key_a   = (const float*)d_in[3];
    const float* value_a = (const float*)d_in[4];
    const int*   mask    = (const int*)  d_in[5];
    const float* Wqg = (const float*)d_in[6];  const float* bqg = (const float*)d_in[7];
    const float* Wkg = (const float*)d_in[8];  const float* bkg = (const float*)d_in[9];
    const float* Wqa = (const float*)d_in[10]; const float* bqa = (const float*)d_in[11];
    const float* Wka = (const float*)d_in[12]; const float* bka = (const float*)d_in[13];
    const float* Wva = (const float*)d_in[14]; const float* bva = (const float*)d_in[15];
    const float* Wgate = (const float*)d_in[16]; const float* bgate = (const float*)d_in[17];
    const float* Winfo = (const float*)d_in[18]; const float* binfo = (const float*)d_in[19];

    static int smem_set = 0;
    if (!smem_set) {
        cudaFuncSetAttribute(attn_kernel, cudaFuncAttributeMaxDynamicSharedMemorySize, ATTN_SMEM);
        smem_set = 1;
    }

    dim3 blk(256);
    proj_kernel<<<dim3(8, 32, 5), blk>>>(query_a, query_g, key_a, key_g, value_a,
                                         Wqa, Wqg, Wka, Wkg, Wva,
                                         bqa, bqg, bka, bkg, bva);
    gate_kernel<<<dim3(8, 32, 1), blk>>>(query_a, query_g, Wgate, bgate);
    attn_kernel<<<dim3(8, 64), blk, ATTN_SMEM>>>(mask);
    info_kernel<<<dim3(8, 32, 1), blk>>>(Winfo, binfo, (float*)d_out);
}

// round 9
// speedup vs baseline: 1.5619x; 1.4204x over previous
#include <cuda_runtime.h>
#include <cuda_bf16.h>
#include <cuda_fp16.h>
#include <math.h>
#include <stdint.h>

// Problem constants
#define B_  4
#define S_  1024
#define D_  1024
#define H_  16
#define BH  64     // B*H

// Scratch
static __device__ float g_Q[(size_t)BH * S_ * 128];   // [bh, s, 128] (qa|qg)
static __device__ float g_K[(size_t)BH * S_ * 128];   // [bh, s, 128] (ka|kg)
static __device__ float g_V[(size_t)BH * 64 * S_];    // TRANSPOSED [bh, j(64), s(1024)]
static __device__ float g_X[(size_t)B_ * S_ * D_];    // attn out [token][1024]
static __device__ float g_G[(size_t)B_ * S_ * D_];    // gate

// ---------------------------------------------------------------------------
// Precision helpers
// ---------------------------------------------------------------------------
__device__ __forceinline__ void cvt_split2(float x, float y, uint32_t &hi, uint32_t &lo) {
    __nv_bfloat16 hx = __float2bfloat16_rn(x);
    __nv_bfloat16 hy = __float2bfloat16_rn(y);
    float rx = x - __bfloat162float(hx);
    float ry = y - __bfloat162float(hy);
    __nv_bfloat16 lx = __float2bfloat16_rn(rx);
    __nv_bfloat16 ly = __float2bfloat16_rn(ry);
    hi = (uint32_t)__bfloat16_as_ushort(hx) | ((uint32_t)__bfloat16_as_ushort(hy) << 16);
    lo = (uint32_t)__bfloat16_as_ushort(lx) | ((uint32_t)__bfloat16_as_ushort(ly) << 16);
}

__device__ __forceinline__ uint32_t pack_h2(float x, float y) {
    __half2 h = __floats2half2_rn(x, y);
    return *(uint32_t*)&h;
}

__device__ __forceinline__ void mma_bf16(float* c,
    uint32_t a0, uint32_t a1, uint32_t a2, uint32_t a3,
    uint32_t b0, uint32_t b1)
{
    asm volatile(
        "mma.sync.aligned.m16n8k16.row.col.f32.bf16.bf16.f32 "
        "{%0,%1,%2,%3},{%4,%5,%6,%7},{%8,%9},{%0,%1,%2,%3};"
        : "+f"(c[0]), "+f"(c[1]), "+f"(c[2]), "+f"(c[3])
        : "r"(a0), "r"(a1), "r"(a2), "r"(a3), "r"(b0), "r"(b1));
}

__device__ __forceinline__ void mma_fp16(float* c,
    uint32_t a0, uint32_t a1, uint32_t a2, uint32_t a3,
    uint32_t b0, uint32_t b1)
{
    asm volatile(
        "mma.sync.aligned.m16n8k16.row.col.f32.f16.f16.f32 "
        "{%0,%1,%2,%3},{%4,%5,%6,%7},{%8,%9},{%0,%1,%2,%3};"
        : "+f"(c[0]), "+f"(c[1]), "+f"(c[2]), "+f"(c[3])
        : "r"(a0), "r"(a1), "r"(a2), "r"(a3), "r"(b0), "r"(b1));
}

// ---------------------------------------------------------------------------
// Shared pieces: 128x128 C tile, 256 thr = 8 warps (4m x 2n), warp 32x64,
// k-tile = 32 floats. Register-prefetch pipeline (R4 issue order).
// ---------------------------------------------------------------------------
typedef uint32_t (*SmT)[20];

__device__ __forceinline__ void load_ab_regs(
    const float* __restrict__ A, int lda,
    const float* __restrict__ A2, int ksplit,
    const float* __restrict__ Bm, int ldb,
    int m0, int n0, int k0, int k4, int ar,
    float4 va[4], float4 vb[4])
{
    const int colA = k0 + k4;
    const float* abase; int ldaa;
    if (colA >= ksplit) { abase = A2 + (colA - ksplit); ldaa = 1024; }
    else                { abase = A  + colA;            ldaa = lda;  }
    #pragma unroll
    for (int i = 0; i < 4; i++) {
        const int m = ar + i * 32;
        va[i] = *(const float4*)(abase + (size_t)(m0 + m) * ldaa);
        vb[i] = *(const float4*)(Bm + (size_t)(n0 + m) * ldb + k0 + k4);
    }
}

// ======================= bf16 3-term body (R4 order) =======================
__device__ __forceinline__ void store_tile_bf16(
    const float4 va[4], const float4 vb[4], int k4, int ar,
    SmT Ah, SmT Al, SmT Bh, SmT Bl)
{
    const int pc = k4 >> 1;
    #pragma unroll
    for (int i = 0; i < 4; i++) {
        const int m = ar + i * 32;
        uint32_t h0, l0, h1, l1;
        cvt_split2(va[i].x, va[i].y, h0, l0);
        cvt_split2(va[i].z, va[i].w, h1, l1);
        Ah[m][pc] = h0; Ah[m][pc + 1] = h1;
        Al[m][pc] = l0; Al[m][pc + 1] = l1;
        cvt_split2(vb[i].x, vb[i].y, h0, l0);
        cvt_split2(vb[i].z, vb[i].w, h1, l1);
        Bh[m][pc] = h0; Bh[m][pc + 1] = h1;
        Bl[m][pc] = l0; Bl[m][pc + 1] = l1;
    }
}

__device__ __forceinline__ void gemm_bf16_body(
    const float* __restrict__ A, int lda,
    const float* __restrict__ A2, int ksplit,
    const float* __restrict__ Bm, int ldb,
    int K, int m0, int n0,
    float acc[2][8][4],
    SmT Ah, SmT Al, SmT Bh, SmT Bl)
{
    const int tid  = threadIdx.x;
    const int warp = tid >> 5, lane = tid & 31;
    const int wm = (warp & 3) * 32;
    const int wn = (warp >> 2) * 64;
    const int g  = lane >> 2;
    const int t  = lane & 3;
    const int k4 = (tid & 7) * 4;
    const int ar = tid >> 3;

    float4 va[4], vb[4];
    load_ab_regs(A, lda, A2, ksplit, Bm, ldb, m0, n0, 0, k4, ar, va, vb);

    for (int k0 = 0; k0 < K; k0 += 32) {
        __syncthreads();
        store_tile_bf16(va, vb, k4, ar, Ah, Al, Bh, Bl);
        __syncthreads();

        if (k0 + 32 < K)
            load_ab_regs(A, lda, A2, ksplit, Bm, ldb, m0, n0, k0 + 32, k4, ar, va, vb);

        #pragma unroll
        for (int kk = 0; kk < 2; kk++) {
            const int pc = kk * 8;
            uint32_t ah[2][4], al[2][4];
            #pragma unroll
            for (int mt = 0; mt < 2; mt++) {
                #pragma unroll
                for (int q = 0; q < 4; q++) {
                    const int row = wm + mt * 16 + g + (q & 1) * 8;
                    const int col = pc + t + (q >> 1) * 4;
                    ah[mt][q] = Ah[row][col];
                    al[mt][q] = Al[row][col];
                }
            }
            #pragma unroll
            for (int nf = 0; nf < 8; nf++) {
                const int rb = wn + nf * 8 + g;
                const uint32_t bh0 = Bh[rb][pc + t], bh1 = Bh[rb][pc + t + 4];
                const uint32_t bl0 = Bl[rb][pc + t], bl1 = Bl[rb][pc + t + 4];
                #pragma unroll
                for (int mt = 0; mt < 2; mt++) {
                    mma_bf16(acc[mt][nf], ah[mt][0], ah[mt][1], ah[mt][2], ah[mt][3], bh0, bh1);
                    mma_bf16(acc[mt][nf], ah[mt][0], ah[mt][1], ah[mt][2], ah[mt][3], bl0, bl1);
                    mma_bf16(acc[mt][nf], al[mt][0], al[mt][1], al[mt][2], al[mt][3], bh0, bh1);
                }
            }
        }
    }
}

// ======================= fp16 single-term body =======================
__device__ __forceinline__ void store_tile_fp16(
    const float4 va[4], const float4 vb[4], int k4, int ar,
    SmT Ah, SmT Bh)
{
    const int pc = k4 >> 1;
    #pragma unroll
    for (int i = 0; i < 4; i++) {
        const int m = ar + i * 32;
        Ah[m][pc]     = pack_h2(va[i].x, va[i].y);
        Ah[m][pc + 1] = pack_h2(va[i].z, va[i].w);
        Bh[m][pc]     = pack_h2(vb[i].x, vb[i].y);
        Bh[m][pc + 1] = pack_h2(vb[i].z, vb[i].w);
    }
}

__device__ __forceinline__ void gemm_fp16_body(
    const float* __restrict__ A, int lda,
    const float* __restrict__ A2, int ksplit,
    const float* __restrict__ Bm, int ldb,
    int K, int m0, int n0,
    float acc[2][8][4],
    SmT Ah, SmT Bh)
{
    const int tid  = threadIdx.x;
    const int warp = tid >> 5, lane = tid & 31;
    const int wm = (warp & 3) * 32;
    const int wn = (warp >> 2) * 64;
    const int g  = lane >> 2;
    const int t  = lane & 3;
    const int k4 = (tid & 7) * 4;
    const int ar = tid >> 3;

    float4 va[4], vb[4];
    load_ab_regs(A, lda, A2, ksplit, Bm, ldb, m0, n0, 0, k4, ar, va, vb);

    for (int k0 = 0; k0 < K; k0 += 32) {
        __syncthreads();
        store_tile_fp16(va, vb, k4, ar, Ah, Bh);
        __syncthreads();

        if (k0 + 32 < K)
            load_ab_regs(A, lda, A2, ksplit, Bm, ldb, m0, n0, k0 + 32, k4, ar, va, vb);

        #pragma unroll
        for (int kk = 0; kk < 2; kk++) {
            const int pc = kk * 8;
            uint32_t ah[2][4];
            #pragma unroll
            for (int mt = 0; mt < 2; mt++) {
                #pragma unroll
                for (int q = 0; q < 4; q++) {
                    const int row = wm + mt * 16 + g + (q & 1) * 8;
                    const int col = pc + t + (q >> 1) * 4;
                    ah[mt][q] = Ah[row][col];
                }
            }
            #pragma unroll
            for (int nf = 0; nf < 8; nf++) {
                const int rb = wn + nf * 8 + g;
                const uint32_t b0 = Bh[rb][pc + t], b1 = Bh[rb][pc + t + 4];
                #pragma unroll
                for (int mt = 0; mt < 2; mt++)
                    mma_fp16(acc[mt][nf], ah[mt][0], ah[mt][1], ah[mt][2], ah[mt][3], b0, b1);
            }
        }
    }
}

// ---------------------------------------------------------------------------
// Kernel 1a: Q/K projections (bf16 3-term), grid.z in 0..3.
// ---------------------------------------------------------------------------
__global__ __launch_bounds__(256, 2) void projqk_kernel(
    const float* __restrict__ qa_in, const float* __restrict__ qg_in,
    const float* __restrict__ ka_in, const float* __restrict__ kg_in,
    const float* __restrict__ Wqa, const float* __restrict__ Wqg,
    const float* __restrict__ Wka, const float* __restrict__ Wkg,
    const float* __restrict__ bqa, const float* __restrict__ bqg,
    const float* __restrict__ bka, const float* __restrict__ bkg)
{
    __shared__ uint32_t Ah[128][20], Al[128][20], Bh[128][20], Bl[128][20];
    const int p = blockIdx.z;
    const float* A; const float* W; const float* bias;
    if      (p == 0) { A = qa_in; W = Wqa; bias = bqa; }
    else if (p == 1) { A = qg_in; W = Wqg; bias = bqg; }
    else if (p == 2) { A = ka_in; W = Wka; bias = bka; }
    else             { A = kg_in; W = Wkg; bias = bkg; }

    const int m0 = blockIdx.y * 128;
    const int n0 = blockIdx.x * 128;
    float acc[2][8][4] = {};
    gemm_bf16_body(A, 1024, nullptr, 1 << 30, W, 1024, 1024, m0, n0, acc,
                   (SmT)Ah, (SmT)Al, (SmT)Bh, (SmT)Bl);

    const int lane = threadIdx.x & 31, warp = threadIdx.x >> 5;
    const int wm = (warp & 3) * 32, wn = (warp >> 2) * 64;
    const int g = lane >> 2, t = lane & 3;

    #pragma unroll
    for (int nf = 0; nf < 8; nf++) {
        const int n  = n0 + wn + nf * 8 + 2 * t;
        const int h  = n >> 6, jj = n & 63;
        const float bx = bias[n], by = bias[n + 1];
        #pragma unroll
        for (int mt = 0; mt < 2; mt++) {
            #pragma unroll
            for (int h2 = 0; h2 < 2; h2++) {
                const int m = m0 + wm + mt * 16 + g + h2 * 8;
                const int b = m >> 10, s = m & 1023;
                const size_t bhh = (size_t)(b * 16 + h);
                float2 v;
                v.x = acc[mt][nf][h2 * 2 + 0] + bx;
                v.y = acc[mt][nf][h2 * 2 + 1] + by;
                if      (p == 0) *(float2*)&g_Q[(bhh * 1024 + s) * 128 + jj]      = v;
                else if (p == 1) *(float2*)&g_Q[(bhh * 1024 + s) * 128 + 64 + jj] = v;
                else if (p == 2) *(float2*)&g_K[(bhh * 1024 + s) * 128 + jj]      = v;
                else             *(float2*)&g_K[(bhh * 1024 + s) * 128 + 64 + jj] = v;
            }
        }
    }
}

// ---------------------------------------------------------------------------
// Kernel 1b: V projection (fp16 single). Writes g_V transposed.
// ---------------------------------------------------------------------------
__global__ __launch_bounds__(256, 2) void projv_kernel(
    const float* __restrict__ va_in, const float* __restrict__ Wva,
    const float* __restrict__ bva)
{
    __shared__ uint32_t Ah[128][20], Bh[128][20];
    const int m0 = blockIdx.y * 128;
    const int n0 = blockIdx.x * 128;
    float acc[2][8][4] = {};
    gemm_fp16_body(va_in, 1024, nullptr, 1 << 30, Wva, 1024, 1024, m0, n0, acc,
                   (SmT)Ah, (SmT)Bh);

    const int lane = threadIdx.x & 31, warp = threadIdx.x >> 5;
    const int wm = (warp & 3) * 32, wn = (warp >> 2) * 64;
    const int g = lane >> 2, t = lane & 3;

    #pragma unroll
    for (int nf = 0; nf < 8; nf++) {
        const int n  = n0 + wn + nf * 8 + 2 * t;
        const int h  = n >> 6, jj = n & 63;
        const float bx = bva[n], by = bva[n + 1];
        #pragma unroll
        for (int mt = 0; mt < 2; mt++) {
            #pragma unroll
            for (int h2 = 0; h2 < 2; h2++) {
                const int m = m0 + wm + mt * 16 + g + h2 * 8;
                const int b = m >> 10, s = m & 1023;
                const size_t bhh = (size_t)(b * 16 + h);
                g_V[(bhh * 64 + jj)     * 1024 + s] = acc[mt][nf][h2 * 2 + 0] + bx;
                g_V[(bhh * 64 + jj + 1) * 1024 + s] = acc[mt][nf][h2 * 2 + 1] + by;
            }
        }
    }
}

// ---------------------------------------------------------------------------
// Kernel 2: gate = sigmoid(concat(qa,qg) @ Wgate^T + bgate)  (fp16 single)
// ---------------------------------------------------------------------------
__global__ __launch_bounds__(256, 2) void gate_kernel(
    const float* __restrict__ qa_in, const float* __restrict__ qg_in,
    const float* __restrict__ Wgate, const float* __restrict__ bgate)
{
    __shared__ uint32_t Ah[128][20], Bh[128][20];
    const int m0 = blockIdx.y * 128;
    const int n0 = blockIdx.x * 128;
    float acc[2][8][4] = {};
    gemm_fp16_body(qa_in, 1024, qg_in, 1024, Wgate, 2048, 2048, m0, n0, acc,
                   (SmT)Ah, (SmT)Bh);

    const int lane = threadIdx.x & 31, warp = threadIdx.x >> 5;
    const int wm = (warp & 3) * 32, wn = (warp >> 2) * 64;
    const int g = lane >> 2, t = lane & 3;

    #pragma unroll
    for (int nf = 0; nf < 8; nf++) {
        const int n = n0 + wn + nf * 8 + 2 * t;
        const float bx = bgate[n], by = bgate[n + 1];
        #pragma unroll
        for (int mt = 0; mt < 2; mt++) {
            #pragma unroll
            for (int h2 = 0; h2 < 2; h2++) {
                const int m = m0 + wm + mt * 16 + g + h2 * 8;
                float2 v;
                v.x = 1.0f / (1.0f + __expf(-(acc[mt][nf][h2 * 2 + 0] + bx)));
                v.y = 1.0f / (1.0f + __expf(-(acc[mt][nf][h2 * 2 + 1] + by)));
                *(float2*)&g_G[(size_t)m * 1024 + n] = v;
            }
        }
    }
}

// ---------------------------------------------------------------------------
// Kernel 3: fused flash attention.
// QK^T: bf16 3-term (precision-critical). PV: fp16 single.
// ---------------------------------------------------------------------------
#define ATTN_SMEM 176128

__global__ __launch_bounds__(256) void attn_kernel(const int* __restrict__ mask)
{
    extern __shared__ char smem[];
    uint32_t (*Qh)[68] = (uint32_t(*)[68])(smem);
    uint32_t (*Ql)[68] = (uint32_t(*)[68])(smem + 34816);
    uint32_t (*Kh)[68] = (uint32_t(*)[68])(smem + 69632);
    uint32_t (*Kl)[68] = (uint32_t(*)[68])(smem + 104448);
    uint32_t (*Vh)[68] = (uint32_t(*)[68])(smem + 139264);   // fp16 pairs
    float* redmax = (float*)(smem + 174080);
    float* redsum = (float*)(smem + 175104);
    float* Osum   = (float*)(smem + 69632);   // reuse K region post-loop

    const int tid  = threadIdx.x;
    const int warp = tid >> 5, lane = tid & 31;
    const int wm = (warp & 3) * 32;
    const int wn = (warp >> 2);
    const int g  = lane >> 2;
    const int t  = lane & 3;

    const int bh = blockIdx.y;
    const int b  = bh >> 4, h = bh & 15;
    const int m0 = blockIdx.x * 128;

    const float* Qg = g_Q + ((size_t)bh << 17);
    const float* Kg = g_K + ((size_t)bh << 17);
    const float* Vg = g_V + ((size_t)bh << 16);

    const int lrow = tid >> 5;
    const int col4 = (tid & 31) * 4;
    const int pcw  = (tid & 31) * 2;

    #pragma unroll
    for (int i = 0; i < 16; i++) {
        const int r = lrow + i * 8;
        float4 v = *(const float4*)(Qg + (size_t)(m0 + r) * 128 + col4);
        uint32_t h0, l0, h1, l1;
        cvt_split2(v.x, v.y, h0, l0);
        cvt_split2(v.z, v.w, h1, l1);
        Qh[r][pcw] = h0; Qh[r][pcw + 1] = h1;
        Ql[r][pcw] = l0; Ql[r][pcw + 1] = l1;
    }

    float o[2][8][4] = {};
    float mrun[2][2] = {{-INFINITY, -INFINITY}, {-INFINITY, -INFINITY}};
    float lrun[2][2] = {};
    const float scale = 0.08838834764831845f;

    for (int nt = 0; nt < 8; nt++) {
        const int n0 = nt * 128;
        __syncthreads();

        #pragma unroll
        for (int i = 0; i < 16; i++) {
            const int r = lrow + i * 8;
            float4 v = *(const float4*)(Kg + (size_t)(n0 + r) * 128 + col4);
            uint32_t h0, l0, h1, l1;
            cvt_split2(v.x, v.y, h0, l0);
            cvt_split2(v.z, v.w, h1, l1);
            Kh[r][pcw] = h0; Kh[r][pcw + 1] = h1;
            Kl[r][pcw] = l0; Kl[r][pcw + 1] = l1;
        }
        #pragma unroll
        for (int i = 0; i < 8; i++) {
            const int r = lrow + i * 8;
            float4 v = *(const float4*)(Vg + (size_t)r * 1024 + n0 + col4);
            Vh[r][pcw]     = pack_h2(v.x, v.y);
            Vh[r][pcw + 1] = pack_h2(v.z, v.w);
        }
        __syncthreads();

        // ---- S = Q K^T (bf16 3-term, R4 issue order) ----
        float s[2][8][4] = {};
        #pragma unroll
        for (int ks = 0; ks < 8; ks++) {
            const int pc = ks * 8;
            uint32_t ah[2][4], al[2][4];
            #pragma unroll
            for (int mt = 0; mt < 2; mt++) {
                #pragma unroll
                for (int q = 0; q < 4; q++) {
                    const int row = wm + mt * 16 + g + (q & 1) * 8;
                    const int col = pc + t + (q >> 1) * 4;
                    ah[mt][q] = Qh[row][col];
                    al[mt][q] = Ql[row][col];
                }
            }
            #pragma unroll
            for (int nf = 0; nf < 8; nf++) {
                const int rb = wn * 64 + nf * 8 + g;
                const uint32_t bh0 = Kh[rb][pc + t], bh1 = Kh[rb][pc + t + 4];
                const uint32_t bl0 = Kl[rb][pc + t], bl1 = Kl[rb][pc + t + 4];
                #pragma unroll
                for (int mt = 0; mt < 2; mt++) {
                    mma_bf16(s[mt][nf], ah[mt][0], ah[mt][1], ah[mt][2], ah[mt][3], bh0, bh1);
                    mma_bf16(s[mt][nf], ah[mt][0], ah[mt][1], ah[mt][2], ah[mt][3], bl0, bl1);
                    mma_bf16(s[mt][nf], al[mt][0], al[mt][1], al[mt][2], al[mt][3], bh0, bh1);
                }
            }
        }

        // ---- scale + mask + row max ----
        float pm[2][2];
        #pragma unroll
        for (int mt = 0; mt < 2; mt++) {
            #pragma unroll
            for (int h2 = 0; h2 < 2; h2++) {
                const int rglob = m0 + wm + mt * 16 + g + h2 * 8;
                float mx = -INFINITY;
                #pragma unroll
                for (int nf = 0; nf < 8; nf++) {
                    const int ncol = n0 + wn * 64 + nf * 8 + 2 * t;
                    const int2 mk = *(const int2*)(mask + (((size_t)b << 20) + ((size_t)rglob << 10) + ncol));
                    float v0 = s[mt][nf][h2 * 2 + 0] * scale;
                    float v1 = s[mt][nf][h2 * 2 + 1] * scale;
                    if (mk.x == 0) v0 = -1e9f;
                    if (mk.y == 0) v1 = -1e9f;
                    s[mt][nf][h2 * 2 + 0] = v0;
                    s[mt][nf][h2 * 2 + 1] = v1;
                    mx = fmaxf(mx, fmaxf(v0, v1));
                }
                pm[mt][h2] = mx;
            }
        }
        #pragma unroll
        for (int mt = 0; mt < 2; mt++)
            #pragma unroll
            for (int h2 = 0; h2 < 2; h2++) {
                pm[mt][h2] = fmaxf(pm[mt][h2], __shfl_xor_sync(0xffffffffu, pm[mt][h2], 1));
                pm[mt][h2] = fmaxf(pm[mt][h2], __shfl_xor_sync(0xffffffffu, pm[mt][h2], 2));
            }
        if (t == 0) {
            #pragma unroll
            for (int mt = 0; mt < 2; mt++)
                #pragma unroll
                for (int h2 = 0; h2 < 2; h2++)
                    redmax[wn * 128 + wm + mt * 16 + g + h2 * 8] = pm[mt][h2];
        }
        __syncthreads();

        // ---- running stats, exponentiate, rescale O ----
        float alpha[2][2], psum[2][2];
        #pragma unroll
        for (int mt = 0; mt < 2; mt++) {
            #pragma unroll
            for (int h2 = 0; h2 < 2; h2++) {
                const int rl = wm + mt * 16 + g + h2 * 8;
                const float mtile = fmaxf(redmax[rl], redmax[128 + rl]);
                const float mnew  = fmaxf(mrun[mt][h2], mtile);
                alpha[mt][h2] = __expf(mrun[mt][h2] - mnew);
                mrun[mt][h2]  = mnew;
                float ps = 0.0f;
                #pragma unroll
                for (int nf = 0; nf < 8; nf++) {
                    float p0 = __expf(s[mt][nf][h2 * 2 + 0] - mnew);
                    float p1 = __expf(s[mt][nf][h2 * 2 + 1] - mnew);
                    s[mt][nf][h2 * 2 + 0] = p0;
                    s[mt][nf][h2 * 2 + 1] = p1;
                    ps += p0 + p1;
                }
                psum[mt][h2] = ps;
            }
        }
        #pragma unroll
        for (int mt = 0; mt < 2; mt++)
            #pragma unroll
            for (int nf = 0; nf < 8; nf++)
                #pragma unroll
                for (int e = 0; e < 4; e++)
                    o[mt][nf][e] *= alpha[mt][e >> 1];
        #pragma unroll
        for (int mt = 0; mt < 2; mt++)
            #pragma unroll
            for (int h2 = 0; h2 < 2; h2++) {
                psum[mt][h2] += __shfl_xor_sync(0xffffffffu, psum[mt][h2], 1);
                psum[mt][h2] += __shfl_xor_sync(0xffffffffu, psum[mt][h2], 2);
            }
        if (t == 0) {
            #pragma unroll
            for (int mt = 0; mt < 2; mt++)
                #pragma unroll
                for (int h2 = 0; h2 < 2; h2++)
                    redsum[wn * 128 + wm + mt * 16 + g + h2 * 8] = psum[mt][h2];
        }
        __syncthreads();
        #pragma unroll
        for (int mt = 0; mt < 2; mt++)
            #pragma unroll
            for (int h2 = 0; h2 < 2; h2++) {
                const int rl = wm + mt * 16 + g + h2 * 8;
                lrun[mt][h2] = lrun[mt][h2] * alpha[mt][h2] + redsum[rl] + redsum[128 + rl];
            }

        // ---- O += P V (fp16 single-term) ----
        #pragma unroll
        for (int ks2 = 0; ks2 < 4; ks2++) {
            uint32_t ah[2][4];
            #pragma unroll
            for (int mt = 0; mt < 2; mt++) {
                ah[mt][0] = pack_h2(s[mt][2 * ks2][0],     s[mt][2 * ks2][1]);
                ah[mt][1] = pack_h2(s[mt][2 * ks2][2],     s[mt][2 * ks2][3]);
                ah[mt][2] = pack_h2(s[mt][2 * ks2 + 1][0], s[mt][2 * ks2 + 1][1]);
                ah[mt][3] = pack_h2(s[mt][2 * ks2 + 1][2], s[mt][2 * ks2 + 1][3]);
            }
            const int vcol = wn * 32 + ks2 * 8 + t;
            #pragma unroll
            for (int nf = 0; nf < 8; nf++) {
                const int rv = nf * 8 + g;
                const uint32_t b0 = Vh[rv][vcol], b1 = Vh[rv][vcol + 4];
                #pragma unroll
                for (int mt = 0; mt < 2; mt++)
                    mma_fp16(o[mt][nf], ah[mt][0], ah[mt][1], ah[mt][2], ah[mt][3], b0, b1);
            }
        }
    }

    // ---- epilogue: combine the two n-warps' partials, normalize, store ----
    __syncthreads();
    if (wn == 1) {
        #pragma unroll
        for (int mt = 0; mt < 2; mt++)
            #pragma unroll
            for (int h2 = 0; h2 < 2; h2++) {
                const int rl = wm + mt * 16 + g + h2 * 8;
                #pragma unroll
                for (int nf = 0; nf < 8; nf++) {
                    float2 v;
                    v.x = o[mt][nf][h2 * 2 + 0];
                    v.y = o[mt][nf][h2 * 2 + 1];
                    *(float2*)&Osum[rl * 66 + nf * 8 + 2 * t] = v;
                }
            }
    }
    __syncthreads();
    if (wn == 0) {
        #pragma unroll
        for (int mt = 0; mt < 2; mt++)
            #pragma unroll
            for (int h2 = 0; h2 < 2; h2++) {
                const int rl = wm + mt * 16 + g + h2 * 8;
                const float inv = 1.0f / lrun[mt][h2];
                #pragma unroll
                for (int nf = 0; nf < 8; nf++) {
                    const int c = nf * 8 + 2 * t;
                    float2 p = *(float2*)&Osum[rl * 66 + c];
                    float2 v;
                    v.x = (o[mt][nf][h2 * 2 + 0] + p.x) * inv;
                    v.y = (o[mt][nf][h2 * 2 + 1] + p.y) * inv;
                    *(float2*)&g_X[(size_t)(b * 1024 + m0 + rl) * 1024 + h * 64 + c] = v;
                }
            }
    }
}

// ---------------------------------------------------------------------------
// Kernel 4: out = gate * (X @ Winfo^T + binfo)  (fp16 single)
// ---------------------------------------------------------------------------
__global__ __launch_bounds__(256, 2) void info_kernel(
    const float* __restrict__ Winfo, const float* __restrict__ binfo,
    float* __restrict__ out)
{
    __shared__ uint32_t Ah[128][20], Bh[128][20];
    const int m0 = blockIdx.y * 128;
    const int n0 = blockIdx.x * 128;
    float acc[2][8][4] = {};
    gemm_fp16_body(g_X, 1024, nullptr, 1 << 30, Winfo, 1024, 1024, m0, n0, acc,
                   (SmT)Ah, (SmT)Bh);

    const int lane = threadIdx.x & 31, warp = threadIdx.x >> 5;
    const int wm = (warp & 3) * 32, wn = (warp >> 2) * 64;
    const int g = lane >> 2, t = lane & 3;

    #pragma unroll
    for (int nf = 0; nf < 8; nf++) {
        const int n = n0 + wn + nf * 8 + 2 * t;
        const float bx = binfo[n], by = binfo[n + 1];
        #pragma unroll
        for (int mt = 0; mt < 2; mt++) {
            #pragma unroll
            for (int h2 = 0; h2 < 2; h2++) {
                const int m = m0 + wm + mt * 16 + g + h2 * 8;
                const float2 gg = *(const float2*)&g_G[(size_t)m * 1024 + n];
                float2 v;
                v.x = gg.x * (acc[mt][nf][h2 * 2 + 0] + bx);
                v.y = gg.y * (acc[mt][nf][h2 * 2 + 1] + by);
                *(float2*)&out[(size_t)m * 1024 + n] = v;
            }
        }
    }
}

// ---------------------------------------------------------------------------
extern "C" void kernel_launch(void* const* d_in, const int* in_sizes, int n_in,
                              void* d_out, int out_size)
{
    (void)in_sizes; (void)n_in; (void)out_size;
    const float* query_g = (const float*)d_in[0];
    const float* key_g   = (const float*)d_in[1];
    const float* query_a = (const float*)d_in[2];
    const float* key_a   = (const float*)d_in[3];
    const float* value_a = (const float*)d_in[4];
    const int*   mask    = (const int*)  d_in[5];
    const float* Wqg = (const float*)d_in[6];  const float* bqg = (const float*)d_in[7];
    const float* Wkg = (const float*)d_in[8];  const float* bkg = (const float*)d_in[9];
    const float* Wqa = (const float*)d_in[10]; const float* bqa = (const float*)d_in[11];
    const float* Wka = (const float*)d_in[12]; const float* bka = (const float*)d_in[13];
    const float* Wva = (const float*)d_in[14]; const float* bva = (const float*)d_in[15];
    const float* Wgate = (const float*)d_in[16]; const float* bgate = (const float*)d_in[17];
    const float* Winfo = (const float*)d_in[18]; const float* binfo = (const float*)d_in[19];

    static int smem_set = 0;
    if (!smem_set) {
        cudaFuncSetAttribute(attn_kernel, cudaFuncAttributeMaxDynamicSharedMemorySize, ATTN_SMEM);
        smem_set = 1;
    }

    dim3 blk(256);
    projqk_kernel<<<dim3(8, 32, 4), blk>>>(query_a, query_g, key_a, key_g,
                                           Wqa, Wqg, Wka, Wkg,
                                           bqa, bqg, bka, bkg);
    projv_kernel<<<dim3(8, 32, 1), blk>>>(value_a, Wva, bva);
    gate_kernel<<<dim3(8, 32, 1), blk>>>(query_a, query_g, Wgate, bgate);
    attn_kernel<<<dim3(8, 64), blk, ATTN_SMEM>>>(mask);
    info_kernel<<<dim3(8, 32, 1), blk>>>(Winfo, binfo, (float*)d_out);
}

// round 10
// speedup vs baseline: 2.1540x; 1.3790x over previous
#include <cuda_runtime.h>
#include <cuda_fp16.h>
#include <math.h>
#include <stdint.h>

// Problem constants
#define B_  4
#define S_  1024
#define D_  1024
#define H_  16
#define BH  64     // B*H

// Scratch
static __device__ float g_Q[(size_t)BH * S_ * 128];   // [bh, s, 128] (qa|qg)
static __device__ float g_K[(size_t)BH * S_ * 128];   // [bh, s, 128] (ka|kg)
static __device__ float g_V[(size_t)BH * 64 * S_];    // TRANSPOSED [bh, j(64), s(1024)]
static __device__ float g_X[(size_t)B_ * S_ * D_];    // attn out [token][1024]
static __device__ float g_G[(size_t)B_ * S_ * D_];    // gate

// ---------------------------------------------------------------------------
__device__ __forceinline__ uint32_t pack_h2(float x, float y) {
    __half2 h = __floats2half2_rn(x, y);
    return *(uint32_t*)&h;
}

__device__ __forceinline__ void mma_fp16(float* c,
    uint32_t a0, uint32_t a1, uint32_t a2, uint32_t a3,
    uint32_t b0, uint32_t b1)
{
    asm volatile(
        "mma.sync.aligned.m16n8k16.row.col.f32.f16.f16.f32 "
        "{%0,%1,%2,%3},{%4,%5,%6,%7},{%8,%9},{%0,%1,%2,%3};"
        : "+f"(c[0]), "+f"(c[1]), "+f"(c[2]), "+f"(c[3])
        : "r"(a0), "r"(a1), "r"(a2), "r"(a3), "r"(b0), "r"(b1));
}

// ---------------------------------------------------------------------------
// fp16 single-term GEMM: C[128,128] = A * B^T, K contiguous both sides.
// 256 thr = 8 warps (4m x 2n), warp 32x64, register-prefetch pipeline.
// smem: Ah/Bh [128][20] packed fp16 pairs.
// ---------------------------------------------------------------------------
typedef uint32_t (*SmT)[20];

__device__ __forceinline__ void load_ab_regs(
    const float* __restrict__ A, int lda,
    const float* __restrict__ A2, int ksplit,
    const float* __restrict__ Bm, int ldb,
    int m0, int n0, int k0, int k4, int ar,
    float4 va[4], float4 vb[4])
{
    const int colA = k0 + k4;
    const float* abase; int ldaa;
    if (colA >= ksplit) { abase = A2 + (colA - ksplit); ldaa = 1024; }
    else                { abase = A  + colA;            ldaa = lda;  }
    #pragma unroll
    for (int i = 0; i < 4; i++) {
        const int m = ar + i * 32;
        va[i] = *(const float4*)(abase + (size_t)(m0 + m) * ldaa);
        vb[i] = *(const float4*)(Bm + (size_t)(n0 + m) * ldb + k0 + k4);
    }
}

__device__ __forceinline__ void store_tile_fp16(
    const float4 va[4], const float4 vb[4], int k4, int ar,
    SmT Ah, SmT Bh)
{
    const int pc = k4 >> 1;
    #pragma unroll
    for (int i = 0; i < 4; i++) {
        const int m = ar + i * 32;
        Ah[m][pc]     = pack_h2(va[i].x, va[i].y);
        Ah[m][pc + 1] = pack_h2(va[i].z, va[i].w);
        Bh[m][pc]     = pack_h2(vb[i].x, vb[i].y);
        Bh[m][pc + 1] = pack_h2(vb[i].z, vb[i].w);
    }
}

__device__ __forceinline__ void gemm_fp16_body(
    const float* __restrict__ A, int lda,
    const float* __restrict__ A2, int ksplit,
    const float* __restrict__ Bm, int ldb,
    int K, int m0, int n0,
    float acc[2][8][4],
    SmT Ah, SmT Bh)
{
    const int tid  = threadIdx.x;
    const int warp = tid >> 5, lane = tid & 31;
    const int wm = (warp & 3) * 32;
    const int wn = (warp >> 2) * 64;
    const int g  = lane >> 2;
    const int t  = lane & 3;
    const int k4 = (tid & 7) * 4;
    const int ar = tid >> 3;

    float4 va[4], vb[4];
    load_ab_regs(A, lda, A2, ksplit, Bm, ldb, m0, n0, 0, k4, ar, va, vb);

    for (int k0 = 0; k0 < K; k0 += 32) {
        __syncthreads();
        store_tile_fp16(va, vb, k4, ar, Ah, Bh);
        __syncthreads();

        if (k0 + 32 < K)
            load_ab_regs(A, lda, A2, ksplit, Bm, ldb, m0, n0, k0 + 32, k4, ar, va, vb);

        #pragma unroll
        for (int kk = 0; kk < 2; kk++) {
            const int pc = kk * 8;
            uint32_t ah[2][4];
            #pragma unroll
            for (int mt = 0; mt < 2; mt++) {
                #pragma unroll
                for (int q = 0; q < 4; q++) {
                    const int row = wm + mt * 16 + g + (q & 1) * 8;
                    const int col = pc + t + (q >> 1) * 4;
                    ah[mt][q] = Ah[row][col];
                }
            }
            #pragma unroll
            for (int nf = 0; nf < 8; nf++) {
                const int rb = wn + nf * 8 + g;
                const uint32_t b0 = Bh[rb][pc + t], b1 = Bh[rb][pc + t + 4];
                #pragma unroll
                for (int mt = 0; mt < 2; mt++)
                    mma_fp16(acc[mt][nf], ah[mt][0], ah[mt][1], ah[mt][2], ah[mt][3], b0, b1);
            }
        }
    }
}

// ---------------------------------------------------------------------------
// Kernel 1: all 5 head projections (fp16 single), grid.z selects which.
// ---------------------------------------------------------------------------
__global__ __launch_bounds__(256, 2) void proj_kernel(
    const float* __restrict__ qa_in, const float* __restrict__ qg_in,
    const float* __restrict__ ka_in, const float* __restrict__ kg_in,
    const float* __restrict__ va_in,
    const float* __restrict__ Wqa, const float* __restrict__ Wqg,
    const float* __restrict__ Wka, const float* __restrict__ Wkg,
    const float* __restrict__ Wva,
    const float* __restrict__ bqa, const float* __restrict__ bqg,
    const float* __restrict__ bka, const float* __restrict__ bkg,
    const float* __restrict__ bva)
{
    __shared__ uint32_t Ah[128][20], Bh[128][20];
    const int p = blockIdx.z;
    const float* A; const float* W; const float* bias;
    if      (p == 0) { A = qa_in; W = Wqa; bias = bqa; }
    else if (p == 1) { A = qg_in; W = Wqg; bias = bqg; }
    else if (p == 2) { A = ka_in; W = Wka; bias = bka; }
    else if (p == 3) { A = kg_in; W = Wkg; bias = bkg; }
    else             { A = va_in; W = Wva; bias = bva; }

    const int m0 = blockIdx.y * 128;
    const int n0 = blockIdx.x * 128;
    float acc[2][8][4] = {};
    gemm_fp16_body(A, 1024, nullptr, 1 << 30, W, 1024, 1024, m0, n0, acc,
                   (SmT)Ah, (SmT)Bh);

    const int lane = threadIdx.x & 31, warp = threadIdx.x >> 5;
    const int wm = (warp & 3) * 32, wn = (warp >> 2) * 64;
    const int g = lane >> 2, t = lane & 3;

    #pragma unroll
    for (int nf = 0; nf < 8; nf++) {
        const int n  = n0 + wn + nf * 8 + 2 * t;
        const int h  = n >> 6, jj = n & 63;
        const float bx = bias[n], by = bias[n + 1];
        #pragma unroll
        for (int mt = 0; mt < 2; mt++) {
            #pragma unroll
            for (int h2 = 0; h2 < 2; h2++) {
                const int m = m0 + wm + mt * 16 + g + h2 * 8;
                const int b = m >> 10, s = m & 1023;
                const size_t bhh = (size_t)(b * 16 + h);
                float2 v;
                v.x = acc[mt][nf][h2 * 2 + 0] + bx;
                v.y = acc[mt][nf][h2 * 2 + 1] + by;
                if      (p == 0) *(float2*)&g_Q[(bhh * 1024 + s) * 128 + jj]      = v;
                else if (p == 1) *(float2*)&g_Q[(bhh * 1024 + s) * 128 + 64 + jj] = v;
                else if (p == 2) *(float2*)&g_K[(bhh * 1024 + s) * 128 + jj]      = v;
                else if (p == 3) *(float2*)&g_K[(bhh * 1024 + s) * 128 + 64 + jj] = v;
                else {
                    g_V[(bhh * 64 + jj)     * 1024 + s] = v.x;
                    g_V[(bhh * 64 + jj + 1) * 1024 + s] = v.y;
                }
            }
        }
    }
}

// ---------------------------------------------------------------------------
// Kernel 2: gate = sigmoid(concat(qa,qg) @ Wgate^T + bgate)  (fp16 single)
// ---------------------------------------------------------------------------
__global__ __launch_bounds__(256, 2) void gate_kernel(
    const float* __restrict__ qa_in, const float* __restrict__ qg_in,
    const float* __restrict__ Wgate, const float* __restrict__ bgate)
{
    __shared__ uint32_t Ah[128][20], Bh[128][20];
    const int m0 = blockIdx.y * 128;
    const int n0 = blockIdx.x * 128;
    float acc[2][8][4] = {};
    gemm_fp16_body(qa_in, 1024, qg_in, 1024, Wgate, 2048, 2048, m0, n0, acc,
                   (SmT)Ah, (SmT)Bh);

    const int lane = threadIdx.x & 31, warp = threadIdx.x >> 5;
    const int wm = (warp & 3) * 32, wn = (warp >> 2) * 64;
    const int g = lane >> 2, t = lane & 3;

    #pragma unroll
    for (int nf = 0; nf < 8; nf++) {
        const int n = n0 + wn + nf * 8 + 2 * t;
        const float bx = bgate[n], by = bgate[n + 1];
        #pragma unroll
        for (int mt = 0; mt < 2; mt++) {
            #pragma unroll
            for (int h2 = 0; h2 < 2; h2++) {
                const int m = m0 + wm + mt * 16 + g + h2 * 8;
                float2 v;
                v.x = 1.0f / (1.0f + __expf(-(acc[mt][nf][h2 * 2 + 0] + bx)));
                v.y = 1.0f / (1.0f + __expf(-(acc[mt][nf][h2 * 2 + 1] + by)));
                *(float2*)&g_G[(size_t)m * 1024 + n] = v;
            }
        }
    }
}

// ---------------------------------------------------------------------------
// Kernel 3: fused flash attention — fp16 single-term QK^T and PV.
// smem: Qh [128][68] @0 (34816B), Kh [128][68] @34816, Vh [64][68] @69632,
// redmax @87040, redsum @88064. Osum reuses Kh region post-loop.
// ---------------------------------------------------------------------------
#define ATTN_SMEM 89088

__global__ __launch_bounds__(256) void attn_kernel(const int* __restrict__ mask)
{
    extern __shared__ char smem[];
    uint32_t (*Qh)[68] = (uint32_t(*)[68])(smem);
    uint32_t (*Kh)[68] = (uint32_t(*)[68])(smem + 34816);
    uint32_t (*Vh)[68] = (uint32_t(*)[68])(smem + 69632);
    float* redmax = (float*)(smem + 87040);
    float* redsum = (float*)(smem + 88064);
    float* Osum   = (float*)(smem + 34816);   // reuse K region post-loop

    const int tid  = threadIdx.x;
    const int warp = tid >> 5, lane = tid & 31;
    const int wm = (warp & 3) * 32;
    const int wn = (warp >> 2);
    const int g  = lane >> 2;
    const int t  = lane & 3;

    const int bh = blockIdx.y;
    const int b  = bh >> 4, h = bh & 15;
    const int m0 = blockIdx.x * 128;

    const float* Qg = g_Q + ((size_t)bh << 17);
    const float* Kg = g_K + ((size_t)bh << 17);
    const float* Vg = g_V + ((size_t)bh << 16);

    const int lrow = tid >> 5;
    const int col4 = (tid & 31) * 4;
    const int pcw  = (tid & 31) * 2;

    // ---- load Q tile once (fp16 packed) ----
    #pragma unroll
    for (int i = 0; i < 16; i++) {
        const int r = lrow + i * 8;
        float4 v = *(const float4*)(Qg + (size_t)(m0 + r) * 128 + col4);
        Qh[r][pcw]     = pack_h2(v.x, v.y);
        Qh[r][pcw + 1] = pack_h2(v.z, v.w);
    }

    float o[2][8][4] = {};
    float mrun[2][2] = {{-INFINITY, -INFINITY}, {-INFINITY, -INFINITY}};
    float lrun[2][2] = {};
    const float scale = 0.08838834764831845f;

    for (int nt = 0; nt < 8; nt++) {
        const int n0 = nt * 128;
        __syncthreads();

        #pragma unroll
        for (int i = 0; i < 16; i++) {
            const int r = lrow + i * 8;
            float4 v = *(const float4*)(Kg + (size_t)(n0 + r) * 128 + col4);
            Kh[r][pcw]     = pack_h2(v.x, v.y);
            Kh[r][pcw + 1] = pack_h2(v.z, v.w);
        }
        #pragma unroll
        for (int i = 0; i < 8; i++) {
            const int r = lrow + i * 8;
            float4 v = *(const float4*)(Vg + (size_t)r * 1024 + n0 + col4);
            Vh[r][pcw]     = pack_h2(v.x, v.y);
            Vh[r][pcw + 1] = pack_h2(v.z, v.w);
        }
        __syncthreads();

        // ---- S = Q K^T (fp16 single) ----
        float s[2][8][4] = {};
        #pragma unroll
        for (int ks = 0; ks < 8; ks++) {
            const int pc = ks * 8;
            uint32_t ah[2][4];
            #pragma unroll
            for (int mt = 0; mt < 2; mt++) {
                #pragma unroll
                for (int q = 0; q < 4; q++) {
                    const int row = wm + mt * 16 + g + (q & 1) * 8;
                    const int col = pc + t + (q >> 1) * 4;
                    ah[mt][q] = Qh[row][col];
                }
            }
            #pragma unroll
            for (int nf = 0; nf < 8; nf++) {
                const int rb = wn * 64 + nf * 8 + g;
                const uint32_t b0 = Kh[rb][pc + t], b1 = Kh[rb][pc + t + 4];
                #pragma unroll
                for (int mt = 0; mt < 2; mt++)
                    mma_fp16(s[mt][nf], ah[mt][0], ah[mt][1], ah[mt][2], ah[mt][3], b0, b1);
            }
        }

        // ---- scale + mask + row max ----
        float pm[2][2];
        #pragma unroll
        for (int mt = 0; mt < 2; mt++) {
            #pragma unroll
            for (int h2 = 0; h2 < 2; h2++) {
                const int rglob = m0 + wm + mt * 16 + g + h2 * 8;
                float mx = -INFINITY;
                #pragma unroll
                for (int nf = 0; nf < 8; nf++) {
                    const int ncol = n0 + wn * 64 + nf * 8 + 2 * t;
                    const int2 mk = *(const int2*)(mask + (((size_t)b << 20) + ((size_t)rglob << 10) + ncol));
                    float v0 = s[mt][nf][h2 * 2 + 0] * scale;
                    float v1 = s[mt][nf][h2 * 2 + 1] * scale;
                    if (mk.x == 0) v0 = -1e9f;
                    if (mk.y == 0) v1 = -1e9f;
                    s[mt][nf][h2 * 2 + 0] = v0;
                    s[mt][nf][h2 * 2 + 1] = v1;
                    mx = fmaxf(mx, fmaxf(v0, v1));
                }
                pm[mt][h2] = mx;
            }
        }
        #pragma unroll
        for (int mt = 0; mt < 2; mt++)
            #pragma unroll
            for (int h2 = 0; h2 < 2; h2++) {
                pm[mt][h2] = fmaxf(pm[mt][h2], __shfl_xor_sync(0xffffffffu, pm[mt][h2], 1));
                pm[mt][h2] = fmaxf(pm[mt][h2], __shfl_xor_sync(0xffffffffu, pm[mt][h2], 2));
            }
        if (t == 0) {
            #pragma unroll
            for (int mt = 0; mt < 2; mt++)
                #pragma unroll
                for (int h2 = 0; h2 < 2; h2++)
                    redmax[wn * 128 + wm + mt * 16 + g + h2 * 8] = pm[mt][h2];
        }
        __syncthreads();

        // ---- running stats, exponentiate, rescale O ----
        float alpha[2][2], psum[2][2];
        #pragma unroll
        for (int mt = 0; mt < 2; mt++) {
            #pragma unroll
            for (int h2 = 0; h2 < 2; h2++) {
                const int rl = wm + mt * 16 + g + h2 * 8;
                const float mtile = fmaxf(redmax[rl], redmax[128 + rl]);
                const float mnew  = fmaxf(mrun[mt][h2], mtile);
                alpha[mt][h2] = __expf(mrun[mt][h2] - mnew);
                mrun[mt][h2]  = mnew;
                float ps = 0.0f;
                #pragma unroll
                for (int nf = 0; nf < 8; nf++) {
                    float p0 = __expf(s[mt][nf][h2 * 2 + 0] - mnew);
                    float p1 = __expf(s[mt][nf][h2 * 2 + 1] - mnew);
                    s[mt][nf][h2 * 2 + 0] = p0;
                    s[mt][nf][h2 * 2 + 1] = p1;
                    ps += p0 + p1;
                }
                psum[mt][h2] = ps;
            }
        }
        #pragma unroll
        for (int mt = 0; mt < 2; mt++)
            #pragma unroll
            for (int nf = 0; nf < 8; nf++)
                #pragma unroll
                for (int e = 0; e < 4; e++)
                    o[mt][nf][e] *= alpha[mt][e >> 1];
        #pragma unroll
        for (int mt = 0; mt < 2; mt++)
            #pragma unroll
            for (int h2 = 0; h2 < 2; h2++) {
                psum[mt][h2] += __shfl_xor_sync(0xffffffffu, psum[mt][h2], 1);
                psum[mt][h2] += __shfl_xor_sync(0xffffffffu, psum[mt][h2], 2);
            }
        if (t == 0) {
            #pragma unroll
            for (int mt = 0; mt < 2; mt++)
                #pragma unroll
                for (int h2 = 0; h2 < 2; h2++)
                    redsum[wn * 128 + wm + mt * 16 + g + h2 * 8] = psum[mt][h2];
        }
        __syncthreads();
        #pragma unroll
        for (int mt = 0; mt < 2; mt++)
            #pragma unroll
            for (int h2 = 0; h2 < 2; h2++) {
                const int rl = wm + mt * 16 + g + h2 * 8;
                lrun[mt][h2] = lrun[mt][h2] * alpha[mt][h2] + redsum[rl] + redsum[128 + rl];
            }

        // ---- O += P V (fp16 single) ----
        #pragma unroll
        for (int ks2 = 0; ks2 < 4; ks2++) {
            uint32_t ah[2][4];
            #pragma unroll
            for (int mt = 0; mt < 2; mt++) {
                ah[mt][0] = pack_h2(s[mt][2 * ks2][0],     s[mt][2 * ks2][1]);
                ah[mt][1] = pack_h2(s[mt][2 * ks2][2],     s[mt][2 * ks2][3]);
                ah[mt][2] = pack_h2(s[mt][2 * ks2 + 1][0], s[mt][2 * ks2 + 1][1]);
                ah[mt][3] = pack_h2(s[mt][2 * ks2 + 1][2], s[mt][2 * ks2 + 1][3]);
            }
            const int vcol = wn * 32 + ks2 * 8 + t;
            #pragma unroll
            for (int nf = 0; nf < 8; nf++) {
                const int rv = nf * 8 + g;
                const uint32_t b0 = Vh[rv][vcol], b1 = Vh[rv][vcol + 4];
                #pragma unroll
                for (int mt = 0; mt < 2; mt++)
                    mma_fp16(o[mt][nf], ah[mt][0], ah[mt][1], ah[mt][2], ah[mt][3], b0, b1);
            }
        }
    }

    // ---- epilogue ----
    __syncthreads();
    if (wn == 1) {
        #pragma unroll
        for (int mt = 0; mt < 2; mt++)
            #pragma unroll
            for (int h2 = 0; h2 < 2; h2++) {
                const int rl = wm + mt * 16 + g + h2 * 8;
                #pragma unroll
                for (int nf = 0; nf < 8; nf++) {
                    float2 v;
                    v.x = o[mt][nf][h2 * 2 + 0];
                    v.y = o[mt][nf][h2 * 2 + 1];
                    *(float2*)&Osum[rl * 66 + nf * 8 + 2 * t] = v;
                }
            }
    }
    __syncthreads();
    if (wn == 0) {
        #pragma unroll
        for (int mt = 0; mt < 2; mt++)
            #pragma unroll
            for (int h2 = 0; h2 < 2; h2++) {
                const int rl = wm + mt * 16 + g + h2 * 8;
                const float inv = 1.0f / lrun[mt][h2];
                #pragma unroll
                for (int nf = 0; nf < 8; nf++) {
                    const int c = nf * 8 + 2 * t;
                    float2 p = *(float2*)&Osum[rl * 66 + c];
                    float2 v;
                    v.x = (o[mt][nf][h2 * 2 + 0] + p.x) * inv;
                    v.y = (o[mt][nf][h2 * 2 + 1] + p.y) * inv;
                    *(float2*)&g_X[(size_t)(b * 1024 + m0 + rl) * 1024 + h * 64 + c] = v;
                }
            }
    }
}

// ---------------------------------------------------------------------------
// Kernel 4: out = gate * (X @ Winfo^T + binfo)  (fp16 single)
// ---------------------------------------------------------------------------
__global__ __launch_bounds__(256, 2) void info_kernel(
    const float* __restrict__ Winfo, const float* __restrict__ binfo,
    float* __restrict__ out)
{
    __shared__ uint32_t Ah[128][20], Bh[128][20];
    const int m0 = blockIdx.y * 128;
    const int n0 = blockIdx.x * 128;
    float acc[2][8][4] = {};
    gemm_fp16_body(g_X, 1024, nullptr, 1 << 30, Winfo, 1024, 1024, m0, n0, acc,
                   (SmT)Ah, (SmT)Bh);

    const int lane = threadIdx.x & 31, warp = threadIdx.x >> 5;
    const int wm = (warp & 3) * 32, wn = (warp >> 2) * 64;
    const int g = lane >> 2, t = lane & 3;

    #pragma unroll
    for (int nf = 0; nf < 8; nf++) {
        const int n = n0 + wn + nf * 8 + 2 * t;
        const float bx = binfo[n], by = binfo[n + 1];
        #pragma unroll
        for (int mt = 0; mt < 2; mt++) {
            #pragma unroll
            for (int h2 = 0; h2 < 2; h2++) {
                const int m = m0 + wm + mt * 16 + g + h2 * 8;
                const float2 gg = *(const float2*)&g_G[(size_t)m * 1024 + n];
                float2 v;
                v.x = gg.x * (acc[mt][nf][h2 * 2 + 0] + bx);
                v.y = gg.y * (acc[mt][nf][h2 * 2 + 1] + by);
                *(float2*)&out[(size_t)m * 1024 + n] = v;
            }
        }
    }
}

// ---------------------------------------------------------------------------
extern "C" void kernel_launch(void* const* d_in, const int* in_sizes, int n_in,
                              void* d_out, int out_size)
{
    (void)in_sizes; (void)n_in; (void)out_size;
    const float* query_g = (const float*)d_in[0];
    const float* key_g   = (const float*)d_in[1];
    const float* query_a = (const float*)d_in[2];
    const float* key_a   = (const float*)d_in[3];
    const float* value_a = (const float*)d_in[4];
    const int*   mask    = (const int*)  d_in[5];
    const float* Wqg = (const float*)d_in[6];  const float* bqg = (const float*)d_in[7];
    const float* Wkg = (const float*)d_in[8];  const float* bkg = (const float*)d_in[9];
    const float* Wqa = (const float*)d_in[10]; const float* bqa = (const float*)d_in[11];
    const float* Wka = (const float*)d_in[12]; const float* bka = (const float*)d_in[13];
    const float* Wva = (const float*)d_in[14]; const float* bva = (const float*)d_in[15];
    const float* Wgate = (const float*)d_in[16]; const float* bgate = (const float*)d_in[17];
    const float* Winfo = (const float*)d_in[18]; const float* binfo = (const float*)d_in[19];

    static int smem_set = 0;
    if (!smem_set) {
        cudaFuncSetAttribute(attn_kernel, cudaFuncAttributeMaxDynamicSharedMemorySize, ATTN_SMEM);
        smem_set = 1;
    }

    dim3 blk(256);
    proj_kernel<<<dim3(8, 32, 5), blk>>>(query_a, query_g, key_a, key_g, value_a,
                                         Wqa, Wqg, Wka, Wkg, Wva,
                                         bqa, bqg, bka, bkg, bva);
    gate_kernel<<<dim3(8, 32, 1), blk>>>(query_a, query_g, Wgate, bgate);
    attn_kernel<<<dim3(8, 64), blk, ATTN_SMEM>>>(mask);
    info_kernel<<<dim3(8, 32, 1), blk>>>(Winfo, binfo, (float*)d_out);
}

// round 11
// speedup vs baseline: 2.2285x; 1.0346x over previous
#include <cuda_runtime.h>
#include <cuda_fp16.h>
#include <math.h>
#include <stdint.h>

// Problem constants
#define B_  4
#define S_  1024
#define BH  64     // B*H

// ---------------------------------------------------------------------------
// Scratch. All "h" arrays hold packed fp16 pairs: word w = h(x[2w]) | h(x[2w+1])<<16
// ---------------------------------------------------------------------------
static __device__ uint32_t g_INh[(size_t)5 * 2097152];   // [qa,qg,ka,kg,va] inputs
static __device__ uint32_t g_Wh[(size_t)4194304];        // Wqa..Wva,Wgate,Winfo
static __device__ uint32_t g_Qh[(size_t)BH * S_ * 64];   // [bh,s,64w] (qa|qg)
static __device__ uint32_t g_Kh[(size_t)BH * S_ * 64];
static __device__ uint32_t g_Vh[(size_t)BH * 64 * 512];  // transposed [bh,j,s] fp16
static __device__ uint32_t g_Xh[(size_t)4096 * 512];     // attn out packed
static __device__ float    g_G [(size_t)4096 * 1024];    // gate fp32

#define OW_QA 0u
#define OW_QG 524288u
#define OW_KA 1048576u
#define OW_KG 1572864u
#define OW_VA 2097152u
#define OW_GATE 2621440u
#define OW_INFO 3670016u

// ---------------------------------------------------------------------------
__device__ __forceinline__ uint32_t pack_h2(float x, float y) {
    __half2 h = __floats2half2_rn(x, y);
    return *(uint32_t*)&h;
}

__device__ __forceinline__ void mma_fp16(float* c,
    uint32_t a0, uint32_t a1, uint32_t a2, uint32_t a3,
    uint32_t b0, uint32_t b1)
{
    asm volatile(
        "mma.sync.aligned.m16n8k16.row.col.f32.f16.f16.f32 "
        "{%0,%1,%2,%3},{%4,%5,%6,%7},{%8,%9},{%0,%1,%2,%3};"
        : "+f"(c[0]), "+f"(c[1]), "+f"(c[2]), "+f"(c[3])
        : "r"(a0), "r"(a1), "r"(a2), "r"(a3), "r"(b0), "r"(b1));
}

__device__ __forceinline__ uint32_t smem_u32(const void* p) {
    uint32_t a;
    asm("{ .reg .u64 t; cvta.to.shared.u64 t, %1; cvt.u32.u64 %0, t; }" : "=r"(a) : "l"(p));
    return a;
}

__device__ __forceinline__ void cp16(uint32_t dst, const void* src) {
    asm volatile("cp.async.ca.shared.global [%0], [%1], 16;" :: "r"(dst), "l"(src));
}
#define CP_COMMIT() asm volatile("cp.async.commit_group;" ::: "memory")
#define CP_WAIT1()  asm volatile("cp.async.wait_group 1;" ::: "memory")

// ---------------------------------------------------------------------------
// Conversion kernels (fp32 -> packed fp16), once per launch.
// ---------------------------------------------------------------------------
__global__ __launch_bounds__(256) void conv_in_kernel(
    const float* __restrict__ q_g, const float* __restrict__ k_g,
    const float* __restrict__ q_a, const float* __restrict__ k_a,
    const float* __restrict__ v_a)
{
    const int z = blockIdx.y;
    const float* src = (z == 0) ? q_a : (z == 1) ? q_g : (z == 2) ? k_a
                     : (z == 3) ? k_g : v_a;
    const size_t i = (size_t)blockIdx.x * 256 + threadIdx.x;
    float4 v = ((const float4*)src)[i];
    const size_t w = (size_t)z * 2097152 + i * 2;
    g_INh[w]     = pack_h2(v.x, v.y);
    g_INh[w + 1] = pack_h2(v.z, v.w);
}

__global__ __launch_bounds__(256) void conv_w_kernel(
    const float* __restrict__ Wqa, const float* __restrict__ Wqg,
    const float* __restrict__ Wka, const float* __restrict__ Wkg,
    const float* __restrict__ Wva, const float* __restrict__ Wgate,
    const float* __restrict__ Winfo)
{
    const int z = blockIdx.y;
    const float* src; size_t offw; size_t nf4;
    switch (z) {
        case 0: src = Wqa;   offw = OW_QA;   nf4 = 262144; break;
        case 1: src = Wqg;   offw = OW_QG;   nf4 = 262144; break;
        case 2: src = Wka;   offw = OW_KA;   nf4 = 262144; break;
        case 3: src = Wkg;   offw = OW_KG;   nf4 = 262144; break;
        case 4: src = Wva;   offw = OW_VA;   nf4 = 262144; break;
        case 5: src = Wgate; offw = OW_GATE; nf4 = 524288; break;
        default: src = Winfo; offw = OW_INFO; nf4 = 262144; break;
    }
    for (size_t i = (size_t)blockIdx.x * 256 + threadIdx.x; i < nf4; i += 262144) {
        float4 v = ((const float4*)src)[i];
        const size_t w = offw + i * 2;
        g_Wh[w]     = pack_h2(v.x, v.y);
        g_Wh[w + 1] = pack_h2(v.z, v.w);
    }
}

// ---------------------------------------------------------------------------
// fp16 GEMM on pre-packed word arrays via cp.async 3-stage pipeline.
// C tile 128x128, 8 warps (4m x 2n). K-tile = 16 words (32 fp16).
// Stage: A [128][20]w @ +0, B [128][20]w @ +2560w. Stage stride 5120 words.
// GSMEM = 3 * 20480 B.
// ---------------------------------------------------------------------------
#define GSMEM 61440
typedef uint32_t (*SmT)[20];

__device__ __forceinline__ void issue_stage(
    uint32_t smu, int stage,
    const uint32_t* __restrict__ Ahp, int ldaw,
    const uint32_t* __restrict__ A2h, int kspw,
    const uint32_t* __restrict__ Bhp, int ldbw,
    int m0, int n0, int kw0)
{
    const int tid = threadIdx.x;
    const uint32_t sbase = smu + (uint32_t)stage * 20480u;
    #pragma unroll
    for (int c = 0; c < 2; c++) {
        const int cid = tid + c * 256;
        const int row = cid >> 2, cw = (cid & 3) << 2;
        const int gw = kw0 + cw;
        const uint32_t* srcA;
        if (gw >= kspw) srcA = A2h + (size_t)(m0 + row) * 512 + (gw - kspw);
        else            srcA = Ahp + (size_t)(m0 + row) * ldaw + gw;
        const uint32_t dstA = sbase + (uint32_t)((row * 20 + cw) * 4);
        cp16(dstA, srcA);
        cp16(dstA + 10240u, Bhp + (size_t)(n0 + row) * ldbw + gw);
    }
}

__device__ __forceinline__ void mma_stage(
    uint32_t* stg, int wm, int wn, int g, int t, float acc[2][8][4])
{
    SmT Ah = (SmT)stg;
    SmT Bh = (SmT)(stg + 2560);
    #pragma unroll
    for (int kk = 0; kk < 2; kk++) {
        const int pc = kk * 8;
        uint32_t ah[2][4];
        #pragma unroll
        for (int mt = 0; mt < 2; mt++) {
            #pragma unroll
            for (int q = 0; q < 4; q++) {
                const int row = wm + mt * 16 + g + (q & 1) * 8;
                const int col = pc + t + (q >> 1) * 4;
                ah[mt][q] = Ah[row][col];
            }
        }
        #pragma unroll
        for (int nf = 0; nf < 8; nf++) {
            const int rb = wn + nf * 8 + g;
            const uint32_t b0 = Bh[rb][pc + t], b1 = Bh[rb][pc + t + 4];
            #pragma unroll
            for (int mt = 0; mt < 2; mt++)
                mma_fp16(acc[mt][nf], ah[mt][0], ah[mt][1], ah[mt][2], ah[mt][3], b0, b1);
        }
    }
}

__device__ __forceinline__ void gemm_fp16_ca(
    uint32_t* sm,
    const uint32_t* __restrict__ Ahp, int ldaw,
    const uint32_t* __restrict__ A2h, int kspw,
    const uint32_t* __restrict__ Bhp, int ldbw,
    int Kw, int m0, int n0, float acc[2][8][4])
{
    const uint32_t smu = smem_u32(sm);
    const int warp = threadIdx.x >> 5, lane = threadIdx.x & 31;
    const int wm = (warp & 3) * 32, wn = (warp >> 2) * 64;
    const int g = lane >> 2, t = lane & 3;
    const int nK = Kw >> 4;

    issue_stage(smu, 0, Ahp, ldaw, A2h, kspw, Bhp, ldbw, m0, n0, 0);
    CP_COMMIT();
    issue_stage(smu, 1, Ahp, ldaw, A2h, kspw, Bhp, ldbw, m0, n0, 16);
    CP_COMMIT();

    for (int kt = 0; kt < nK; kt++) {
        CP_WAIT1();
        __syncthreads();
        if (kt + 2 < nK) {
            issue_stage(smu, (kt + 2) % 3, Ahp, ldaw, A2h, kspw, Bhp, ldbw,
                        m0, n0, (kt + 2) * 16);
            CP_COMMIT();
        }
        mma_stage(sm + (kt % 3) * 5120, wm, wn, g, t, acc);
    }
}

// ---------------------------------------------------------------------------
// Kernel 1: all 5 head projections, grid.z selects which. fp16 outputs.
// ---------------------------------------------------------------------------
__global__ __launch_bounds__(256, 2) void proj_kernel(
    const float* __restrict__ bqa, const float* __restrict__ bqg,
    const float* __restrict__ bka, const float* __restrict__ bkg,
    const float* __restrict__ bva)
{
    extern __shared__ uint32_t sm[];
    const int p = blockIdx.z;
    const uint32_t* Ahp = g_INh + (size_t)p * 2097152;
    const uint32_t woff = (p == 0) ? OW_QA : (p == 1) ? OW_QG : (p == 2) ? OW_KA
                        : (p == 3) ? OW_KG : OW_VA;
    const float* bias = (p == 0) ? bqa : (p == 1) ? bqg : (p == 2) ? bka
                      : (p == 3) ? bkg : bva;

    const int m0 = blockIdx.y * 128;
    const int n0 = blockIdx.x * 128;
    float acc[2][8][4] = {};
    gemm_fp16_ca(sm, Ahp, 512, nullptr, 1 << 30, g_Wh + woff, 512, 512, m0, n0, acc);

    const int lane = threadIdx.x & 31, warp = threadIdx.x >> 5;
    const int wm = (warp & 3) * 32, wn = (warp >> 2) * 64;
    const int g = lane >> 2, t = lane & 3;

    #pragma unroll
    for (int nf = 0; nf < 8; nf++) {
        const int n  = n0 + wn + nf * 8 + 2 * t;
        const int h  = n >> 6, jj = n & 63;
        const float bx = bias[n], by = bias[n + 1];
        #pragma unroll
        for (int mt = 0; mt < 2; mt++) {
            #pragma unroll
            for (int h2 = 0; h2 < 2; h2++) {
                const int m = m0 + wm + mt * 16 + g + h2 * 8;
                const int b = m >> 10, s = m & 1023;
                const size_t bhh = (size_t)(b * 16 + h);
                const float vx = acc[mt][nf][h2 * 2 + 0] + bx;
                const float vy = acc[mt][nf][h2 * 2 + 1] + by;
                if (p == 4) {
                    __half* Vp = (__half*)g_Vh;
                    Vp[(bhh * 64 + jj)     * 1024 + s] = __float2half_rn(vx);
                    Vp[(bhh * 64 + jj + 1) * 1024 + s] = __float2half_rn(vy);
                } else {
                    const size_t widx = (bhh * 1024 + s) * 64 + ((p & 1) ? 32 : 0) + (jj >> 1);
                    if (p < 2) g_Qh[widx] = pack_h2(vx, vy);
                    else       g_Kh[widx] = pack_h2(vx, vy);
                }
            }
        }
    }
}

// ---------------------------------------------------------------------------
// Kernel 2: gate = sigmoid(concat(qa,qg) @ Wgate^T + bgate), Kw=1024 words
// ---------------------------------------------------------------------------
__global__ __launch_bounds__(256, 2) void gate_kernel(const float* __restrict__ bgate)
{
    extern __shared__ uint32_t sm[];
    const int m0 = blockIdx.y * 128;
    const int n0 = blockIdx.x * 128;
    float acc[2][8][4] = {};
    gemm_fp16_ca(sm, g_INh, 512, g_INh + 2097152, 512,
                 g_Wh + OW_GATE, 1024, 1024, m0, n0, acc);

    const int lane = threadIdx.x & 31, warp = threadIdx.x >> 5;
    const int wm = (warp & 3) * 32, wn = (warp >> 2) * 64;
    const int g = lane >> 2, t = lane & 3;

    #pragma unroll
    for (int nf = 0; nf < 8; nf++) {
        const int n = n0 + wn + nf * 8 + 2 * t;
        const float bx = bgate[n], by = bgate[n + 1];
        #pragma unroll
        for (int mt = 0; mt < 2; mt++) {
            #pragma unroll
            for (int h2 = 0; h2 < 2; h2++) {
                const int m = m0 + wm + mt * 16 + g + h2 * 8;
                float2 v;
                v.x = 1.0f / (1.0f + __expf(-(acc[mt][nf][h2 * 2 + 0] + bx)));
                v.y = 1.0f / (1.0f + __expf(-(acc[mt][nf][h2 * 2 + 1] + by)));
                *(float2*)&g_G[(size_t)m * 1024 + n] = v;
            }
        }
    }
}

// ---------------------------------------------------------------------------
// Kernel 3: fused flash attention, fp16 everywhere, pre-packed gmem loads.
// smem: Qh [128][68] @0, Kh [128][68] @34816, Vh [64][68] @69632,
// redmax @87040, redsum @88064. Osum reuses Kh post-loop.
// ---------------------------------------------------------------------------
#define ATTN_SMEM 89088

__global__ __launch_bounds__(256) void attn_kernel(const int* __restrict__ mask)
{
    extern __shared__ char smem[];
    uint32_t (*Qh)[68] = (uint32_t(*)[68])(smem);
    uint32_t (*Kh)[68] = (uint32_t(*)[68])(smem + 34816);
    uint32_t (*Vh)[68] = (uint32_t(*)[68])(smem + 69632);
    float* redmax = (float*)(smem + 87040);
    float* redsum = (float*)(smem + 88064);
    float* Osum   = (float*)(smem + 34816);

    const int tid  = threadIdx.x;
    const int warp = tid >> 5, lane = tid & 31;
    const int wm = (warp & 3) * 32;
    const int wn = (warp >> 2);
    const int g  = lane >> 2;
    const int t  = lane & 3;

    const int bh = blockIdx.y;
    const int b  = bh >> 4, h = bh & 15;
    const int m0 = blockIdx.x * 128;

    const uint32_t* Qhg = g_Qh + ((size_t)bh << 16);
    const uint32_t* Khg = g_Kh + ((size_t)bh << 16);
    const uint32_t* Vhg = g_Vh + (size_t)bh * 32768;

    const int lrow = tid >> 5;
    const int pcw  = (tid & 31) * 2;

    #pragma unroll
    for (int i = 0; i < 16; i++) {
        const int r = lrow + i * 8;
        *(uint2*)&Qh[r][pcw] = *(const uint2*)(Qhg + (size_t)(m0 + r) * 64 + pcw);
    }

    float o[2][8][4] = {};
    float mrun[2][2] = {{-INFINITY, -INFINITY}, {-INFINITY, -INFINITY}};
    float lrun[2][2] = {};
    const float scale = 0.08838834764831845f;

    for (int nt = 0; nt < 8; nt++) {
        const int n0 = nt * 128;
        __syncthreads();

        #pragma unroll
        for (int i = 0; i < 16; i++) {
            const int r = lrow + i * 8;
            *(uint2*)&Kh[r][pcw] = *(const uint2*)(Khg + (size_t)(n0 + r) * 64 + pcw);
        }
        #pragma unroll
        for (int i = 0; i < 8; i++) {
            const int r = lrow + i * 8;
            *(uint2*)&Vh[r][pcw] = *(const uint2*)(Vhg + (size_t)r * 512 + (n0 >> 1) + pcw);
        }
        __syncthreads();

        // ---- S = Q K^T ----
        float s[2][8][4] = {};
        #pragma unroll
        for (int ks = 0; ks < 8; ks++) {
            const int pc = ks * 8;
            uint32_t ah[2][4];
            #pragma unroll
            for (int mt = 0; mt < 2; mt++) {
                #pragma unroll
                for (int q = 0; q < 4; q++) {
                    const int row = wm + mt * 16 + g + (q & 1) * 8;
                    const int col = pc + t + (q >> 1) * 4;
                    ah[mt][q] = Qh[row][col];
                }
            }
            #pragma unroll
            for (int nf = 0; nf < 8; nf++) {
                const int rb = wn * 64 + nf * 8 + g;
                const uint32_t b0 = Kh[rb][pc + t], b1 = Kh[rb][pc + t + 4];
                #pragma unroll
                for (int mt = 0; mt < 2; mt++)
                    mma_fp16(s[mt][nf], ah[mt][0], ah[mt][1], ah[mt][2], ah[mt][3], b0, b1);
            }
        }

        // ---- scale + mask + row max ----
        float pm[2][2];
        #pragma unroll
        for (int mt = 0; mt < 2; mt++) {
            #pragma unroll
            for (int h2 = 0; h2 < 2; h2++) {
                const int rglob = m0 + wm + mt * 16 + g + h2 * 8;
                float mx = -INFINITY;
                #pragma unroll
                for (int nf = 0; nf < 8; nf++) {
                    const int ncol = n0 + wn * 64 + nf * 8 + 2 * t;
                    const int2 mk = *(const int2*)(mask + (((size_t)b << 20) + ((size_t)rglob << 10) + ncol));
                    float v0 = s[mt][nf][h2 * 2 + 0] * scale;
                    float v1 = s[mt][nf][h2 * 2 + 1] * scale;
                    if (mk.x == 0) v0 = -1e9f;
                    if (mk.y == 0) v1 = -1e9f;
                    s[mt][nf][h2 * 2 + 0] = v0;
                    s[mt][nf][h2 * 2 + 1] = v1;
                    mx = fmaxf(mx, fmaxf(v0, v1));
                }
                pm[mt][h2] = mx;
            }
        }
        #pragma unroll
        for (int mt = 0; mt < 2; mt++)
            #pragma unroll
            for (int h2 = 0; h2 < 2; h2++) {
                pm[mt][h2] = fmaxf(pm[mt][h2], __shfl_xor_sync(0xffffffffu, pm[mt][h2], 1));
                pm[mt][h2] = fmaxf(pm[mt][h2], __shfl_xor_sync(0xffffffffu, pm[mt][h2], 2));
            }
        if (t == 0) {
            #pragma unroll
            for (int mt = 0; mt < 2; mt++)
                #pragma unroll
                for (int h2 = 0; h2 < 2; h2++)
                    redmax[wn * 128 + wm + mt * 16 + g + h2 * 8] = pm[mt][h2];
        }
        __syncthreads();

        // ---- running stats, exponentiate, rescale O ----
        float alpha[2][2], psum[2][2];
        #pragma unroll
        for (int mt = 0; mt < 2; mt++) {
            #pragma unroll
            for (int h2 = 0; h2 < 2; h2++) {
                const int rl = wm + mt * 16 + g + h2 * 8;
                const float mtile = fmaxf(redmax[rl], redmax[128 + rl]);
                const float mnew  = fmaxf(mrun[mt][h2], mtile);
                alpha[mt][h2] = __expf(mrun[mt][h2] - mnew);
                mrun[mt][h2]  = mnew;
                float ps = 0.0f;
                #pragma unroll
                for (int nf = 0; nf < 8; nf++) {
                    float p0 = __expf(s[mt][nf][h2 * 2 + 0] - mnew);
                    float p1 = __expf(s[mt][nf][h2 * 2 + 1] - mnew);
                    s[mt][nf][h2 * 2 + 0] = p0;
                    s[mt][nf][h2 * 2 + 1] = p1;
                    ps += p0 + p1;
                }
                psum[mt][h2] = ps;
            }
        }
        #pragma unroll
        for (int mt = 0; mt < 2; mt++)
            #pragma unroll
            for (int nf = 0; nf < 8; nf++)
                #pragma unroll
                for (int e = 0; e < 4; e++)
                    o[mt][nf][e] *= alpha[mt][e >> 1];
        #pragma unroll
        for (int mt = 0; mt < 2; mt++)
            #pragma unroll
            for (int h2 = 0; h2 < 2; h2++) {
                psum[mt][h2] += __shfl_xor_sync(0xffffffffu, psum[mt][h2], 1);
                psum[mt][h2] += __shfl_xor_sync(0xffffffffu, psum[mt][h2], 2);
            }
        if (t == 0) {
            #pragma unroll
            for (int mt = 0; mt < 2; mt++)
                #pragma unroll
                for (int h2 = 0; h2 < 2; h2++)
                    redsum[wn * 128 + wm + mt * 16 + g + h2 * 8] = psum[mt][h2];
        }
        __syncthreads();
        #pragma unroll
        for (int mt = 0; mt < 2; mt++)
            #pragma unroll
            for (int h2 = 0; h2 < 2; h2++) {
                const int rl = wm + mt * 16 + g + h2 * 8;
                lrun[mt][h2] = lrun[mt][h2] * alpha[mt][h2] + redsum[rl] + redsum[128 + rl];
            }

        // ---- O += P V ----
        #pragma unroll
        for (int ks2 = 0; ks2 < 4; ks2++) {
            uint32_t ah[2][4];
            #pragma unroll
            for (int mt = 0; mt < 2; mt++) {
                ah[mt][0] = pack_h2(s[mt][2 * ks2][0],     s[mt][2 * ks2][1]);
                ah[mt][1] = pack_h2(s[mt][2 * ks2][2],     s[mt][2 * ks2][3]);
                ah[mt][2] = pack_h2(s[mt][2 * ks2 + 1][0], s[mt][2 * ks2 + 1][1]);
                ah[mt][3] = pack_h2(s[mt][2 * ks2 + 1][2], s[mt][2 * ks2 + 1][3]);
            }
            const int vcol = wn * 32 + ks2 * 8 + t;
            #pragma unroll
            for (int nf = 0; nf < 8; nf++) {
                const int rv = nf * 8 + g;
                const uint32_t b0 = Vh[rv][vcol], b1 = Vh[rv][vcol + 4];
                #pragma unroll
                for (int mt = 0; mt < 2; mt++)
                    mma_fp16(o[mt][nf], ah[mt][0], ah[mt][1], ah[mt][2], ah[mt][3], b0, b1);
            }
        }
    }

    // ---- epilogue: combine partials, normalize, write packed X ----
    __syncthreads();
    if (wn == 1) {
        #pragma unroll
        for (int mt = 0; mt < 2; mt++)
            #pragma unroll
            for (int h2 = 0; h2 < 2; h2++) {
                const int rl = wm + mt * 16 + g + h2 * 8;
                #pragma unroll
                for (int nf = 0; nf < 8; nf++) {
                    float2 v;
                    v.x = o[mt][nf][h2 * 2 + 0];
                    v.y = o[mt][nf][h2 * 2 + 1];
                    *(float2*)&Osum[rl * 66 + nf * 8 + 2 * t] = v;
                }
            }
    }
    __syncthreads();
    if (wn == 0) {
        #pragma unroll
        for (int mt = 0; mt < 2; mt++)
            #pragma unroll
            for (int h2 = 0; h2 < 2; h2++) {
                const int rl = wm + mt * 16 + g + h2 * 8;
                const float inv = 1.0f / lrun[mt][h2];
                #pragma unroll
                for (int nf = 0; nf < 8; nf++) {
                    const int c = nf * 8 + 2 * t;
                    float2 p = *(float2*)&Osum[rl * 66 + c];
                    const float vx = (o[mt][nf][h2 * 2 + 0] + p.x) * inv;
                    const float vy = (o[mt][nf][h2 * 2 + 1] + p.y) * inv;
                    g_Xh[(size_t)(b * 1024 + m0 + rl) * 512 + ((h * 64 + c) >> 1)] = pack_h2(vx, vy);
                }
            }
    }
}

// ---------------------------------------------------------------------------
// Kernel 4: out = gate * (X @ Winfo^T + binfo)
// ---------------------------------------------------------------------------
__global__ __launch_bounds__(256, 2) void info_kernel(
    const float* __restrict__ binfo, float* __restrict__ out)
{
    extern __shared__ uint32_t sm[];
    const int m0 = blockIdx.y * 128;
    const int n0 = blockIdx.x * 128;
    float acc[2][8][4] = {};
    gemm_fp16_ca(sm, g_Xh, 512, nullptr, 1 << 30, g_Wh + OW_INFO, 512, 512, m0, n0, acc);

    const int lane = threadIdx.x & 31, warp = threadIdx.x >> 5;
    const int wm = (warp & 3) * 32, wn = (warp >> 2) * 64;
    const int g = lane >> 2, t = lane & 3;

    #pragma unroll
    for (int nf = 0; nf < 8; nf++) {
        const int n = n0 + wn + nf * 8 + 2 * t;
        const float bx = binfo[n], by = binfo[n + 1];
        #pragma unroll
        for (int mt = 0; mt < 2; mt++) {
            #pragma unroll
            for (int h2 = 0; h2 < 2; h2++) {
                const int m = m0 + wm + mt * 16 + g + h2 * 8;
                const float2 gg = *(const float2*)&g_G[(size_t)m * 1024 + n];
                float2 v;
                v.x = gg.x * (acc[mt][nf][h2 * 2 + 0] + bx);
                v.y = gg.y * (acc[mt][nf][h2 * 2 + 1] + by);
                *(float2*)&out[(size_t)m * 1024 + n] = v;
            }
        }
    }
}

// ---------------------------------------------------------------------------
extern "C" void kernel_launch(void* const* d_in, const int* in_sizes, int n_in,
                              void* d_out, int out_size)
{
    (void)in_sizes; (void)n_in; (void)out_size;
    const float* query_g = (const float*)d_in[0];
    const float* key_g   = (const float*)d_in[1];
    const float* query_a = (const float*)d_in[2];
    const float* key_a   = (const float*)d_in[3];
    const float* value_a = (const float*)d_in[4];
    const int*   mask    = (const int*)  d_in[5];
    const float* Wqg = (const float*)d_in[6];  const float* bqg = (const float*)d_in[7];
    const float* Wkg = (const float*)d_in[8];  const float* bkg = (const float*)d_in[9];
    const float* Wqa = (const float*)d_in[10]; const float* bqa = (const float*)d_in[11];
    const float* Wka = (const float*)d_in[12]; const float* bka = (const float*)d_in[13];
    const float* Wva = (const float*)d_in[14]; const float* bva = (const float*)d_in[15];
    const float* Wgate = (const float*)d_in[16]; const float* bgate = (const float*)d_in[17];
    const float* Winfo = (const float*)d_in[18]; const float* binfo = (const float*)d_in[19];

    static int attr_set = 0;
    if (!attr_set) {
        cudaFuncSetAttribute(attn_kernel, cudaFuncAttributeMaxDynamicSharedMemorySize, ATTN_SMEM);
        cudaFuncSetAttribute(proj_kernel, cudaFuncAttributeMaxDynamicSharedMemorySize, GSMEM);
        cudaFuncSetAttribute(gate_kernel, cudaFuncAttributeMaxDynamicSharedMemorySize, GSMEM);
        cudaFuncSetAttribute(info_kernel, cudaFuncAttributeMaxDynamicSharedMemorySize, GSMEM);
        attr_set = 1;
    }

    dim3 blk(256);
    conv_in_kernel<<<dim3(4096, 5), blk>>>(query_g, key_g, query_a, key_a, value_a);
    conv_w_kernel<<<dim3(1024, 7), blk>>>(Wqa, Wqg, Wka, Wkg, Wva, Wgate, Winfo);
    proj_kernel<<<dim3(8, 32, 5), blk, GSMEM>>>(bqa, bqg, bka, bkg, bva);
    gate_kernel<<<dim3(8, 32, 1), blk, GSMEM>>>(bgate);
    attn_kernel<<<dim3(8, 64), blk, ATTN_SMEM>>>(mask);
    info_kernel<<<dim3(8, 32, 1), blk, GSMEM>>>(binfo, (float*)d_out);
}

// round 12
// speedup vs baseline: 2.5250x; 1.1331x over previous
#include <cuda_runtime.h>
#include <cuda_fp16.h>
#include <math.h>
#include <stdint.h>

// Problem constants
#define B_  4
#define S_  1024
#define BH  64     // B*H

// ---------------------------------------------------------------------------
// Scratch. All "h" arrays hold packed fp16 pairs: word w = h(x[2w]) | h(x[2w+1])<<16
// ---------------------------------------------------------------------------
static __device__ uint32_t g_INh[(size_t)5 * 2097152];   // [qa,qg,ka,kg,va] inputs
static __device__ uint32_t g_Wh[(size_t)4194304];        // Wqa..Wva,Wgate,Winfo
static __device__ uint32_t g_Qh[(size_t)BH * S_ * 64];   // [bh,s,64w] (qa|qg)
static __device__ uint32_t g_Kh[(size_t)BH * S_ * 64];
static __device__ uint32_t g_Vh[(size_t)BH * 64 * 512];  // transposed [bh,j,s] fp16
static __device__ uint32_t g_Xh[(size_t)4096 * 512];     // attn out packed
static __device__ float    g_G [(size_t)4096 * 1024];    // gate fp32

#define OW_QA 0u
#define OW_QG 524288u
#define OW_KA 1048576u
#define OW_KG 1572864u
#define OW_VA 2097152u
#define OW_GATE 2621440u
#define OW_INFO 3670016u

// ---------------------------------------------------------------------------
__device__ __forceinline__ uint32_t pack_h2(float x, float y) {
    __half2 h = __floats2half2_rn(x, y);
    return *(uint32_t*)&h;
}

__device__ __forceinline__ void mma_fp16(float* c,
    uint32_t a0, uint32_t a1, uint32_t a2, uint32_t a3,
    uint32_t b0, uint32_t b1)
{
    asm volatile(
        "mma.sync.aligned.m16n8k16.row.col.f32.f16.f16.f32 "
        "{%0,%1,%2,%3},{%4,%5,%6,%7},{%8,%9},{%0,%1,%2,%3};"
        : "+f"(c[0]), "+f"(c[1]), "+f"(c[2]), "+f"(c[3])
        : "r"(a0), "r"(a1), "r"(a2), "r"(a3), "r"(b0), "r"(b1));
}

__device__ __forceinline__ uint32_t smem_u32(const void* p) {
    uint32_t a;
    asm("{ .reg .u64 t; cvta.to.shared.u64 t, %1; cvt.u32.u64 %0, t; }" : "=r"(a) : "l"(p));
    return a;
}

__device__ __forceinline__ void cp16(uint32_t dst, const void* src) {
    asm volatile("cp.async.ca.shared.global [%0], [%1], 16;" :: "r"(dst), "l"(src));
}
#define CP_COMMIT() asm volatile("cp.async.commit_group;" ::: "memory")
#define CP_WAIT1()  asm volatile("cp.async.wait_group 1;" ::: "memory")
#define CP_WAIT0()  asm volatile("cp.async.wait_group 0;" ::: "memory")

// ---------------------------------------------------------------------------
// Conversion kernels (fp32 -> packed fp16), once per launch.
// ---------------------------------------------------------------------------
__global__ __launch_bounds__(256) void conv_in_kernel(
    const float* __restrict__ q_g, const float* __restrict__ k_g,
    const float* __restrict__ q_a, const float* __restrict__ k_a,
    const float* __restrict__ v_a)
{
    const int z = blockIdx.y;
    const float* src = (z == 0) ? q_a : (z == 1) ? q_g : (z == 2) ? k_a
                     : (z == 3) ? k_g : v_a;
    const size_t i = (size_t)blockIdx.x * 256 + threadIdx.x;
    float4 v = ((const float4*)src)[i];
    const size_t w = (size_t)z * 2097152 + i * 2;
    g_INh[w]     = pack_h2(v.x, v.y);
    g_INh[w + 1] = pack_h2(v.z, v.w);
}

__global__ __launch_bounds__(256) void conv_w_kernel(
    const float* __restrict__ Wqa, const float* __restrict__ Wqg,
    const float* __restrict__ Wka, const float* __restrict__ Wkg,
    const float* __restrict__ Wva, const float* __restrict__ Wgate,
    const float* __restrict__ Winfo)
{
    const int z = blockIdx.y;
    const float* src; size_t offw; size_t nf4;
    switch (z) {
        case 0: src = Wqa;   offw = OW_QA;   nf4 = 262144; break;
        case 1: src = Wqg;   offw = OW_QG;   nf4 = 262144; break;
        case 2: src = Wka;   offw = OW_KA;   nf4 = 262144; break;
        case 3: src = Wkg;   offw = OW_KG;   nf4 = 262144; break;
        case 4: src = Wva;   offw = OW_VA;   nf4 = 262144; break;
        case 5: src = Wgate; offw = OW_GATE; nf4 = 524288; break;
        default: src = Winfo; offw = OW_INFO; nf4 = 262144; break;
    }
    for (size_t i = (size_t)blockIdx.x * 256 + threadIdx.x; i < nf4; i += 262144) {
        float4 v = ((const float4*)src)[i];
        const size_t w = offw + i * 2;
        g_Wh[w]     = pack_h2(v.x, v.y);
        g_Wh[w + 1] = pack_h2(v.z, v.w);
    }
}

// ---------------------------------------------------------------------------
// fp16 GEMM via cp.async 3-stage pipeline (unchanged from R11).
// ---------------------------------------------------------------------------
#define GSMEM 61440
typedef uint32_t (*SmT)[20];

__device__ __forceinline__ void issue_stage(
    uint32_t smu, int stage,
    const uint32_t* __restrict__ Ahp, int ldaw,
    const uint32_t* __restrict__ A2h, int kspw,
    const uint32_t* __restrict__ Bhp, int ldbw,
    int m0, int n0, int kw0)
{
    const int tid = threadIdx.x;
    const uint32_t sbase = smu + (uint32_t)stage * 20480u;
    #pragma unroll
    for (int c = 0; c < 2; c++) {
        const int cid = tid + c * 256;
        const int row = cid >> 2, cw = (cid & 3) << 2;
        const int gw = kw0 + cw;
        const uint32_t* srcA;
        if (gw >= kspw) srcA = A2h + (size_t)(m0 + row) * 512 + (gw - kspw);
        else            srcA = Ahp + (size_t)(m0 + row) * ldaw + gw;
        const uint32_t dstA = sbase + (uint32_t)((row * 20 + cw) * 4);
        cp16(dstA, srcA);
        cp16(dstA + 10240u, Bhp + (size_t)(n0 + row) * ldbw + gw);
    }
}

__device__ __forceinline__ void mma_stage(
    uint32_t* stg, int wm, int wn, int g, int t, float acc[2][8][4])
{
    SmT Ah = (SmT)stg;
    SmT Bh = (SmT)(stg + 2560);
    #pragma unroll
    for (int kk = 0; kk < 2; kk++) {
        const int pc = kk * 8;
        uint32_t ah[2][4];
        #pragma unroll
        for (int mt = 0; mt < 2; mt++) {
            #pragma unroll
            for (int q = 0; q < 4; q++) {
                const int row = wm + mt * 16 + g + (q & 1) * 8;
                const int col = pc + t + (q >> 1) * 4;
                ah[mt][q] = Ah[row][col];
            }
        }
        #pragma unroll
        for (int nf = 0; nf < 8; nf++) {
            const int rb = wn + nf * 8 + g;
            const uint32_t b0 = Bh[rb][pc + t], b1 = Bh[rb][pc + t + 4];
            #pragma unroll
            for (int mt = 0; mt < 2; mt++)
                mma_fp16(acc[mt][nf], ah[mt][0], ah[mt][1], ah[mt][2], ah[mt][3], b0, b1);
        }
    }
}

__device__ __forceinline__ void gemm_fp16_ca(
    uint32_t* sm,
    const uint32_t* __restrict__ Ahp, int ldaw,
    const uint32_t* __restrict__ A2h, int kspw,
    const uint32_t* __restrict__ Bhp, int ldbw,
    int Kw, int m0, int n0, float acc[2][8][4])
{
    const uint32_t smu = smem_u32(sm);
    const int warp = threadIdx.x >> 5, lane = threadIdx.x & 31;
    const int wm = (warp & 3) * 32, wn = (warp >> 2) * 64;
    const int g = lane >> 2, t = lane & 3;
    const int nK = Kw >> 4;

    issue_stage(smu, 0, Ahp, ldaw, A2h, kspw, Bhp, ldbw, m0, n0, 0);
    CP_COMMIT();
    issue_stage(smu, 1, Ahp, ldaw, A2h, kspw, Bhp, ldbw, m0, n0, 16);
    CP_COMMIT();

    for (int kt = 0; kt < nK; kt++) {
        CP_WAIT1();
        __syncthreads();
        if (kt + 2 < nK) {
            issue_stage(smu, (kt + 2) % 3, Ahp, ldaw, A2h, kspw, Bhp, ldbw,
                        m0, n0, (kt + 2) * 16);
            CP_COMMIT();
        }
        mma_stage(sm + (kt % 3) * 5120, wm, wn, g, t, acc);
    }
}

// ---------------------------------------------------------------------------
// Kernel 1: 5 projections + gate in ONE launch (grid.z = 6).
// ---------------------------------------------------------------------------
__global__ __launch_bounds__(256, 2) void projgate_kernel(
    const float* __restrict__ bqa, const float* __restrict__ bqg,
    const float* __restrict__ bka, const float* __restrict__ bkg,
    const float* __restrict__ bva, const float* __restrict__ bgate)
{
    extern __shared__ uint32_t sm[];
    const int p = blockIdx.z;
    const int m0 = blockIdx.y * 128;
    const int n0 = blockIdx.x * 128;
    const int lane = threadIdx.x & 31, warp = threadIdx.x >> 5;
    const int wm = (warp & 3) * 32, wn = (warp >> 2) * 64;
    const int g = lane >> 2, t = lane & 3;
    float acc[2][8][4] = {};

    if (p < 5) {
        const uint32_t* Ahp = g_INh + (size_t)p * 2097152;
        const uint32_t woff = (p == 0) ? OW_QA : (p == 1) ? OW_QG : (p == 2) ? OW_KA
                            : (p == 3) ? OW_KG : OW_VA;
        const float* bias = (p == 0) ? bqa : (p == 1) ? bqg : (p == 2) ? bka
                          : (p == 3) ? bkg : bva;
        gemm_fp16_ca(sm, Ahp, 512, nullptr, 1 << 30, g_Wh + woff, 512, 512, m0, n0, acc);

        #pragma unroll
        for (int nf = 0; nf < 8; nf++) {
            const int n  = n0 + wn + nf * 8 + 2 * t;
            const int h  = n >> 6, jj = n & 63;
            const float bx = bias[n], by = bias[n + 1];
            #pragma unroll
            for (int mt = 0; mt < 2; mt++) {
                #pragma unroll
                for (int h2 = 0; h2 < 2; h2++) {
                    const int m = m0 + wm + mt * 16 + g + h2 * 8;
                    const int b = m >> 10, s = m & 1023;
                    const size_t bhh = (size_t)(b * 16 + h);
                    const float vx = acc[mt][nf][h2 * 2 + 0] + bx;
                    const float vy = acc[mt][nf][h2 * 2 + 1] + by;
                    if (p == 4) {
                        __half* Vp = (__half*)g_Vh;
                        Vp[(bhh * 64 + jj)     * 1024 + s] = __float2half_rn(vx);
                        Vp[(bhh * 64 + jj + 1) * 1024 + s] = __float2half_rn(vy);
                    } else {
                        const size_t widx = (bhh * 1024 + s) * 64 + ((p & 1) ? 32 : 0) + (jj >> 1);
                        if (p < 2) g_Qh[widx] = pack_h2(vx, vy);
                        else       g_Kh[widx] = pack_h2(vx, vy);
                    }
                }
            }
        }
    } else {
        // gate: concat(qa,qg) @ Wgate^T, Kw = 1024 words
        gemm_fp16_ca(sm, g_INh, 512, g_INh + 2097152, 512,
                     g_Wh + OW_GATE, 1024, 1024, m0, n0, acc);

        #pragma unroll
        for (int nf = 0; nf < 8; nf++) {
            const int n = n0 + wn + nf * 8 + 2 * t;
            const float bx = bgate[n], by = bgate[n + 1];
            #pragma unroll
            for (int mt = 0; mt < 2; mt++) {
                #pragma unroll
                for (int h2 = 0; h2 < 2; h2++) {
                    const int m = m0 + wm + mt * 16 + g + h2 * 8;
                    float2 v;
                    v.x = 1.0f / (1.0f + __expf(-(acc[mt][nf][h2 * 2 + 0] + bx)));
                    v.y = 1.0f / (1.0f + __expf(-(acc[mt][nf][h2 * 2 + 1] + by)));
                    *(float2*)&g_G[(size_t)m * 1024 + n] = v;
                }
            }
        }
    }
}

// ---------------------------------------------------------------------------
// Kernel 3: fused flash attention, double-buffered cp.async K/V.
// smem: Qh [128][68] @0, Kst0 @34816, Kst1 @69632, Vst0 @104448, Vst1 @121856,
// redmax @139264, redsum @140288. Osum reuses Kst0.
// ---------------------------------------------------------------------------
#define ATTN_SMEM 141312

__global__ __launch_bounds__(256) void attn_kernel(const int* __restrict__ mask)
{
    extern __shared__ char smem[];
    uint32_t (*Qh)[68] = (uint32_t(*)[68])(smem);
    float* redmax = (float*)(smem + 139264);
    float* redsum = (float*)(smem + 140288);
    float* Osum   = (float*)(smem + 34816);
    const uint32_t smu = smem_u32(smem);

    const int tid  = threadIdx.x;
    const int warp = tid >> 5, lane = tid & 31;
    const int wm = (warp & 3) * 32;
    const int wn = (warp >> 2);
    const int g  = lane >> 2;
    const int t  = lane & 3;

    const int bh = blockIdx.y;
    const int b  = bh >> 4, h = bh & 15;
    const int m0 = blockIdx.x * 128;

    const uint32_t* Qhg = g_Qh + ((size_t)bh << 16);
    const uint32_t* Khg = g_Kh + ((size_t)bh << 16);
    const uint32_t* Vhg = g_Vh + (size_t)bh * 32768;

    // cp.async loader mapping: 16 threads per row, 4 words (16B) each
    const int lr16 = tid >> 4;          // 0..15
    const int cw4  = (tid & 15) * 4;    // word col

    // Q tile (once, plain loads)
    {
        const int lrow = tid >> 5;
        const int pcw  = (tid & 31) * 2;
        #pragma unroll
        for (int i = 0; i < 16; i++) {
            const int r = lrow + i * 8;
            *(uint2*)&Qh[r][pcw] = *(const uint2*)(Qhg + (size_t)(m0 + r) * 64 + pcw);
        }
    }

    // issue K/V stage for tile nt into buffer st
    auto issue_kv = [&](int nt, int st) {
        const int n0 = nt * 128;
        const uint32_t kbase = smu + 34816u + (uint32_t)st * 34816u;
        const uint32_t vbase = smu + 104448u + (uint32_t)st * 17408u;
        #pragma unroll
        for (int i = 0; i < 8; i++) {
            const int r = lr16 + i * 16;
            cp16(kbase + (uint32_t)((r * 68 + cw4) * 4),
                 Khg + (size_t)(n0 + r) * 64 + cw4);
        }
        #pragma unroll
        for (int i = 0; i < 4; i++) {
            const int r = lr16 + i * 16;
            cp16(vbase + (uint32_t)((r * 68 + cw4) * 4),
                 Vhg + (size_t)r * 512 + (n0 >> 1) + cw4);
        }
        CP_COMMIT();
    };

    float o[2][8][4] = {};
    float mrun[2][2] = {{-INFINITY, -INFINITY}, {-INFINITY, -INFINITY}};
    float lrun[2][2] = {};
    const float scale = 0.08838834764831845f;

    issue_kv(0, 0);

    for (int nt = 0; nt < 8; nt++) {
        CP_WAIT0();
        __syncthreads();           // stage nt visible; prior compute done
        if (nt + 1 < 8)
            issue_kv(nt + 1, (nt + 1) & 1);   // overlaps compute below

        const int st = nt & 1;
        uint32_t (*Kh)[68] = (uint32_t(*)[68])(smem + 34816 + st * 34816);
        uint32_t (*Vh)[68] = (uint32_t(*)[68])(smem + 104448 + st * 17408);
        const int n0 = nt * 128;

        // ---- S = Q K^T ----
        float s[2][8][4] = {};
        #pragma unroll
        for (int ks = 0; ks < 8; ks++) {
            const int pc = ks * 8;
            uint32_t ah[2][4];
            #pragma unroll
            for (int mt = 0; mt < 2; mt++) {
                #pragma unroll
                for (int q = 0; q < 4; q++) {
                    const int row = wm + mt * 16 + g + (q & 1) * 8;
                    const int col = pc + t + (q >> 1) * 4;
                    ah[mt][q] = Qh[row][col];
                }
            }
            #pragma unroll
            for (int nf = 0; nf < 8; nf++) {
                const int rb = wn * 64 + nf * 8 + g;
                const uint32_t b0 = Kh[rb][pc + t], b1 = Kh[rb][pc + t + 4];
                #pragma unroll
                for (int mt = 0; mt < 2; mt++)
                    mma_fp16(s[mt][nf], ah[mt][0], ah[mt][1], ah[mt][2], ah[mt][3], b0, b1);
            }
        }

        // ---- scale + mask + row max ----
        float pm[2][2];
        #pragma unroll
        for (int mt = 0; mt < 2; mt++) {
            #pragma unroll
            for (int h2 = 0; h2 < 2; h2++) {
                const int rglob = m0 + wm + mt * 16 + g + h2 * 8;
                float mx = -INFINITY;
                #pragma unroll
                for (int nf = 0; nf < 8; nf++) {
                    const int ncol = n0 + wn * 64 + nf * 8 + 2 * t;
                    const int2 mk = *(const int2*)(mask + (((size_t)b << 20) + ((size_t)rglob << 10) + ncol));
                    float v0 = s[mt][nf][h2 * 2 + 0] * scale;
                    float v1 = s[mt][nf][h2 * 2 + 1] * scale;
                    if (mk.x == 0) v0 = -1e9f;
                    if (mk.y == 0) v1 = -1e9f;
                    s[mt][nf][h2 * 2 + 0] = v0;
                    s[mt][nf][h2 * 2 + 1] = v1;
                    mx = fmaxf(mx, fmaxf(v0, v1));
                }
                pm[mt][h2] = mx;
            }
        }
        #pragma unroll
        for (int mt = 0; mt < 2; mt++)
            #pragma unroll
            for (int h2 = 0; h2 < 2; h2++) {
                pm[mt][h2] = fmaxf(pm[mt][h2], __shfl_xor_sync(0xffffffffu, pm[mt][h2], 1));
                pm[mt][h2] = fmaxf(pm[mt][h2], __shfl_xor_sync(0xffffffffu, pm[mt][h2], 2));
            }
        if (t == 0) {
            #pragma unroll
            for (int mt = 0; mt < 2; mt++)
                #pragma unroll
                for (int h2 = 0; h2 < 2; h2++)
                    redmax[wn * 128 + wm + mt * 16 + g + h2 * 8] = pm[mt][h2];
        }
        __syncthreads();

        // ---- running stats, exponentiate, rescale O ----
        float alpha[2][2], psum[2][2];
        #pragma unroll
        for (int mt = 0; mt < 2; mt++) {
            #pragma unroll
            for (int h2 = 0; h2 < 2; h2++) {
                const int rl = wm + mt * 16 + g + h2 * 8;
                const float mtile = fmaxf(redmax[rl], redmax[128 + rl]);
                const float mnew  = fmaxf(mrun[mt][h2], mtile);
                alpha[mt][h2] = __expf(mrun[mt][h2] - mnew);
                mrun[mt][h2]  = mnew;
                float ps = 0.0f;
                #pragma unroll
                for (int nf = 0; nf < 8; nf++) {
                    float p0 = __expf(s[mt][nf][h2 * 2 + 0] - mnew);
                    float p1 = __expf(s[mt][nf][h2 * 2 + 1] - mnew);
                    s[mt][nf][h2 * 2 + 0] = p0;
                    s[mt][nf][h2 * 2 + 1] = p1;
                    ps += p0 + p1;
                }
                psum[mt][h2] = ps;
            }
        }
        #pragma unroll
        for (int mt = 0; mt < 2; mt++)
            #pragma unroll
            for (int nf = 0; nf < 8; nf++)
                #pragma unroll
                for (int e = 0; e < 4; e++)
                    o[mt][nf][e] *= alpha[mt][e >> 1];
        #pragma unroll
        for (int mt = 0; mt < 2; mt++)
            #pragma unroll
            for (int h2 = 0; h2 < 2; h2++) {
                psum[mt][h2] += __shfl_xor_sync(0xffffffffu, psum[mt][h2], 1);
                psum[mt][h2] += __shfl_xor_sync(0xffffffffu, psum[mt][h2], 2);
            }
        if (t == 0) {
            #pragma unroll
            for (int mt = 0; mt < 2; mt++)
                #pragma unroll
                for (int h2 = 0; h2 < 2; h2++)
                    redsum[wn * 128 + wm + mt * 16 + g + h2 * 8] = psum[mt][h2];
        }
        __syncthreads();
        #pragma unroll
        for (int mt = 0; mt < 2; mt++)
            #pragma unroll
            for (int h2 = 0; h2 < 2; h2++) {
                const int rl = wm + mt * 16 + g + h2 * 8;
                lrun[mt][h2] = lrun[mt][h2] * alpha[mt][h2] + redsum[rl] + redsum[128 + rl];
            }

        // ---- O += P V ----
        #pragma unroll
        for (int ks2 = 0; ks2 < 4; ks2++) {
            uint32_t ah[2][4];
            #pragma unroll
            for (int mt = 0; mt < 2; mt++) {
                ah[mt][0] = pack_h2(s[mt][2 * ks2][0],     s[mt][2 * ks2][1]);
                ah[mt][1] = pack_h2(s[mt][2 * ks2][2],     s[mt][2 * ks2][3]);
                ah[mt][2] = pack_h2(s[mt][2 * ks2 + 1][0], s[mt][2 * ks2 + 1][1]);
                ah[mt][3] = pack_h2(s[mt][2 * ks2 + 1][2], s[mt][2 * ks2 + 1][3]);
            }
            const int vcol = wn * 32 + ks2 * 8 + t;
            #pragma unroll
            for (int nf = 0; nf < 8; nf++) {
                const int rv = nf * 8 + g;
                const uint32_t b0 = Vh[rv][vcol], b1 = Vh[rv][vcol + 4];
                #pragma unroll
                for (int mt = 0; mt < 2; mt++)
                    mma_fp16(o[mt][nf], ah[mt][0], ah[mt][1], ah[mt][2], ah[mt][3], b0, b1);
            }
        }
    }

    // ---- epilogue: combine partials, normalize, write packed X ----
    __syncthreads();
    if (wn == 1) {
        #pragma unroll
        for (int mt = 0; mt < 2; mt++)
            #pragma unroll
            for (int h2 = 0; h2 < 2; h2++) {
                const int rl = wm + mt * 16 + g + h2 * 8;
                #pragma unroll
                for (int nf = 0; nf < 8; nf++) {
                    float2 v;
                    v.x = o[mt][nf][h2 * 2 + 0];
                    v.y = o[mt][nf][h2 * 2 + 1];
                    *(float2*)&Osum[rl * 66 + nf * 8 + 2 * t] = v;
                }
            }
    }
    __syncthreads();
    if (wn == 0) {
        #pragma unroll
        for (int mt = 0; mt < 2; mt++)
            #pragma unroll
            for (int h2 = 0; h2 < 2; h2++) {
                const int rl = wm + mt * 16 + g + h2 * 8;
                const float inv = 1.0f / lrun[mt][h2];
                #pragma unroll
                for (int nf = 0; nf < 8; nf++) {
                    const int c = nf * 8 + 2 * t;
                    float2 p = *(float2*)&Osum[rl * 66 + c];
                    const float vx = (o[mt][nf][h2 * 2 + 0] + p.x) * inv;
                    const float vy = (o[mt][nf][h2 * 2 + 1] + p.y) * inv;
                    g_Xh[(size_t)(b * 1024 + m0 + rl) * 512 + ((h * 64 + c) >> 1)] = pack_h2(vx, vy);
                }
            }
    }
}

// ---------------------------------------------------------------------------
// Kernel 4: out = gate * (X @ Winfo^T + binfo)
// ---------------------------------------------------------------------------
__global__ __launch_bounds__(256, 2) void info_kernel(
    const float* __restrict__ binfo, float* __restrict__ out)
{
    extern __shared__ uint32_t sm[];
    const int m0 = blockIdx.y * 128;
    const int n0 = blockIdx.x * 128;
    float acc[2][8][4] = {};
    gemm_fp16_ca(sm, g_Xh, 512, nullptr, 1 << 30, g_Wh + OW_INFO, 512, 512, m0, n0, acc);

    const int lane = threadIdx.x & 31, warp = threadIdx.x >> 5;
    const int wm = (warp & 3) * 32, wn = (warp >> 2) * 64;
    const int g = lane >> 2, t = lane & 3;

    #pragma unroll
    for (int nf = 0; nf < 8; nf++) {
        const int n = n0 + wn + nf * 8 + 2 * t;
        const float bx = binfo[n], by = binfo[n + 1];
        #pragma unroll
        for (int mt = 0; mt < 2; mt++) {
            #pragma unroll
            for (int h2 = 0; h2 < 2; h2++) {
                const int m = m0 + wm + mt * 16 + g + h2 * 8;
                const float2 gg = *(const float2*)&g_G[(size_t)m * 1024 + n];
                float2 v;
                v.x = gg.x * (acc[mt][nf][h2 * 2 + 0] + bx);
                v.y = gg.y * (acc[mt][nf][h2 * 2 + 1] + by);
                *(float2*)&out[(size_t)m * 1024 + n] = v;
            }
        }
    }
}

// ---------------------------------------------------------------------------
extern "C" void kernel_launch(void* const* d_in, const int* in_sizes, int n_in,
                              void* d_out, int out_size)
{
    (void)in_sizes; (void)n_in; (void)out_size;
    const float* query_g = (const float*)d_in[0];
    const float* key_g   = (const float*)d_in[1];
    const float* query_a = (const float*)d_in[2];
    const float* key_a   = (const float*)d_in[3];
    const float* value_a = (const float*)d_in[4];
    const int*   mask    = (const int*)  d_in[5];
    const float* Wqg = (const float*)d_in[6];  const float* bqg = (const float*)d_in[7];
    const float* Wkg = (const float*)d_in[8];  const float* bkg = (const float*)d_in[9];
    const float* Wqa = (const float*)d_in[10]; const float* bqa = (const float*)d_in[11];
    const float* Wka = (const float*)d_in[12]; const float* bka = (const float*)d_in[13];
    const float* Wva = (const float*)d_in[14]; const float* bva = (const float*)d_in[15];
    const float* Wgate = (const float*)d_in[16]; const float* bgate = (const float*)d_in[17];
    const float* Winfo = (const float*)d_in[18]; const float* binfo = (const float*)d_in[19];

    static int attr_set = 0;
    if (!attr_set) {
        cudaFuncSetAttribute(attn_kernel, cudaFuncAttributeMaxDynamicSharedMemorySize, ATTN_SMEM);
        cudaFuncSetAttribute(projgate_kernel, cudaFuncAttributeMaxDynamicSharedMemorySize, GSMEM);
        cudaFuncSetAttribute(info_kernel, cudaFuncAttributeMaxDynamicSharedMemorySize, GSMEM);
        attr_set = 1;
    }

    dim3 blk(256);
    conv_in_kernel<<<dim3(4096, 5), blk>>>(query_g, key_g, query_a, key_a, value_a);
    conv_w_kernel<<<dim3(1024, 7), blk>>>(Wqa, Wqg, Wka, Wkg, Wva, Wgate, Winfo);
    projgate_kernel<<<dim3(8, 32, 6), blk, GSMEM>>>(bqa, bqg, bka, bkg, bva, bgate);
    attn_kernel<<<dim3(8, 64), blk, ATTN_SMEM>>>(mask);
    info_kernel<<<dim3(8, 32, 1), blk, GSMEM>>>(binfo, (float*)d_out);
}

// round 13
// speedup vs baseline: 2.5768x; 1.0205x over previous
#include <cuda_runtime.h>
#include <cuda_fp16.h>
#include <math.h>
#include <stdint.h>

// Problem constants
#define B_  4
#define S_  1024
#define BH  64     // B*H

// ---------------------------------------------------------------------------
// Scratch. "h" arrays hold packed fp16 pairs: word w = h(x[2w]) | h(x[2w+1])<<16
// ---------------------------------------------------------------------------
static __device__ uint32_t g_INh[(size_t)5 * 2097152];   // [qa,qg,ka,kg,va] inputs
static __device__ uint32_t g_Wh[(size_t)4194304];        // Wqa..Wva,Wgate,Winfo
static __device__ uint32_t g_Qh[(size_t)BH * S_ * 64];   // [bh,s,64w] (qa|qg), pre-scaled
static __device__ uint32_t g_Kh[(size_t)BH * S_ * 64];
static __device__ uint32_t g_Vh[(size_t)BH * 64 * 512];  // transposed [bh,j,s] fp16
static __device__ uint32_t g_MB[(size_t)B_ * S_ * 512];  // mask bias packed fp16 (0 / -30000)
static __device__ uint32_t g_Xh[(size_t)4096 * 512];     // attn out packed
static __device__ float    g_G [(size_t)4096 * 1024];    // gate fp32

#define OW_QA 0u
#define OW_QG 524288u
#define OW_KA 1048576u
#define OW_KG 1572864u
#define OW_VA 2097152u
#define OW_GATE 2621440u
#define OW_INFO 3670016u

// ---------------------------------------------------------------------------
__device__ __forceinline__ uint32_t pack_h2(float x, float y) {
    __half2 h = __floats2half2_rn(x, y);
    return *(uint32_t*)&h;
}

__device__ __forceinline__ void mma_fp16(float* c,
    uint32_t a0, uint32_t a1, uint32_t a2, uint32_t a3,
    uint32_t b0, uint32_t b1)
{
    asm volatile(
        "mma.sync.aligned.m16n8k16.row.col.f32.f16.f16.f32 "
        "{%0,%1,%2,%3},{%4,%5,%6,%7},{%8,%9},{%0,%1,%2,%3};"
        : "+f"(c[0]), "+f"(c[1]), "+f"(c[2]), "+f"(c[3])
        : "r"(a0), "r"(a1), "r"(a2), "r"(a3), "r"(b0), "r"(b1));
}

__device__ __forceinline__ uint32_t smem_u32(const void* p) {
    uint32_t a;
    asm("{ .reg .u64 t; cvta.to.shared.u64 t, %1; cvt.u32.u64 %0, t; }" : "=r"(a) : "l"(p));
    return a;
}

__device__ __forceinline__ void cp16(uint32_t dst, const void* src) {
    asm volatile("cp.async.ca.shared.global [%0], [%1], 16;" :: "r"(dst), "l"(src));
}
#define CP_COMMIT() asm volatile("cp.async.commit_group;" ::: "memory")
#define CP_WAIT1()  asm volatile("cp.async.wait_group 1;" ::: "memory")
#define CP_WAIT0()  asm volatile("cp.async.wait_group 0;" ::: "memory")

// ---------------------------------------------------------------------------
// Conversion kernels (once per launch)
// ---------------------------------------------------------------------------
__global__ __launch_bounds__(256) void conv_in_kernel(
    const float* __restrict__ q_g, const float* __restrict__ k_g,
    const float* __restrict__ q_a, const float* __restrict__ k_a,
    const float* __restrict__ v_a)
{
    const int z = blockIdx.y;
    const float* src = (z == 0) ? q_a : (z == 1) ? q_g : (z == 2) ? k_a
                     : (z == 3) ? k_g : v_a;
    const size_t i = (size_t)blockIdx.x * 256 + threadIdx.x;
    float4 v = ((const float4*)src)[i];
    const size_t w = (size_t)z * 2097152 + i * 2;
    g_INh[w]     = pack_h2(v.x, v.y);
    g_INh[w + 1] = pack_h2(v.z, v.w);
}

__global__ __launch_bounds__(256) void conv_w_kernel(
    const float* __restrict__ Wqa, const float* __restrict__ Wqg,
    const float* __restrict__ Wka, const float* __restrict__ Wkg,
    const float* __restrict__ Wva, const float* __restrict__ Wgate,
    const float* __restrict__ Winfo)
{
    const int z = blockIdx.y;
    const float* src; size_t offw; size_t nf4;
    switch (z) {
        case 0: src = Wqa;   offw = OW_QA;   nf4 = 262144; break;
        case 1: src = Wqg;   offw = OW_QG;   nf4 = 262144; break;
        case 2: src = Wka;   offw = OW_KA;   nf4 = 262144; break;
        case 3: src = Wkg;   offw = OW_KG;   nf4 = 262144; break;
        case 4: src = Wva;   offw = OW_VA;   nf4 = 262144; break;
        case 5: src = Wgate; offw = OW_GATE; nf4 = 524288; break;
        default: src = Winfo; offw = OW_INFO; nf4 = 262144; break;
    }
    for (size_t i = (size_t)blockIdx.x * 256 + threadIdx.x; i < nf4; i += 262144) {
        float4 v = ((const float4*)src)[i];
        const size_t w = offw + i * 2;
        g_Wh[w]     = pack_h2(v.x, v.y);
        g_Wh[w + 1] = pack_h2(v.z, v.w);
    }
}

// mask (int32 0/1) -> packed fp16 additive bias (-30000 / 0)
__global__ __launch_bounds__(256) void conv_mask_kernel(const int* __restrict__ mask)
{
    const size_t i = (size_t)blockIdx.x * 256 + threadIdx.x;   // int2 index
    const int2 mk = ((const int2*)mask)[i];
    g_MB[i] = pack_h2(mk.x == 0 ? -30000.0f : 0.0f,
                      mk.y == 0 ? -30000.0f : 0.0f);
}

// ---------------------------------------------------------------------------
// fp16 GEMM via cp.async 3-stage pipeline.
// ---------------------------------------------------------------------------
#define GSMEM 61440
typedef uint32_t (*SmT)[20];

__device__ __forceinline__ void issue_stage(
    uint32_t smu, int stage,
    const uint32_t* __restrict__ Ahp, int ldaw,
    const uint32_t* __restrict__ A2h, int kspw,
    const uint32_t* __restrict__ Bhp, int ldbw,
    int m0, int n0, int kw0)
{
    const int tid = threadIdx.x;
    const uint32_t sbase = smu + (uint32_t)stage * 20480u;
    #pragma unroll
    for (int c = 0; c < 2; c++) {
        const int cid = tid + c * 256;
        const int row = cid >> 2, cw = (cid & 3) << 2;
        const int gw = kw0 + cw;
        const uint32_t* srcA;
        if (gw >= kspw) srcA = A2h + (size_t)(m0 + row) * 512 + (gw - kspw);
        else            srcA = Ahp + (size_t)(m0 + row) * ldaw + gw;
        const uint32_t dstA = sbase + (uint32_t)((row * 20 + cw) * 4);
        cp16(dstA, srcA);
        cp16(dstA + 10240u, Bhp + (size_t)(n0 + row) * ldbw + gw);
    }
}

__device__ __forceinline__ void mma_stage(
    uint32_t* stg, int wm, int wn, int g, int t, float acc[2][8][4])
{
    SmT Ah = (SmT)stg;
    SmT Bh = (SmT)(stg + 2560);
    #pragma unroll
    for (int kk = 0; kk < 2; kk++) {
        const int pc = kk * 8;
        uint32_t ah[2][4];
        #pragma unroll
        for (int mt = 0; mt < 2; mt++) {
            #pragma unroll
            for (int q = 0; q < 4; q++) {
                const int row = wm + mt * 16 + g + (q & 1) * 8;
                const int col = pc + t + (q >> 1) * 4;
                ah[mt][q] = Ah[row][col];
            }
        }
        #pragma unroll
        for (int nf = 0; nf < 8; nf++) {
            const int rb = wn + nf * 8 + g;
            const uint32_t b0 = Bh[rb][pc + t], b1 = Bh[rb][pc + t + 4];
            #pragma unroll
            for (int mt = 0; mt < 2; mt++)
                mma_fp16(acc[mt][nf], ah[mt][0], ah[mt][1], ah[mt][2], ah[mt][3], b0, b1);
        }
    }
}

__device__ __forceinline__ void gemm_fp16_ca(
    uint32_t* sm,
    const uint32_t* __restrict__ Ahp, int ldaw,
    const uint32_t* __restrict__ A2h, int kspw,
    const uint32_t* __restrict__ Bhp, int ldbw,
    int Kw, int m0, int n0, float acc[2][8][4])
{
    const uint32_t smu = smem_u32(sm);
    const int warp = threadIdx.x >> 5, lane = threadIdx.x & 31;
    const int wm = (warp & 3) * 32, wn = (warp >> 2) * 64;
    const int g = lane >> 2, t = lane & 3;
    const int nK = Kw >> 4;

    issue_stage(smu, 0, Ahp, ldaw, A2h, kspw, Bhp, ldbw, m0, n0, 0);
    CP_COMMIT();
    issue_stage(smu, 1, Ahp, ldaw, A2h, kspw, Bhp, ldbw, m0, n0, 16);
    CP_COMMIT();

    for (int kt = 0; kt < nK; kt++) {
        CP_WAIT1();
        __syncthreads();
        if (kt + 2 < nK) {
            issue_stage(smu, (kt + 2) % 3, Ahp, ldaw, A2h, kspw, Bhp, ldbw,
                        m0, n0, (kt + 2) * 16);
            CP_COMMIT();
        }
        mma_stage(sm + (kt % 3) * 5120, wm, wn, g, t, acc);
    }
}

// ---------------------------------------------------------------------------
// Kernel 1: gate (z=0, longest first) + 5 projections (z=1..5).
// Q written pre-scaled by 1/sqrt(128).
// ---------------------------------------------------------------------------
__global__ __launch_bounds__(256, 2) void projgate_kernel(
    const float* __restrict__ bqa, const float* __restrict__ bqg,
    const float* __restrict__ bka, const float* __restrict__ bkg,
    const float* __restrict__ bva, const float* __restrict__ bgate)
{
    extern __shared__ uint32_t sm[];
    const int m0 = blockIdx.y * 128;
    const int n0 = blockIdx.x * 128;
    const int lane = threadIdx.x & 31, warp = threadIdx.x >> 5;
    const int wm = (warp & 3) * 32, wn = (warp >> 2) * 64;
    const int g = lane >> 2, t = lane & 3;
    float acc[2][8][4] = {};

    if (blockIdx.z == 0) {
        // gate: concat(qa,qg) @ Wgate^T, Kw = 1024 words
        gemm_fp16_ca(sm, g_INh, 512, g_INh + 2097152, 512,
                     g_Wh + OW_GATE, 1024, 1024, m0, n0, acc);

        #pragma unroll
        for (int nf = 0; nf < 8; nf++) {
            const int n = n0 + wn + nf * 8 + 2 * t;
            const float bx = bgate[n], by = bgate[n + 1];
            #pragma unroll
            for (int mt = 0; mt < 2; mt++) {
                #pragma unroll
                for (int h2 = 0; h2 < 2; h2++) {
                    const int m = m0 + wm + mt * 16 + g + h2 * 8;
                    float2 v;
                    v.x = 1.0f / (1.0f + __expf(-(acc[mt][nf][h2 * 2 + 0] + bx)));
                    v.y = 1.0f / (1.0f + __expf(-(acc[mt][nf][h2 * 2 + 1] + by)));
                    *(float2*)&g_G[(size_t)m * 1024 + n] = v;
                }
            }
        }
    } else {
        const int p = blockIdx.z - 1;
        const uint32_t* Ahp = g_INh + (size_t)p * 2097152;
        const uint32_t woff = (p == 0) ? OW_QA : (p == 1) ? OW_QG : (p == 2) ? OW_KA
                            : (p == 3) ? OW_KG : OW_VA;
        const float* bias = (p == 0) ? bqa : (p == 1) ? bqg : (p == 2) ? bka
                          : (p == 3) ? bkg : bva;
        gemm_fp16_ca(sm, Ahp, 512, nullptr, 1 << 30, g_Wh + woff, 512, 512, m0, n0, acc);

        const float qs = (p < 2) ? 0.08838834764831845f : 1.0f;   // fold 1/sqrt(128) into Q
        #pragma unroll
        for (int nf = 0; nf < 8; nf++) {
            const int n  = n0 + wn + nf * 8 + 2 * t;
            const int h  = n >> 6, jj = n & 63;
            const float bx = bias[n], by = bias[n + 1];
            #pragma unroll
            for (int mt = 0; mt < 2; mt++) {
                #pragma unroll
                for (int h2 = 0; h2 < 2; h2++) {
                    const int m = m0 + wm + mt * 16 + g + h2 * 8;
                    const int b = m >> 10, s = m & 1023;
                    const size_t bhh = (size_t)(b * 16 + h);
                    const float vx = (acc[mt][nf][h2 * 2 + 0] + bx) * qs;
                    const float vy = (acc[mt][nf][h2 * 2 + 1] + by) * qs;
                    if (p == 4) {
                        __half* Vp = (__half*)g_Vh;
                        Vp[(bhh * 64 + jj)     * 1024 + s] = __float2half_rn(vx);
                        Vp[(bhh * 64 + jj + 1) * 1024 + s] = __float2half_rn(vy);
                    } else {
                        const size_t widx = (bhh * 1024 + s) * 64 + ((p & 1) ? 32 : 0) + (jj >> 1);
                        if (p < 2) g_Qh[widx] = pack_h2(vx, vy);
                        else       g_Kh[widx] = pack_h2(vx, vy);
                    }
                }
            }
        }
    }
}

// ---------------------------------------------------------------------------
// Kernel 3: fused flash attention, double-buffered cp.async K/V, fp16 bias mask.
// smem: Qh [128][68] @0, Kst0 @34816, Kst1 @69632, Vst0 @104448, Vst1 @121856,
// redmax @139264, redsum @140288. Osum reuses Kst0.
// ---------------------------------------------------------------------------
#define ATTN_SMEM 141312

__global__ __launch_bounds__(256) void attn_kernel()
{
    extern __shared__ char smem[];
    uint32_t (*Qh)[68] = (uint32_t(*)[68])(smem);
    float* redmax = (float*)(smem + 139264);
    float* redsum = (float*)(smem + 140288);
    float* Osum   = (float*)(smem + 34816);
    const uint32_t smu = smem_u32(smem);

    const int tid  = threadIdx.x;
    const int warp = tid >> 5, lane = tid & 31;
    const int wm = (warp & 3) * 32;
    const int wn = (warp >> 2);
    const int g  = lane >> 2;
    const int t  = lane & 3;

    const int bh = blockIdx.y;
    const int b  = bh >> 4, h = bh & 15;
    const int m0 = blockIdx.x * 128;

    const uint32_t* Qhg = g_Qh + ((size_t)bh << 16);
    const uint32_t* Khg = g_Kh + ((size_t)bh << 16);
    const uint32_t* Vhg = g_Vh + (size_t)bh * 32768;

    const int lr16 = tid >> 4;
    const int cw4  = (tid & 15) * 4;

    // Q tile (once)
    {
        const int lrow = tid >> 5;
        const int pcw  = (tid & 31) * 2;
        #pragma unroll
        for (int i = 0; i < 16; i++) {
            const int r = lrow + i * 8;
            *(uint2*)&Qh[r][pcw] = *(const uint2*)(Qhg + (size_t)(m0 + r) * 64 + pcw);
        }
    }

    auto issue_kv = [&](int nt, int st) {
        const int n0 = nt * 128;
        const uint32_t kbase = smu + 34816u + (uint32_t)st * 34816u;
        const uint32_t vbase = smu + 104448u + (uint32_t)st * 17408u;
        #pragma unroll
        for (int i = 0; i < 8; i++) {
            const int r = lr16 + i * 16;
            cp16(kbase + (uint32_t)((r * 68 + cw4) * 4),
                 Khg + (size_t)(n0 + r) * 64 + cw4);
        }
        #pragma unroll
        for (int i = 0; i < 4; i++) {
            const int r = lr16 + i * 16;
            cp16(vbase + (uint32_t)((r * 68 + cw4) * 4),
                 Vhg + (size_t)r * 512 + (n0 >> 1) + cw4);
        }
        CP_COMMIT();
    };

    float o[2][8][4] = {};
    float mrun[2][2] = {{-INFINITY, -INFINITY}, {-INFINITY, -INFINITY}};
    float lrun[2][2] = {};

    issue_kv(0, 0);

    for (int nt = 0; nt < 8; nt++) {
        CP_WAIT0();
        __syncthreads();
        if (nt + 1 < 8)
            issue_kv(nt + 1, (nt + 1) & 1);

        const int st = nt & 1;
        uint32_t (*Kh)[68] = (uint32_t(*)[68])(smem + 34816 + st * 34816);
        uint32_t (*Vh)[68] = (uint32_t(*)[68])(smem + 104448 + st * 17408);
        const int n0 = nt * 128;

        // ---- S = Q K^T (Q pre-scaled) ----
        float s[2][8][4] = {};
        #pragma unroll
        for (int ks = 0; ks < 8; ks++) {
            const int pc = ks * 8;
            uint32_t ah[2][4];
            #pragma unroll
            for (int mt = 0; mt < 2; mt++) {
                #pragma unroll
                for (int q = 0; q < 4; q++) {
                    const int row = wm + mt * 16 + g + (q & 1) * 8;
                    const int col = pc + t + (q >> 1) * 4;
                    ah[mt][q] = Qh[row][col];
                }
            }
            #pragma unroll
            for (int nf = 0; nf < 8; nf++) {
                const int rb = wn * 64 + nf * 8 + g;
                const uint32_t b0 = Kh[rb][pc + t], b1 = Kh[rb][pc + t + 4];
                #pragma unroll
                for (int mt = 0; mt < 2; mt++)
                    mma_fp16(s[mt][nf], ah[mt][0], ah[mt][1], ah[mt][2], ah[mt][3], b0, b1);
            }
        }

        // ---- + mask bias + row max ----
        float pm[2][2];
        #pragma unroll
        for (int mt = 0; mt < 2; mt++) {
            #pragma unroll
            for (int h2 = 0; h2 < 2; h2++) {
                const int rglob = m0 + wm + mt * 16 + g + h2 * 8;
                float mx = -INFINITY;
                #pragma unroll
                for (int nf = 0; nf < 8; nf++) {
                    const int ncol = n0 + wn * 64 + nf * 8 + 2 * t;
                    const uint32_t mb = g_MB[((size_t)b << 19) + ((size_t)rglob << 9) + (ncol >> 1)];
                    const float2 bias = __half22float2(*(const __half2*)&mb);
                    float v0 = s[mt][nf][h2 * 2 + 0] + bias.x;
                    float v1 = s[mt][nf][h2 * 2 + 1] + bias.y;
                    s[mt][nf][h2 * 2 + 0] = v0;
                    s[mt][nf][h2 * 2 + 1] = v1;
                    mx = fmaxf(mx, fmaxf(v0, v1));
                }
                pm[mt][h2] = mx;
            }
        }
        #pragma unroll
        for (int mt = 0; mt < 2; mt++)
            #pragma unroll
            for (int h2 = 0; h2 < 2; h2++) {
                pm[mt][h2] = fmaxf(pm[mt][h2], __shfl_xor_sync(0xffffffffu, pm[mt][h2], 1));
                pm[mt][h2] = fmaxf(pm[mt][h2], __shfl_xor_sync(0xffffffffu, pm[mt][h2], 2));
            }
        if (t == 0) {
            #pragma unroll
            for (int mt = 0; mt < 2; mt++)
                #pragma unroll
                for (int h2 = 0; h2 < 2; h2++)
                    redmax[wn * 128 + wm + mt * 16 + g + h2 * 8] = pm[mt][h2];
        }
        __syncthreads();

        // ---- running stats, exponentiate, rescale O ----
        float alpha[2][2], psum[2][2];
        #pragma unroll
        for (int mt = 0; mt < 2; mt++) {
            #pragma unroll
            for (int h2 = 0; h2 < 2; h2++) {
                const int rl = wm + mt * 16 + g + h2 * 8;
                const float mtile = fmaxf(redmax[rl], redmax[128 + rl]);
                const float mnew  = fmaxf(mrun[mt][h2], mtile);
                alpha[mt][h2] = __expf(mrun[mt][h2] - mnew);
                mrun[mt][h2]  = mnew;
                float ps = 0.0f;
                #pragma unroll
                for (int nf = 0; nf < 8; nf++) {
                    float p0 = __expf(s[mt][nf][h2 * 2 + 0] - mnew);
                    float p1 = __expf(s[mt][nf][h2 * 2 + 1] - mnew);
                    s[mt][nf][h2 * 2 + 0] = p0;
                    s[mt][nf][h2 * 2 + 1] = p1;
                    ps += p0 + p1;
                }
                psum[mt][h2] = ps;
            }
        }
        #pragma unroll
        for (int mt = 0; mt < 2; mt++)
            #pragma unroll
            for (int nf = 0; nf < 8; nf++)
                #pragma unroll
                for (int e = 0; e < 4; e++)
                    o[mt][nf][e] *= alpha[mt][e >> 1];
        #pragma unroll
        for (int mt = 0; mt < 2; mt++)
            #pragma unroll
            for (int h2 = 0; h2 < 2; h2++) {
                psum[mt][h2] += __shfl_xor_sync(0xffffffffu, psum[mt][h2], 1);
                psum[mt][h2] += __shfl_xor_sync(0xffffffffu, psum[mt][h2], 2);
            }
        if (t == 0) {
            #pragma unroll
            for (int mt = 0; mt < 2; mt++)
                #pragma unroll
                for (int h2 = 0; h2 < 2; h2++)
                    redsum[wn * 128 + wm + mt * 16 + g + h2 * 8] = psum[mt][h2];
        }
        __syncthreads();
        #pragma unroll
        for (int mt = 0; mt < 2; mt++)
            #pragma unroll
            for (int h2 = 0; h2 < 2; h2++) {
                const int rl = wm + mt * 16 + g + h2 * 8;
                lrun[mt][h2] = lrun[mt][h2] * alpha[mt][h2] + redsum[rl] + redsum[128 + rl];
            }

        // ---- O += P V ----
        #pragma unroll
        for (int ks2 = 0; ks2 < 4; ks2++) {
            uint32_t ah[2][4];
            #pragma unroll
            for (int mt = 0; mt < 2; mt++) {
                ah[mt][0] = pack_h2(s[mt][2 * ks2][0],     s[mt][2 * ks2][1]);
                ah[mt][1] = pack_h2(s[mt][2 * ks2][2],     s[mt][2 * ks2][3]);
                ah[mt][2] = pack_h2(s[mt][2 * ks2 + 1][0], s[mt][2 * ks2 + 1][1]);
                ah[mt][3] = pack_h2(s[mt][2 * ks2 + 1][2], s[mt][2 * ks2 + 1][3]);
            }
            const int vcol = wn * 32 + ks2 * 8 + t;
            #pragma unroll
            for (int nf = 0; nf < 8; nf++) {
                const int rv = nf * 8 + g;
                const uint32_t b0 = Vh[rv][vcol], b1 = Vh[rv][vcol + 4];
                #pragma unroll
                for (int mt = 0; mt < 2; mt++)
                    mma_fp16(o[mt][nf], ah[mt][0], ah[mt][1], ah[mt][2], ah[mt][3], b0, b1);
            }
        }
    }

    // ---- epilogue ----
    __syncthreads();
    if (wn == 1) {
        #pragma unroll
        for (int mt = 0; mt < 2; mt++)
            #pragma unroll
            for (int h2 = 0; h2 < 2; h2++) {
                const int rl = wm + mt * 16 + g + h2 * 8;
                #pragma unroll
                for (int nf = 0; nf < 8; nf++) {
                    float2 v;
                    v.x = o[mt][nf][h2 * 2 + 0];
                    v.y = o[mt][nf][h2 * 2 + 1];
                    *(float2*)&Osum[rl * 66 + nf * 8 + 2 * t] = v;
                }
            }
    }
    __syncthreads();
    if (wn == 0) {
        #pragma unroll
        for (int mt = 0; mt < 2; mt++)
            #pragma unroll
            for (int h2 = 0; h2 < 2; h2++) {
                const int rl = wm + mt * 16 + g + h2 * 8;
                const float inv = 1.0f / lrun[mt][h2];
                #pragma unroll
                for (int nf = 0; nf < 8; nf++) {
                    const int c = nf * 8 + 2 * t;
                    float2 p = *(float2*)&Osum[rl * 66 + c];
                    const float vx = (o[mt][nf][h2 * 2 + 0] + p.x) * inv;
                    const float vy = (o[mt][nf][h2 * 2 + 1] + p.y) * inv;
                    g_Xh[(size_t)(b * 1024 + m0 + rl) * 512 + ((h * 64 + c) >> 1)] = pack_h2(vx, vy);
                }
            }
    }
}

// ---------------------------------------------------------------------------
// Kernel 4: out = gate * (X @ Winfo^T + binfo)
// ---------------------------------------------------------------------------
__global__ __launch_bounds__(256, 2) void info_kernel(
    const float* __restrict__ binfo, float* __restrict__ out)
{
    extern __shared__ uint32_t sm[];
    const int m0 = blockIdx.y * 128;
    const int n0 = blockIdx.x * 128;
    float acc[2][8][4] = {};
    gemm_fp16_ca(sm, g_Xh, 512, nullptr, 1 << 30, g_Wh + OW_INFO, 512, 512, m0, n0, acc);

    const int lane = threadIdx.x & 31, warp = threadIdx.x >> 5;
    const int wm = (warp & 3) * 32, wn = (warp >> 2) * 64;
    const int g = lane >> 2, t = lane & 3;

    #pragma unroll
    for (int nf = 0; nf < 8; nf++) {
        const int n = n0 + wn + nf * 8 + 2 * t;
        const float bx = binfo[n], by = binfo[n + 1];
        #pragma unroll
        for (int mt = 0; mt < 2; mt++) {
            #pragma unroll
            for (int h2 = 0; h2 < 2; h2++) {
                const int m = m0 + wm + mt * 16 + g + h2 * 8;
                const float2 gg = *(const float2*)&g_G[(size_t)m * 1024 + n];
                float2 v;
                v.x = gg.x * (acc[mt][nf][h2 * 2 + 0] + bx);
                v.y = gg.y * (acc[mt][nf][h2 * 2 + 1] + by);
                *(float2*)&out[(size_t)m * 1024 + n] = v;
            }
        }
    }
}

// ---------------------------------------------------------------------------
extern "C" void kernel_launch(void* const* d_in, const int* in_sizes, int n_in,
                              void* d_out, int out_size)
{
    (void)in_sizes; (void)n_in; (void)out_size;
    const float* query_g = (const float*)d_in[0];
    const float* key_g   = (const float*)d_in[1];
    const float* query_a = (const float*)d_in[2];
    const float* key_a   = (const float*)d_in[3];
    const float* value_a = (const float*)d_in[4];
    const int*   mask    = (const int*)  d_in[5];
    const float* Wqg = (const float*)d_in[6];  const float* bqg = (const float*)d_in[7];
    const float* Wkg = (const float*)d_in[8];  const float* bkg = (const float*)d_in[9];
    const float* Wqa = (const float*)d_in[10]; const float* bqa = (const float*)d_in[11];
    const float* Wka = (const float*)d_in[12]; const float* bka = (const float*)d_in[13];
    const float* Wva = (const float*)d_in[14]; const float* bva = (const float*)d_in[15];
    const float* Wgate = (const float*)d_in[16]; const float* bgate = (const float*)d_in[17];
    const float* Winfo = (const float*)d_in[18]; const float* binfo = (const float*)d_in[19];

    static int attr_set = 0;
    if (!attr_set) {
        cudaFuncSetAttribute(attn_kernel, cudaFuncAttributeMaxDynamicSharedMemorySize, ATTN_SMEM);
        cudaFuncSetAttribute(projgate_kernel, cudaFuncAttributeMaxDynamicSharedMemorySize, GSMEM);
        cudaFuncSetAttribute(info_kernel, cudaFuncAttributeMaxDynamicSharedMemorySize, GSMEM);
        attr_set = 1;
    }

    dim3 blk(256);
    conv_in_kernel<<<dim3(4096, 5), blk>>>(query_g, key_g, query_a, key_a, value_a);
    conv_w_kernel<<<dim3(1024, 7), blk>>>(Wqa, Wqg, Wka, Wkg, Wva, Wgate, Winfo);
    conv_mask_kernel<<<8192, blk>>>(mask);
    projgate_kernel<<<dim3(8, 32, 6), blk, GSMEM>>>(bqa, bqg, bka, bkg, bva, bgate);
    attn_kernel<<<dim3(8, 64), blk, ATTN_SMEM>>>();
    info_kernel<<<dim3(8, 32, 1), blk, GSMEM>>>(binfo, (float*)d_out);
}